// round 1
// baseline (speedup 1.0000x reference)
#include <cuda_runtime.h>
#include <cstdint>

// Problem constants
#define BATCH   2
#define SEQ     2048
#define NH      16
#define DH      64
#define DEMB    1024
#define NTOK    (BATCH*SEQ)      // 4096
#define QKV_N   (3*DEMB)         // 3072

// Scratch (device globals — no allocation inside kernel_launch)
__device__ float g_q[(size_t)BATCH*NH*SEQ*DH];
__device__ float g_k[(size_t)BATCH*NH*SEQ*DH];
__device__ float g_v[(size_t)BATCH*NH*SEQ*DH];
__device__ float g_a[(size_t)NTOK*DEMB];

// ---------------------------------------------------------------------------
// GEMM: C[M,N] = A[M,K] @ B[N,K]^T + bias[N]
// MODE 0: plain row-major output to C
// MODE 1: scatter epilogue into g_q/g_k/g_v ([B,H,S,dh] layout)
// MODE 2: plain output, but A comes from g_a (attention output buffer)
// Tiles: 128x128x16, 256 threads, 8x8 per thread (4+4 split fragments)
// ---------------------------------------------------------------------------
template<int MODE>
__global__ __launch_bounds__(256) void gemm_kernel(
    const float* __restrict__ A, const float* __restrict__ B,
    const float* __restrict__ bias, float* __restrict__ C,
    int M, int N, int K)
{
    __shared__ float As[16][128];
    __shared__ float Bs[16][128];

    const int tid = threadIdx.x;
    const int bm  = blockIdx.y * 128;
    const int bn  = blockIdx.x * 128;

    const float* Abase = (MODE == 2) ? (const float*)g_a : A;

    float acc[8][8];
    #pragma unroll
    for (int i = 0; i < 8; i++)
        #pragma unroll
        for (int j = 0; j < 8; j++) acc[i][j] = 0.f;

    // Load mapping: each thread loads two float4 per tile per matrix
    const int ldm = tid >> 2;          // 0..63
    const int ldk = (tid & 3) * 4;     // 0,4,8,12
    const float* Aptr = Abase + (size_t)(bm + ldm) * K + ldk;
    const float* Bptr = B     + (size_t)(bn + ldm) * K + ldk;

    const int tr = (tid >> 4) * 4;     // 0..60 (row fragment base; second at +64)
    const int tc = (tid & 15) * 4;     // 0..60 (col fragment base; second at +64)

    for (int k0 = 0; k0 < K; k0 += 16) {
        float4 a0 = *(const float4*)(Aptr + k0);
        float4 a1 = *(const float4*)(Aptr + k0 + (size_t)64 * K);
        float4 b0 = *(const float4*)(Bptr + k0);
        float4 b1 = *(const float4*)(Bptr + k0 + (size_t)64 * K);

        As[ldk+0][ldm]    = a0.x; As[ldk+1][ldm]    = a0.y;
        As[ldk+2][ldm]    = a0.z; As[ldk+3][ldm]    = a0.w;
        As[ldk+0][ldm+64] = a1.x; As[ldk+1][ldm+64] = a1.y;
        As[ldk+2][ldm+64] = a1.z; As[ldk+3][ldm+64] = a1.w;
        Bs[ldk+0][ldm]    = b0.x; Bs[ldk+1][ldm]    = b0.y;
        Bs[ldk+2][ldm]    = b0.z; Bs[ldk+3][ldm]    = b0.w;
        Bs[ldk+0][ldm+64] = b1.x; Bs[ldk+1][ldm+64] = b1.y;
        Bs[ldk+2][ldm+64] = b1.z; Bs[ldk+3][ldm+64] = b1.w;

        __syncthreads();

        #pragma unroll
        for (int kk = 0; kk < 16; kk++) {
            float ar[8], br[8];
            *(float4*)(ar)   = *(const float4*)&As[kk][tr];
            *(float4*)(ar+4) = *(const float4*)&As[kk][tr + 64];
            *(float4*)(br)   = *(const float4*)&Bs[kk][tc];
            *(float4*)(br+4) = *(const float4*)&Bs[kk][tc + 64];
            #pragma unroll
            for (int i = 0; i < 8; i++)
                #pragma unroll
                for (int j = 0; j < 8; j++)
                    acc[i][j] += ar[i] * br[j];
        }
        __syncthreads();
    }

    // Epilogue
    #pragma unroll
    for (int i = 0; i < 8; i++) {
        const int row = bm + ((i < 4) ? (tr + i) : (64 + tr + i - 4));
        #pragma unroll
        for (int jg = 0; jg < 2; jg++) {
            const int col = bn + tc + jg * 64;
            float4 bv = *(const float4*)&bias[col];
            float4 r;
            r.x = acc[i][jg*4+0] + bv.x;
            r.y = acc[i][jg*4+1] + bv.y;
            r.z = acc[i][jg*4+2] + bv.z;
            r.w = acc[i][jg*4+3] + bv.w;
            if (MODE == 1) {
                const int part = col >> 10;          // 0=q 1=k 2=v
                const int h    = (col & 1023) >> 6;
                const int d    = col & 63;
                const int b    = row >> 11;          // row / SEQ
                const int s    = row & 2047;
                float* dst = (part == 0) ? g_q : (part == 1) ? g_k : g_v;
                *(float4*)&dst[(((size_t)(b*NH + h))*SEQ + s)*DH + d] = r;
            } else {
                *(float4*)&C[(size_t)row * N + col] = r;
            }
        }
    }
}

// ---------------------------------------------------------------------------
// Flash attention: one thread owns one q-row (q[64], o[64] in registers).
// 128 q-rows per block, K/V tiles of 64 keys in smem, online softmax.
// Writes attention output into g_a with [token, h*64+d] layout.
// ---------------------------------------------------------------------------
__global__ __launch_bounds__(128) void attn_kernel(const int* __restrict__ cmask)
{
    __shared__ float Ks[64][64];
    __shared__ float Vs[64][64];

    const int bh  = blockIdx.x;                         // b*NH + h
    // schedule heavy (late) q-tiles first for causal load balance
    const int q0  = (gridDim.y - 1 - blockIdx.y) * 128;
    const int tid = threadIdx.x;
    const int qi  = q0 + tid;

    const float* qp = g_q + ((size_t)bh * SEQ + qi) * DH;
    float q[64], o[64];
    #pragma unroll
    for (int d = 0; d < 64; d += 4) {
        float4 t = *(const float4*)(qp + d);
        q[d]   = t.x * 0.125f;   // fold 1/sqrt(dh)
        q[d+1] = t.y * 0.125f;
        q[d+2] = t.z * 0.125f;
        q[d+3] = t.w * 0.125f;
        o[d] = o[d+1] = o[d+2] = o[d+3] = 0.f;
    }

    const bool causal = (cmask[0] != 0);
    const int  kend   = causal ? (q0 + 127) : (SEQ - 1);

    float m = -1e30f, l = 0.f;

    for (int k0 = 0; k0 <= kend; k0 += 64) {
        const float4* kp = (const float4*)(g_k + ((size_t)bh * SEQ + k0) * DH);
        const float4* vp = (const float4*)(g_v + ((size_t)bh * SEQ + k0) * DH);
        #pragma unroll
        for (int r = 0; r < 8; r++) {
            int idx = tid + r * 128;   // 64*64/4 = 1024 float4
            ((float4*)Ks)[idx] = kp[idx];
            ((float4*)Vs)[idx] = vp[idx];
        }
        __syncthreads();

        const int jlim = causal ? min(64, qi - k0 + 1) : 64;

        for (int jc = 0; jc < jlim; jc += 16) {
            float s[16];
            #pragma unroll
            for (int j = 0; j < 16; j++) {
                float a0 = 0.f;
                #pragma unroll
                for (int d = 0; d < 64; d++)
                    a0 += q[d] * Ks[jc + j][d];
                s[j] = (jc + j < jlim) ? a0 : -1e30f;
            }
            float smax = -1e30f;
            #pragma unroll
            for (int j = 0; j < 16; j++) smax = fmaxf(smax, s[j]);
            const float mnew = fmaxf(m, smax);
            const float corr = __expf(m - mnew);
            l *= corr;
            #pragma unroll
            for (int d = 0; d < 64; d++) o[d] *= corr;
            m = mnew;
            #pragma unroll
            for (int j = 0; j < 16; j++) {
                const float p = __expf(s[j] - m);
                l += p;
                #pragma unroll
                for (int d = 0; d < 64; d++)
                    o[d] += p * Vs[jc + j][d];
            }
        }
        __syncthreads();
    }

    const float inv = 1.f / l;
    const int b = bh >> 4, h = bh & 15;
    float* op = g_a + ((size_t)(b * SEQ) + qi) * DEMB + h * DH;
    #pragma unroll
    for (int d = 0; d < 64; d += 4) {
        float4 r;
        r.x = o[d]   * inv;
        r.y = o[d+1] * inv;
        r.z = o[d+2] * inv;
        r.w = o[d+3] * inv;
        *(float4*)(op + d) = r;
    }
}

// ---------------------------------------------------------------------------
extern "C" void kernel_launch(void* const* d_in, const int* in_sizes, int n_in,
                              void* d_out, int out_size)
{
    const float* x     = (const float*)d_in[0];
    const float* w_in  = (const float*)d_in[1];
    const float* b_in  = (const float*)d_in[2];
    const float* w_out = (const float*)d_in[3];
    const float* b_out = (const float*)d_in[4];
    const int*   cmask = (const int*)d_in[5];
    float* out = (float*)d_out;

    // 1) QKV projection + scatter into [B,H,S,dh] q/k/v buffers
    gemm_kernel<1><<<dim3(QKV_N/128, NTOK/128), 256>>>(
        x, w_in, b_in, nullptr, NTOK, QKV_N, DEMB);

    // 2) Flash attention -> g_a [token, DEMB]
    attn_kernel<<<dim3(BATCH*NH, SEQ/128), 128>>>(cmask);

    // 3) Output projection: out = g_a @ w_out^T + b_out
    gemm_kernel<2><<<dim3(DEMB/128, NTOK/128), 256>>>(
        nullptr, w_out, b_out, out, NTOK, DEMB, DEMB);
}

// round 3
// speedup vs baseline: 1.6529x; 1.6529x over previous
#include <cuda_runtime.h>
#include <cstdint>

// Problem constants
#define BATCH   2
#define SEQ     2048
#define NH      16
#define DH      64
#define DEMB    1024
#define NTOK    (BATCH*SEQ)      // 4096
#define QKV_N   (3*DEMB)         // 3072

// Scratch (device globals — no allocation inside kernel_launch)
__device__ float g_q[(size_t)BATCH*NH*SEQ*DH];
__device__ float g_k[(size_t)BATCH*NH*SEQ*DH];
__device__ float g_v[(size_t)BATCH*NH*SEQ*DH];
__device__ float g_a[(size_t)NTOK*DEMB];

// ---------------------------------------------------------------------------
// Helpers (all compute_103-safe: cp.async, ldmatrix, mma.sync tf32)
// ---------------------------------------------------------------------------
__device__ __forceinline__ uint32_t smem_u32(const void* p) {
    uint32_t a;
    asm("{ .reg .u64 t; cvta.to.shared.u64 t, %1; cvt.u32.u64 %0, t; }"
        : "=r"(a) : "l"(p));
    return a;
}
__device__ __forceinline__ void cp_async16(uint32_t dst, const void* src) {
    asm volatile("cp.async.cg.shared.global [%0], [%1], 16;\n" :: "r"(dst), "l"(src));
}
#define CP_COMMIT()  asm volatile("cp.async.commit_group;\n" ::: "memory")
#define CP_WAIT0()   asm volatile("cp.async.wait_group 0;\n" ::: "memory")

#define SWZ128(off)  ((off) ^ (((off) >> 3) & 0x70))

__device__ __forceinline__ void ldmat4(uint32_t* r, uint32_t addr) {
    asm volatile("ldmatrix.sync.aligned.m8n8.x4.shared.b16 {%0,%1,%2,%3}, [%4];"
        : "=r"(r[0]), "=r"(r[1]), "=r"(r[2]), "=r"(r[3]) : "r"(addr));
}
__device__ __forceinline__ uint32_t f2tf32(uint32_t x) {
    uint32_t o;
    asm("cvt.rna.tf32.f32 %0, %1;" : "=r"(o) : "f"(__uint_as_float(x)));
    return o;
}
__device__ __forceinline__ void mma_tf32(float* d, const uint32_t* a, const uint32_t* b) {
    asm volatile(
        "mma.sync.aligned.m16n8k8.row.col.f32.tf32.tf32.f32 "
        "{%0,%1,%2,%3}, {%4,%5,%6,%7}, {%8,%9}, {%0,%1,%2,%3};"
        : "+f"(d[0]), "+f"(d[1]), "+f"(d[2]), "+f"(d[3])
        : "r"(a[0]), "r"(a[1]), "r"(a[2]), "r"(a[3]), "r"(b[0]), "r"(b[1]));
}

// ---------------------------------------------------------------------------
// mma.sync tf32 GEMM: C[M,N] = A[M,K] @ B[N,K]^T + bias[N]
// Tile 128x128x32, 8 warps (warp tile 64x32), double-buffered cp.async.
// MODE 1: epilogue scatters into g_q/g_k/g_v; MODE 2: A = g_a.
// smem: rows of 128B (32 f32 of K), SW128 swizzle; fragments via ldmatrix.
// ---------------------------------------------------------------------------
#define MT 128
#define NT 128
#define KC 32

#define SM_A0 0
#define SM_A1 (MT*128)            // 16384
#define SM_B0 (2*MT*128)          // 32768
#define SM_B1 (2*MT*128 + NT*128) // 49152
#define SM_TOTAL (2*MT*128 + 2*NT*128)  // 65536

template<int ROWS>
__device__ __forceinline__ void load_tile(uint32_t sbase, const float* __restrict__ g,
                                          int K, int k0, int tid) {
    #pragma unroll
    for (int t = 0; t < ROWS * 8 / 256; ++t) {
        const int c = tid + t * 256;
        const int row = c >> 3, kc = c & 7;
        const uint32_t off = row * 128 + kc * 16;
        cp_async16(sbase + SWZ128(off), g + (size_t)row * K + k0 + kc * 4);
    }
}

template<int MODE>
__global__ __launch_bounds__(256)
void gemm_tc(const float* __restrict__ A, const float* __restrict__ B,
             const float* __restrict__ bias, float* __restrict__ C,
             int M, int N, int K)
{
    extern __shared__ __align__(1024) char smem[];
    const uint32_t sb = smem_u32(smem);
    const int tid  = threadIdx.x;
    const int lane = tid & 31;
    const int warp = tid >> 5;
    const int wm   = (warp >> 2) * 64;   // warp m-offset: 0 / 64
    const int wn   = (warp & 3) * 32;    // warp n-offset: 0/32/64/96
    const int bm   = blockIdx.y * MT;
    const int bn   = blockIdx.x * NT;

    const float* Abase = (MODE == 2) ? (const float*)g_a : A;
    const float* Ag = Abase + (size_t)bm * K;
    const float* Bg = B + (size_t)bn * K;

    float acc[4][4][4];
    #pragma unroll
    for (int i = 0; i < 4; i++)
        #pragma unroll
        for (int j = 0; j < 4; j++)
            #pragma unroll
            for (int r = 0; r < 4; r++) acc[i][j][r] = 0.f;

    // ldmatrix per-thread address components
    const int a_row  = lane & 15;               // rows m..m+15 across matrices
    const int a_byte = ((lane >> 4) & 1) * 16;  // f32 cols 0-3 / 4-7
    const int b_row  = (lane & 7) + (((lane >> 4) & 1) << 3);  // n row within 16
    const int b_byte = ((lane >> 3) & 1) * 16;

    // prologue: stage 0
    load_tile<MT>(sb + SM_A0, Ag, K, 0, tid);
    load_tile<NT>(sb + SM_B0, Bg, K, 0, tid);
    CP_COMMIT();

    const int niter = K / KC;
    for (int it = 0; it < niter; ++it) {
        CP_WAIT0();
        __syncthreads();

        if (it + 1 < niter) {
            const int nb = (it + 1) & 1;
            load_tile<MT>(sb + (nb ? SM_A1 : SM_A0), Ag, K, (it + 1) * KC, tid);
            load_tile<NT>(sb + (nb ? SM_B1 : SM_B0), Bg, K, (it + 1) * KC, tid);
            CP_COMMIT();
        }

        const int buf = it & 1;
        const uint32_t abase = sb + (buf ? SM_A1 : SM_A0);
        const uint32_t bbase = sb + (buf ? SM_B1 : SM_B0);

        #pragma unroll
        for (int kk = 0; kk < KC / 8; ++kk) {
            uint32_t af[4][4], bf[4][2];
            #pragma unroll
            for (int mt = 0; mt < 4; ++mt) {
                const uint32_t off = (wm + mt * 16 + a_row) * 128 + kk * 32 + a_byte;
                ldmat4(af[mt], abase + SWZ128(off));
            }
            #pragma unroll
            for (int np = 0; np < 2; ++np) {
                const uint32_t off = (wn + np * 16 + b_row) * 128 + kk * 32 + b_byte;
                uint32_t r[4];
                ldmat4(r, bbase + SWZ128(off));
                bf[np*2][0]   = r[0]; bf[np*2][1]   = r[1];
                bf[np*2+1][0] = r[2]; bf[np*2+1][1] = r[3];
            }
            #pragma unroll
            for (int mt = 0; mt < 4; ++mt)
                #pragma unroll
                for (int r = 0; r < 4; ++r) af[mt][r] = f2tf32(af[mt][r]);
            #pragma unroll
            for (int nt = 0; nt < 4; ++nt) {
                bf[nt][0] = f2tf32(bf[nt][0]);
                bf[nt][1] = f2tf32(bf[nt][1]);
            }
            #pragma unroll
            for (int mt = 0; mt < 4; ++mt)
                #pragma unroll
                for (int nt = 0; nt < 4; ++nt)
                    mma_tf32(acc[mt][nt], af[mt], bf[nt]);
        }
        __syncthreads();
    }

    // Epilogue: C-fragment layout c0,c1=(g, 2q),(g, 2q+1); c2,c3 = rows +8
    const int g  = lane >> 2;
    const int qd = lane & 3;
    #pragma unroll
    for (int nt = 0; nt < 4; ++nt) {
        const int col = bn + wn + nt * 8 + qd * 2;
        const float2 bv = *(const float2*)&bias[col];
        #pragma unroll
        for (int mt = 0; mt < 4; ++mt) {
            const int row0 = bm + wm + mt * 16 + g;
            float2 v0, v1;
            v0.x = acc[mt][nt][0] + bv.x;
            v0.y = acc[mt][nt][1] + bv.y;
            v1.x = acc[mt][nt][2] + bv.x;
            v1.y = acc[mt][nt][3] + bv.y;
            if (MODE == 1) {
                const int part = col >> 10;
                const int h = (col & 1023) >> 6;
                const int d = col & 63;
                float* dst = (part == 0) ? g_q : (part == 1) ? g_k : g_v;
                const int b0i = row0 >> 11, s0 = row0 & 2047;
                const int b1i = (row0 + 8) >> 11, s1 = (row0 + 8) & 2047;
                *(float2*)&dst[(((size_t)(b0i*NH + h))*SEQ + s0)*DH + d] = v0;
                *(float2*)&dst[(((size_t)(b1i*NH + h))*SEQ + s1)*DH + d] = v1;
            } else {
                *(float2*)&C[(size_t)row0 * N + col] = v0;
                *(float2*)&C[(size_t)(row0 + 8) * N + col] = v1;
            }
        }
    }
}

// ---------------------------------------------------------------------------
// Flash attention (unchanged, known-good): one thread owns one q-row.
// ---------------------------------------------------------------------------
__global__ __launch_bounds__(128) void attn_kernel(const int* __restrict__ cmask)
{
    __shared__ float Ks[64][64];
    __shared__ float Vs[64][64];

    const int bh  = blockIdx.x;
    const int q0  = (gridDim.y - 1 - blockIdx.y) * 128;
    const int tid = threadIdx.x;
    const int qi  = q0 + tid;

    const float* qp = g_q + ((size_t)bh * SEQ + qi) * DH;
    float q[64], o[64];
    #pragma unroll
    for (int d = 0; d < 64; d += 4) {
        float4 t = *(const float4*)(qp + d);
        q[d]   = t.x * 0.125f;
        q[d+1] = t.y * 0.125f;
        q[d+2] = t.z * 0.125f;
        q[d+3] = t.w * 0.125f;
        o[d] = o[d+1] = o[d+2] = o[d+3] = 0.f;
    }

    const bool causal = (cmask[0] != 0);
    const int  kend   = causal ? (q0 + 127) : (SEQ - 1);

    float m = -1e30f, l = 0.f;

    for (int k0 = 0; k0 <= kend; k0 += 64) {
        const float4* kp = (const float4*)(g_k + ((size_t)bh * SEQ + k0) * DH);
        const float4* vp = (const float4*)(g_v + ((size_t)bh * SEQ + k0) * DH);
        #pragma unroll
        for (int r = 0; r < 8; r++) {
            int idx = tid + r * 128;
            ((float4*)Ks)[idx] = kp[idx];
            ((float4*)Vs)[idx] = vp[idx];
        }
        __syncthreads();

        const int jlim = causal ? min(64, qi - k0 + 1) : 64;

        for (int jc = 0; jc < jlim; jc += 16) {
            float s[16];
            #pragma unroll
            for (int j = 0; j < 16; j++) {
                float a0 = 0.f;
                #pragma unroll
                for (int d = 0; d < 64; d++)
                    a0 += q[d] * Ks[jc + j][d];
                s[j] = (jc + j < jlim) ? a0 : -1e30f;
            }
            float smax = -1e30f;
            #pragma unroll
            for (int j = 0; j < 16; j++) smax = fmaxf(smax, s[j]);
            const float mnew = fmaxf(m, smax);
            const float corr = __expf(m - mnew);
            l *= corr;
            #pragma unroll
            for (int d = 0; d < 64; d++) o[d] *= corr;
            m = mnew;
            #pragma unroll
            for (int j = 0; j < 16; j++) {
                const float p = __expf(s[j] - m);
                l += p;
                #pragma unroll
                for (int d = 0; d < 64; d++)
                    o[d] += p * Vs[jc + j][d];
            }
        }
        __syncthreads();
    }

    const float inv = 1.f / l;
    const int b = bh >> 4, h = bh & 15;
    float* op = g_a + ((size_t)(b * SEQ) + qi) * DEMB + h * DH;
    #pragma unroll
    for (int d = 0; d < 64; d += 4) {
        float4 r;
        r.x = o[d]   * inv;
        r.y = o[d+1] * inv;
        r.z = o[d+2] * inv;
        r.w = o[d+3] * inv;
        *(float4*)(op + d) = r;
    }
}

// ---------------------------------------------------------------------------
extern "C" void kernel_launch(void* const* d_in, const int* in_sizes, int n_in,
                              void* d_out, int out_size)
{
    const float* x     = (const float*)d_in[0];
    const float* w_in  = (const float*)d_in[1];
    const float* b_in  = (const float*)d_in[2];
    const float* w_out = (const float*)d_in[3];
    const float* b_out = (const float*)d_in[4];
    const int*   cmask = (const int*)d_in[5];
    float* out = (float*)d_out;

    static bool attr_set = false;
    if (!attr_set) {
        cudaFuncSetAttribute(gemm_tc<1>, cudaFuncAttributeMaxDynamicSharedMemorySize, SM_TOTAL);
        cudaFuncSetAttribute(gemm_tc<2>, cudaFuncAttributeMaxDynamicSharedMemorySize, SM_TOTAL);
        attr_set = true;
    }

    // 1) QKV projection (mma.sync tf32) + scatter into [B,H,S,dh]
    gemm_tc<1><<<dim3(QKV_N/NT, NTOK/MT), 256, SM_TOTAL>>>(
        x, w_in, b_in, nullptr, NTOK, QKV_N, DEMB);

    // 2) Flash attention -> g_a [token, DEMB]
    attn_kernel<<<dim3(BATCH*NH, SEQ/128), 128>>>(cmask);

    // 3) Output projection (mma.sync tf32)
    gemm_tc<2><<<dim3(DEMB/NT, NTOK/MT), 256, SM_TOTAL>>>(
        nullptr, w_out, b_out, out, NTOK, DEMB, DEMB);
}

// round 6
// speedup vs baseline: 2.4980x; 1.5112x over previous
#include <cuda_runtime.h>
#include <cstdint>

// Problem constants
#define BATCH   2
#define SEQ     2048
#define NH      16
#define DH      64
#define DEMB    1024
#define NTOK    (BATCH*SEQ)      // 4096
#define QKV_N   (3*DEMB)         // 3072

// Scratch (device globals — no allocation inside kernel_launch)
__device__ float g_q[(size_t)BATCH*NH*SEQ*DH];
__device__ float g_k[(size_t)BATCH*NH*SEQ*DH];
__device__ float g_v[(size_t)BATCH*NH*SEQ*DH];
__device__ float g_a[(size_t)NTOK*DEMB];

// ---------------------------------------------------------------------------
// Helpers (compute_103-safe: cp.async, ldmatrix, mma.sync tf32)
// ---------------------------------------------------------------------------
__device__ __forceinline__ uint32_t smem_u32(const void* p) {
    uint32_t a;
    asm("{ .reg .u64 t; cvta.to.shared.u64 t, %1; cvt.u32.u64 %0, t; }"
        : "=r"(a) : "l"(p));
    return a;
}
__device__ __forceinline__ void cp_async16(uint32_t dst, const void* src) {
    asm volatile("cp.async.cg.shared.global [%0], [%1], 16;\n" :: "r"(dst), "l"(src));
}
#define CP_COMMIT()  asm volatile("cp.async.commit_group;\n" ::: "memory")
#define CP_WAIT0()   asm volatile("cp.async.wait_group 0;\n" ::: "memory")

#define SWZ128(off)  ((off) ^ (((off) >> 3) & 0x70))

__device__ __forceinline__ void ldmat4(uint32_t* r, uint32_t addr) {
    asm volatile("ldmatrix.sync.aligned.m8n8.x4.shared.b16 {%0,%1,%2,%3}, [%4];"
        : "=r"(r[0]), "=r"(r[1]), "=r"(r[2]), "=r"(r[3]) : "r"(addr));
}
__device__ __forceinline__ uint32_t f2tf32(uint32_t x) {
    uint32_t o;
    asm("cvt.rna.tf32.f32 %0, %1;" : "=r"(o) : "f"(__uint_as_float(x)));
    return o;
}
__device__ __forceinline__ void mma_tf32(float* d, const uint32_t* a, const uint32_t* b) {
    asm volatile(
        "mma.sync.aligned.m16n8k8.row.col.f32.tf32.tf32.f32 "
        "{%0,%1,%2,%3}, {%4,%5,%6,%7}, {%8,%9}, {%0,%1,%2,%3};"
        : "+f"(d[0]), "+f"(d[1]), "+f"(d[2]), "+f"(d[3])
        : "r"(a[0]), "r"(a[1]), "r"(a[2]), "r"(a[3]), "r"(b[0]), "r"(b[1]));
}

// ---------------------------------------------------------------------------
// mma.sync tf32 GEMM: C[M,N] = A[M,K] @ B[N,K]^T + bias[N]  (unchanged, proven)
// ---------------------------------------------------------------------------
#define MT 128
#define NT 128
#define KC 32

#define SM_A0 0
#define SM_A1 (MT*128)
#define SM_B0 (2*MT*128)
#define SM_B1 (2*MT*128 + NT*128)
#define SM_TOTAL (2*MT*128 + 2*NT*128)  // 65536

template<int ROWS>
__device__ __forceinline__ void load_tile(uint32_t sbase, const float* __restrict__ g,
                                          int K, int k0, int tid) {
    #pragma unroll
    for (int t = 0; t < ROWS * 8 / 256; ++t) {
        const int c = tid + t * 256;
        const int row = c >> 3, kc = c & 7;
        const uint32_t off = row * 128 + kc * 16;
        cp_async16(sbase + SWZ128(off), g + (size_t)row * K + k0 + kc * 4);
    }
}

template<int MODE>
__global__ __launch_bounds__(256)
void gemm_tc(const float* __restrict__ A, const float* __restrict__ B,
             const float* __restrict__ bias, float* __restrict__ C,
             int M, int N, int K)
{
    extern __shared__ __align__(1024) char smem[];
    const uint32_t sb = smem_u32(smem);
    const int tid  = threadIdx.x;
    const int lane = tid & 31;
    const int warp = tid >> 5;
    const int wm   = (warp >> 2) * 64;
    const int wn   = (warp & 3) * 32;
    const int bm   = blockIdx.y * MT;
    const int bn   = blockIdx.x * NT;

    const float* Abase = (MODE == 2) ? (const float*)g_a : A;
    const float* Ag = Abase + (size_t)bm * K;
    const float* Bg = B + (size_t)bn * K;

    float acc[4][4][4];
    #pragma unroll
    for (int i = 0; i < 4; i++)
        #pragma unroll
        for (int j = 0; j < 4; j++)
            #pragma unroll
            for (int r = 0; r < 4; r++) acc[i][j][r] = 0.f;

    const int a_row  = lane & 15;
    const int a_byte = ((lane >> 4) & 1) * 16;
    const int b_row  = (lane & 7) + (((lane >> 4) & 1) << 3);
    const int b_byte = ((lane >> 3) & 1) * 16;

    load_tile<MT>(sb + SM_A0, Ag, K, 0, tid);
    load_tile<NT>(sb + SM_B0, Bg, K, 0, tid);
    CP_COMMIT();

    const int niter = K / KC;
    for (int it = 0; it < niter; ++it) {
        CP_WAIT0();
        __syncthreads();

        if (it + 1 < niter) {
            const int nb = (it + 1) & 1;
            load_tile<MT>(sb + (nb ? SM_A1 : SM_A0), Ag, K, (it + 1) * KC, tid);
            load_tile<NT>(sb + (nb ? SM_B1 : SM_B0), Bg, K, (it + 1) * KC, tid);
            CP_COMMIT();
        }

        const int buf = it & 1;
        const uint32_t abase = sb + (buf ? SM_A1 : SM_A0);
        const uint32_t bbase = sb + (buf ? SM_B1 : SM_B0);

        #pragma unroll
        for (int kk = 0; kk < KC / 8; ++kk) {
            uint32_t af[4][4], bf[4][2];
            #pragma unroll
            for (int mt = 0; mt < 4; ++mt) {
                const uint32_t off = (wm + mt * 16 + a_row) * 128 + kk * 32 + a_byte;
                ldmat4(af[mt], abase + SWZ128(off));
            }
            #pragma unroll
            for (int np = 0; np < 2; ++np) {
                const uint32_t off = (wn + np * 16 + b_row) * 128 + kk * 32 + b_byte;
                uint32_t r[4];
                ldmat4(r, bbase + SWZ128(off));
                bf[np*2][0]   = r[0]; bf[np*2][1]   = r[1];
                bf[np*2+1][0] = r[2]; bf[np*2+1][1] = r[3];
            }
            #pragma unroll
            for (int mt = 0; mt < 4; ++mt)
                #pragma unroll
                for (int r = 0; r < 4; ++r) af[mt][r] = f2tf32(af[mt][r]);
            #pragma unroll
            for (int nt = 0; nt < 4; ++nt) {
                bf[nt][0] = f2tf32(bf[nt][0]);
                bf[nt][1] = f2tf32(bf[nt][1]);
            }
            #pragma unroll
            for (int mt = 0; mt < 4; ++mt)
                #pragma unroll
                for (int nt = 0; nt < 4; ++nt)
                    mma_tf32(acc[mt][nt], af[mt], bf[nt]);
        }
        __syncthreads();
    }

    const int g  = lane >> 2;
    const int qd = lane & 3;
    #pragma unroll
    for (int nt = 0; nt < 4; ++nt) {
        const int col = bn + wn + nt * 8 + qd * 2;
        const float2 bv = *(const float2*)&bias[col];
        #pragma unroll
        for (int mt = 0; mt < 4; ++mt) {
            const int row0 = bm + wm + mt * 16 + g;
            float2 v0, v1;
            v0.x = acc[mt][nt][0] + bv.x;
            v0.y = acc[mt][nt][1] + bv.y;
            v1.x = acc[mt][nt][2] + bv.x;
            v1.y = acc[mt][nt][3] + bv.y;
            if (MODE == 1) {
                const int part = col >> 10;
                const int h = (col & 1023) >> 6;
                const int d = col & 63;
                float* dst = (part == 0) ? g_q : (part == 1) ? g_k : g_v;
                const int b0i = row0 >> 11, s0 = row0 & 2047;
                const int b1i = (row0 + 8) >> 11, s1 = (row0 + 8) & 2047;
                *(float2*)&dst[(((size_t)(b0i*NH + h))*SEQ + s0)*DH + d] = v0;
                *(float2*)&dst[(((size_t)(b1i*NH + h))*SEQ + s1)*DH + d] = v1;
            } else {
                *(float2*)&C[(size_t)row0 * N + col] = v0;
                *(float2*)&C[(size_t)(row0 + 8) * N + col] = v1;
            }
        }
    }
}

// ---------------------------------------------------------------------------
// Hybrid flash attention:
//   S = Q@K^T via mma.sync (GEMM-identical fragment paths),
//   S fragments -> plain transposed smem Pt[64 cols][132 pitch],
//   softmax + P@V scalar per q-row (proven R3 machinery).
// CTA: one (b,h) x 128 q-rows, 128 threads (4 warps; warp owns 32 S-rows).
// ---------------------------------------------------------------------------
#define AQ 128
#define AK 64
#define ASH_Q 0                      // 2 planes x 128 rows x 128B = 32768
#define ASH_K 32768                  // 2 planes x  64 rows x 128B = 16384
#define ASH_V 49152                  // plain [64][64] f32         = 16384
#define ASH_P 65536                  // Pt [64][132] f32           = 33792
#define ASH_TOTAL 99328

__global__ __launch_bounds__(128) void attn_hy(const int* __restrict__ cmask)
{
    extern __shared__ __align__(1024) char smem[];
    const uint32_t sb = smem_u32(smem);
    float* Vs = (float*)(smem + ASH_V);
    float* Pt = (float*)(smem + ASH_P);

    const int tid  = threadIdx.x;
    const int lane = tid & 31;
    const int warp = tid >> 5;
    const int bh   = blockIdx.x;
    const int qt   = gridDim.y - 1 - blockIdx.y;   // heavy tiles first
    const int q0   = qt * AQ;
    const int qi   = q0 + tid;                      // this thread's q-row

    const bool causal = (cmask[0] != 0);

    const float* gq  = g_q + ((size_t)bh * SEQ + q0) * DH;
    const float* gkb = g_k + (size_t)bh * SEQ * DH;
    const float* gvb = g_v + (size_t)bh * SEQ * DH;

    const int a_row  = lane & 15;
    const int a_byte = ((lane >> 4) & 1) * 16;
    const int b_row  = (lane & 7) + (((lane >> 4) & 1) << 3);
    const int b_byte = ((lane >> 3) & 1) * 16;
    const int g  = lane >> 2;
    const int qh = lane & 3;

    // ---- load Q tile once (cp.async, 2 planes of 128 rows x 128B) ----
    #pragma unroll
    for (int i = 0; i < 16; ++i) {
        const int c = tid + i * 128;
        const int row = c >> 4, f4 = c & 15;
        const uint32_t dst = sb + ASH_Q + (f4 >> 3) * 16384
                           + SWZ128((uint32_t)(row * 128 + (f4 & 7) * 16));
        cp_async16(dst, gq + (size_t)row * DH + f4 * 4);
    }
    CP_COMMIT();

    // scalar per-row state (R3-proven)
    float o[64];
    #pragma unroll
    for (int d = 0; d < 64; ++d) o[d] = 0.f;
    float m = -1e30f, l = 0.f;

    const int ntiles = causal ? (q0 / AK + 2) : (SEQ / AK);

    for (int t = 0; t < ntiles; ++t) {
        const int k0 = t * AK;

        // ---- load K tile (cp.async, swizzled planes — GEMM-identical) ----
        #pragma unroll
        for (int i = 0; i < 8; ++i) {
            const int c = tid + i * 128;
            const int row = c >> 4, f4 = c & 15;
            const uint32_t dst = sb + ASH_K + (f4 >> 3) * 8192
                               + SWZ128((uint32_t)(row * 128 + (f4 & 7) * 16));
            cp_async16(dst, gkb + (size_t)(k0 + row) * DH + f4 * 4);
        }
        CP_COMMIT();

        // ---- load V tile plain [64][64] (R3-proven straight copy) ----
        {
            const float4* vp = (const float4*)(gvb + (size_t)k0 * DH);
            #pragma unroll
            for (int r = 0; r < 8; ++r)
                ((float4*)Vs)[tid + r * 128] = vp[tid + r * 128];
        }
        CP_WAIT0();
        __syncthreads();

        // ---- S = Q @ K^T (GEMM-identical fragment paths) ----
        float sc[2][8][4];
        #pragma unroll
        for (int mt = 0; mt < 2; ++mt)
            #pragma unroll
            for (int nt = 0; nt < 8; ++nt)
                #pragma unroll
                for (int c = 0; c < 4; ++c) sc[mt][nt][c] = 0.f;

        #pragma unroll
        for (int kk = 0; kk < 8; ++kk) {
            const uint32_t qpl = sb + ASH_Q + (kk >> 2) * 16384;
            const uint32_t kpl = sb + ASH_K + (kk >> 2) * 8192;
            uint32_t aq[2][4], bf[8][2];
            #pragma unroll
            for (int mt = 0; mt < 2; ++mt) {
                const uint32_t off = (warp*32 + mt*16 + a_row) * 128 + (kk & 3) * 32 + a_byte;
                ldmat4(aq[mt], qpl + SWZ128(off));
                #pragma unroll
                for (int r = 0; r < 4; ++r) aq[mt][r] = f2tf32(aq[mt][r]);
            }
            #pragma unroll
            for (int np = 0; np < 4; ++np) {
                const uint32_t off = (np*16 + b_row) * 128 + (kk & 3) * 32 + b_byte;
                uint32_t r[4];
                ldmat4(r, kpl + SWZ128(off));
                bf[np*2][0]   = f2tf32(r[0]); bf[np*2][1]   = f2tf32(r[1]);
                bf[np*2+1][0] = f2tf32(r[2]); bf[np*2+1][1] = f2tf32(r[3]);
            }
            #pragma unroll
            for (int mt = 0; mt < 2; ++mt)
                #pragma unroll
                for (int nt = 0; nt < 8; ++nt)
                    mma_tf32(sc[mt][nt], aq[mt], bf[nt]);
        }

        // ---- store S fragments transposed to Pt[col][row] (plain, no swizzle)
        //      bank-conflict-free: (4*col + row) mod 32 covers all banks ----
        #pragma unroll
        for (int mt = 0; mt < 2; ++mt) {
            const int row = warp*32 + mt*16 + g;
            #pragma unroll
            for (int nt = 0; nt < 8; ++nt) {
                const int col = nt*8 + 2*qh;
                Pt[col*132 + row]           = sc[mt][nt][0];
                Pt[(col+1)*132 + row]       = sc[mt][nt][1];
                Pt[col*132 + row + 8]       = sc[mt][nt][2];
                Pt[(col+1)*132 + row + 8]   = sc[mt][nt][3];
            }
        }
        __syncthreads();

        // ---- scalar softmax + P@V for this thread's row (R3-proven) ----
        const int jlim = causal ? min(AK, qi - k0 + 1) : AK;
        if (jlim > 0) {
            float tmax = -1e30f;
            for (int j = 0; j < jlim; ++j)
                tmax = fmaxf(tmax, Pt[j*132 + tid]);
            tmax *= 0.125f;
            const float mn = fmaxf(m, tmax);
            const float corr = __expf(m - mn);
            l *= corr;
            #pragma unroll
            for (int d = 0; d < 64; ++d) o[d] *= corr;
            m = mn;
            for (int j = 0; j < jlim; ++j) {
                const float p = __expf(Pt[j*132 + tid] * 0.125f - mn);
                l += p;
                const float4* vrow = (const float4*)(Vs + j * 64);
                #pragma unroll
                for (int d4 = 0; d4 < 16; ++d4) {
                    const float4 v = vrow[d4];
                    o[d4*4+0] += p * v.x;
                    o[d4*4+1] += p * v.y;
                    o[d4*4+2] += p * v.z;
                    o[d4*4+3] += p * v.w;
                }
            }
        }
        __syncthreads();
    }

    // ---- normalize + write to g_a [token][h*64+d] ----
    const float inv = 1.f / fmaxf(l, 1e-30f);
    const int b = bh >> 4, h = bh & 15;
    float* op = g_a + ((size_t)(b * SEQ + qi)) * DEMB + h * DH;
    #pragma unroll
    for (int d = 0; d < 64; d += 4) {
        float4 r;
        r.x = o[d]   * inv;
        r.y = o[d+1] * inv;
        r.z = o[d+2] * inv;
        r.w = o[d+3] * inv;
        *(float4*)(op + d) = r;
    }
}

// ---------------------------------------------------------------------------
extern "C" void kernel_launch(void* const* d_in, const int* in_sizes, int n_in,
                              void* d_out, int out_size)
{
    const float* x     = (const float*)d_in[0];
    const float* w_in  = (const float*)d_in[1];
    const float* b_in  = (const float*)d_in[2];
    const float* w_out = (const float*)d_in[3];
    const float* b_out = (const float*)d_in[4];
    const int*   cmask = (const int*)d_in[5];
    float* out = (float*)d_out;

    cudaFuncSetAttribute(gemm_tc<1>, cudaFuncAttributeMaxDynamicSharedMemorySize, SM_TOTAL);
    cudaFuncSetAttribute(gemm_tc<2>, cudaFuncAttributeMaxDynamicSharedMemorySize, SM_TOTAL);
    cudaFuncSetAttribute(attn_hy,    cudaFuncAttributeMaxDynamicSharedMemorySize, ASH_TOTAL);

    // 1) QKV projection (mma.sync tf32) + scatter into [B,H,S,dh]
    gemm_tc<1><<<dim3(QKV_N/NT, NTOK/MT), 256, SM_TOTAL>>>(
        x, w_in, b_in, nullptr, NTOK, QKV_N, DEMB);

    // 2) Hybrid flash attention -> g_a [token, DEMB]
    attn_hy<<<dim3(BATCH*NH, SEQ/AQ), 128, ASH_TOTAL>>>(cmask);

    // 3) Output projection (mma.sync tf32)
    gemm_tc<2><<<dim3(DEMB/NT, NTOK/MT), 256, SM_TOTAL>>>(
        nullptr, w_out, b_out, out, NTOK, DEMB, DEMB);
}

// round 7
// speedup vs baseline: 3.5979x; 1.4403x over previous
#include <cuda_runtime.h>
#include <cstdint>

// Problem constants
#define BATCH   2
#define SEQ     2048
#define NH      16
#define DH      64
#define DEMB    1024
#define NTOK    (BATCH*SEQ)      // 4096
#define QKV_N   (3*DEMB)         // 3072

// Scratch (device globals — no allocation inside kernel_launch)
__device__ float g_q[(size_t)BATCH*NH*SEQ*DH];
__device__ float g_k[(size_t)BATCH*NH*SEQ*DH];
__device__ float g_v[(size_t)BATCH*NH*SEQ*DH];
__device__ float g_a[(size_t)NTOK*DEMB];

// ---------------------------------------------------------------------------
// Helpers (compute_103-safe: cp.async, ldmatrix, mma.sync tf32)
// ---------------------------------------------------------------------------
__device__ __forceinline__ uint32_t smem_u32(const void* p) {
    uint32_t a;
    asm("{ .reg .u64 t; cvta.to.shared.u64 t, %1; cvt.u32.u64 %0, t; }"
        : "=r"(a) : "l"(p));
    return a;
}
__device__ __forceinline__ void cp_async16(uint32_t dst, const void* src) {
    asm volatile("cp.async.cg.shared.global [%0], [%1], 16;\n" :: "r"(dst), "l"(src));
}
#define CP_COMMIT()  asm volatile("cp.async.commit_group;\n" ::: "memory")
#define CP_WAIT0()   asm volatile("cp.async.wait_group 0;\n" ::: "memory")

#define SWZ128(off)  ((off) ^ (((off) >> 3) & 0x70))

__device__ __forceinline__ void ldmat4(uint32_t* r, uint32_t addr) {
    asm volatile("ldmatrix.sync.aligned.m8n8.x4.shared.b16 {%0,%1,%2,%3}, [%4];"
        : "=r"(r[0]), "=r"(r[1]), "=r"(r[2]), "=r"(r[3]) : "r"(addr));
}
__device__ __forceinline__ uint32_t f2tf32(uint32_t x) {
    uint32_t o;
    asm("cvt.rna.tf32.f32 %0, %1;" : "=r"(o) : "f"(__uint_as_float(x)));
    return o;
}
__device__ __forceinline__ void mma_tf32(float* d, const uint32_t* a, const uint32_t* b) {
    asm volatile(
        "mma.sync.aligned.m16n8k8.row.col.f32.tf32.tf32.f32 "
        "{%0,%1,%2,%3}, {%4,%5,%6,%7}, {%8,%9}, {%0,%1,%2,%3};"
        : "+f"(d[0]), "+f"(d[1]), "+f"(d[2]), "+f"(d[3])
        : "r"(a[0]), "r"(a[1]), "r"(a[2]), "r"(a[3]), "r"(b[0]), "r"(b[1]));
}

// ---------------------------------------------------------------------------
// mma.sync tf32 GEMM: C[M,N] = A[M,K] @ B[N,K]^T + bias[N]  (unchanged, proven)
// ---------------------------------------------------------------------------
#define MT 128
#define NT 128
#define KC 32

#define SM_A0 0
#define SM_A1 (MT*128)
#define SM_B0 (2*MT*128)
#define SM_B1 (2*MT*128 + NT*128)
#define SM_TOTAL (2*MT*128 + 2*NT*128)  // 65536

template<int ROWS>
__device__ __forceinline__ void load_tile(uint32_t sbase, const float* __restrict__ g,
                                          int K, int k0, int tid) {
    #pragma unroll
    for (int t = 0; t < ROWS * 8 / 256; ++t) {
        const int c = tid + t * 256;
        const int row = c >> 3, kc = c & 7;
        const uint32_t off = row * 128 + kc * 16;
        cp_async16(sbase + SWZ128(off), g + (size_t)row * K + k0 + kc * 4);
    }
}

template<int MODE>
__global__ __launch_bounds__(256)
void gemm_tc(const float* __restrict__ A, const float* __restrict__ B,
             const float* __restrict__ bias, float* __restrict__ C,
             int M, int N, int K)
{
    extern __shared__ __align__(1024) char smem[];
    const uint32_t sb = smem_u32(smem);
    const int tid  = threadIdx.x;
    const int lane = tid & 31;
    const int warp = tid >> 5;
    const int wm   = (warp >> 2) * 64;
    const int wn   = (warp & 3) * 32;
    const int bm   = blockIdx.y * MT;
    const int bn   = blockIdx.x * NT;

    const float* Abase = (MODE == 2) ? (const float*)g_a : A;
    const float* Ag = Abase + (size_t)bm * K;
    const float* Bg = B + (size_t)bn * K;

    float acc[4][4][4];
    #pragma unroll
    for (int i = 0; i < 4; i++)
        #pragma unroll
        for (int j = 0; j < 4; j++)
            #pragma unroll
            for (int r = 0; r < 4; r++) acc[i][j][r] = 0.f;

    const int a_row  = lane & 15;
    const int a_byte = ((lane >> 4) & 1) * 16;
    const int b_row  = (lane & 7) + (((lane >> 4) & 1) << 3);
    const int b_byte = ((lane >> 3) & 1) * 16;

    load_tile<MT>(sb + SM_A0, Ag, K, 0, tid);
    load_tile<NT>(sb + SM_B0, Bg, K, 0, tid);
    CP_COMMIT();

    const int niter = K / KC;
    for (int it = 0; it < niter; ++it) {
        CP_WAIT0();
        __syncthreads();

        if (it + 1 < niter) {
            const int nb = (it + 1) & 1;
            load_tile<MT>(sb + (nb ? SM_A1 : SM_A0), Ag, K, (it + 1) * KC, tid);
            load_tile<NT>(sb + (nb ? SM_B1 : SM_B0), Bg, K, (it + 1) * KC, tid);
            CP_COMMIT();
        }

        const int buf = it & 1;
        const uint32_t abase = sb + (buf ? SM_A1 : SM_A0);
        const uint32_t bbase = sb + (buf ? SM_B1 : SM_B0);

        #pragma unroll
        for (int kk = 0; kk < KC / 8; ++kk) {
            uint32_t af[4][4], bf[4][2];
            #pragma unroll
            for (int mt = 0; mt < 4; ++mt) {
                const uint32_t off = (wm + mt * 16 + a_row) * 128 + kk * 32 + a_byte;
                ldmat4(af[mt], abase + SWZ128(off));
            }
            #pragma unroll
            for (int np = 0; np < 2; ++np) {
                const uint32_t off = (wn + np * 16 + b_row) * 128 + kk * 32 + b_byte;
                uint32_t r[4];
                ldmat4(r, bbase + SWZ128(off));
                bf[np*2][0]   = r[0]; bf[np*2][1]   = r[1];
                bf[np*2+1][0] = r[2]; bf[np*2+1][1] = r[3];
            }
            #pragma unroll
            for (int mt = 0; mt < 4; ++mt)
                #pragma unroll
                for (int r = 0; r < 4; ++r) af[mt][r] = f2tf32(af[mt][r]);
            #pragma unroll
            for (int nt = 0; nt < 4; ++nt) {
                bf[nt][0] = f2tf32(bf[nt][0]);
                bf[nt][1] = f2tf32(bf[nt][1]);
            }
            #pragma unroll
            for (int mt = 0; mt < 4; ++mt)
                #pragma unroll
                for (int nt = 0; nt < 4; ++nt)
                    mma_tf32(acc[mt][nt], af[mt], bf[nt]);
        }
        __syncthreads();
    }

    const int g  = lane >> 2;
    const int qd = lane & 3;
    #pragma unroll
    for (int nt = 0; nt < 4; ++nt) {
        const int col = bn + wn + nt * 8 + qd * 2;
        const float2 bv = *(const float2*)&bias[col];
        #pragma unroll
        for (int mt = 0; mt < 4; ++mt) {
            const int row0 = bm + wm + mt * 16 + g;
            float2 v0, v1;
            v0.x = acc[mt][nt][0] + bv.x;
            v0.y = acc[mt][nt][1] + bv.y;
            v1.x = acc[mt][nt][2] + bv.x;
            v1.y = acc[mt][nt][3] + bv.y;
            if (MODE == 1) {
                const int part = col >> 10;
                const int h = (col & 1023) >> 6;
                const int d = col & 63;
                float* dst = (part == 0) ? g_q : (part == 1) ? g_k : g_v;
                const int b0i = row0 >> 11, s0 = row0 & 2047;
                const int b1i = (row0 + 8) >> 11, s1 = (row0 + 8) & 2047;
                *(float2*)&dst[(((size_t)(b0i*NH + h))*SEQ + s0)*DH + d] = v0;
                *(float2*)&dst[(((size_t)(b1i*NH + h))*SEQ + s1)*DH + d] = v1;
            } else {
                *(float2*)&C[(size_t)row0 * N + col] = v0;
                *(float2*)&C[(size_t)(row0 + 8) * N + col] = v1;
            }
        }
    }
}

// ---------------------------------------------------------------------------
// Flash attention, both GEMMs on mma.sync tf32:
//   S = Q@K^T via mma (R6-proven), fragments stored into row-major swizzled
//   P_A tile; scalar per-row softmax in place on P_A (R6-proven math, with
//   zero-fill of masked keys); O += P_A @ V^T via mma using the SAME proven
//   A/B fragment paths. corr & l broadcast via smem; O in fragment domain.
// CTA: one (b,h) x 128 q-rows, 128 threads (4 warps; warp owns 32 q-rows).
// ---------------------------------------------------------------------------
#define AQ 128
#define AK 64
#define ASH_Q  0                     // 2 planes x 128 x 128B = 32768
#define ASH_K  32768                 // 2 planes x  64 x 128B = 16384
#define ASH_VT 49152                 // 2 planes x  64 x 128B = 16384 (row=dh, col=key)
#define ASH_PA 65536                 // 2 planes x 128 x 128B = 32768 (row=q,  col=key)
#define ASH_C  98304                 // corr[128]
#define ASH_L  98816                 // l[128]
#define ASH_TOTAL 99328

__global__ __launch_bounds__(128) void attn_tc2(const int* __restrict__ cmask)
{
    extern __shared__ __align__(1024) char smem[];
    const uint32_t sb = smem_u32(smem);
    float* Csh = (float*)(smem + ASH_C);
    float* Lsh = (float*)(smem + ASH_L);

    const int tid  = threadIdx.x;
    const int lane = tid & 31;
    const int warp = tid >> 5;
    const int bh   = blockIdx.x;
    const int qt   = gridDim.y - 1 - blockIdx.y;   // heavy tiles first
    const int q0   = qt * AQ;
    const int qi   = q0 + tid;                      // this thread's softmax row

    const bool causal = (cmask[0] != 0);

    const float* gq  = g_q + ((size_t)bh * SEQ + q0) * DH;
    const float* gkb = g_k + (size_t)bh * SEQ * DH;
    const float* gvb = g_v + (size_t)bh * SEQ * DH;

    const int a_row  = lane & 15;
    const int a_byte = ((lane >> 4) & 1) * 16;
    const int b_row  = (lane & 7) + (((lane >> 4) & 1) << 3);
    const int b_byte = ((lane >> 3) & 1) * 16;
    const int g  = lane >> 2;
    const int qh = lane & 3;

    // ---- load Q tile once (R6-proven) ----
    #pragma unroll
    for (int i = 0; i < 16; ++i) {
        const int c = tid + i * 128;
        const int row = c >> 4, f4 = c & 15;
        const uint32_t dst = sb + ASH_Q + (f4 >> 3) * 16384
                           + SWZ128((uint32_t)(row * 128 + (f4 & 7) * 16));
        cp_async16(dst, gq + (size_t)row * DH + f4 * 4);
    }
    CP_COMMIT();

    float oa[2][8][4];
    #pragma unroll
    for (int mt = 0; mt < 2; ++mt)
        #pragma unroll
        for (int nt = 0; nt < 8; ++nt)
            #pragma unroll
            for (int c = 0; c < 4; ++c) oa[mt][nt][c] = 0.f;
    float m = -1e30f, l = 0.f;          // per-thread=row softmax state

    const int ntiles = causal ? (q0 / AK + 2) : (SEQ / AK);

    for (int t = 0; t < ntiles; ++t) {
        const int k0 = t * AK;

        // ---- K tile (cp.async, R6-proven layout) ----
        #pragma unroll
        for (int i = 0; i < 8; ++i) {
            const int c = tid + i * 128;
            const int row = c >> 4, f4 = c & 15;
            const uint32_t dst = sb + ASH_K + (f4 >> 3) * 8192
                               + SWZ128((uint32_t)(row * 128 + (f4 & 7) * 16));
            cp_async16(dst, gkb + (size_t)(k0 + row) * DH + f4 * 4);
        }
        CP_COMMIT();

        // ---- V^T tile: [dh row][key col], 2 planes by key-half, swizzled.
        //      key = tid&63 -> within warp all 32 keys distinct: conflict-free.
        {
            const int key = tid & 63;
            const int ds  = tid >> 6;
            const int pl  = ASH_VT + (key >> 5) * 8192;
            const uint32_t kb = (uint32_t)(key & 31) * 4;
            #pragma unroll
            for (int i = 0; i < 8; ++i) {
                const int d4 = ds + i * 2;
                const float4 v = *(const float4*)(gvb + (size_t)(k0 + key) * DH + d4 * 4);
                *(float*)(smem + pl + SWZ128((uint32_t)((d4*4+0) * 128) + kb)) = v.x;
                *(float*)(smem + pl + SWZ128((uint32_t)((d4*4+1) * 128) + kb)) = v.y;
                *(float*)(smem + pl + SWZ128((uint32_t)((d4*4+2) * 128) + kb)) = v.z;
                *(float*)(smem + pl + SWZ128((uint32_t)((d4*4+3) * 128) + kb)) = v.w;
            }
        }
        CP_WAIT0();
        __syncthreads();

        // ---- S = Q @ K^T (R6-proven fragment paths) ----
        float sc[2][8][4];
        #pragma unroll
        for (int mt = 0; mt < 2; ++mt)
            #pragma unroll
            for (int nt = 0; nt < 8; ++nt)
                #pragma unroll
                for (int c = 0; c < 4; ++c) sc[mt][nt][c] = 0.f;

        #pragma unroll
        for (int kk = 0; kk < 8; ++kk) {
            const uint32_t qpl = sb + ASH_Q + (kk >> 2) * 16384;
            const uint32_t kpl = sb + ASH_K + (kk >> 2) * 8192;
            uint32_t aq[2][4], bf[8][2];
            #pragma unroll
            for (int mt = 0; mt < 2; ++mt) {
                const uint32_t off = (warp*32 + mt*16 + a_row) * 128 + (kk & 3) * 32 + a_byte;
                ldmat4(aq[mt], qpl + SWZ128(off));
                #pragma unroll
                for (int r = 0; r < 4; ++r) aq[mt][r] = f2tf32(aq[mt][r]);
            }
            #pragma unroll
            for (int np = 0; np < 4; ++np) {
                const uint32_t off = (np*16 + b_row) * 128 + (kk & 3) * 32 + b_byte;
                uint32_t r[4];
                ldmat4(r, kpl + SWZ128(off));
                bf[np*2][0]   = f2tf32(r[0]); bf[np*2][1]   = f2tf32(r[1]);
                bf[np*2+1][0] = f2tf32(r[2]); bf[np*2+1][1] = f2tf32(r[3]);
            }
            #pragma unroll
            for (int mt = 0; mt < 2; ++mt)
                #pragma unroll
                for (int nt = 0; nt < 8; ++nt)
                    mma_tf32(sc[mt][nt], aq[mt], bf[nt]);
        }

        // ---- S fragments -> P_A (row-major swizzled, warp-private rows) ----
        #pragma unroll
        for (int mt = 0; mt < 2; ++mt) {
            const int row = warp*32 + mt*16 + g;
            #pragma unroll
            for (int nt = 0; nt < 8; ++nt) {
                const int col = nt*8 + 2*qh;
                const int pl  = ASH_PA + (col >> 5) * 16384;
                const uint32_t cb = (uint32_t)(col & 31) * 4;
                float2 v01, v23;
                v01.x = sc[mt][nt][0]; v01.y = sc[mt][nt][1];
                v23.x = sc[mt][nt][2]; v23.y = sc[mt][nt][3];
                *(float2*)(smem + pl + SWZ128((uint32_t)(row * 128) + cb))       = v01;
                *(float2*)(smem + pl + SWZ128((uint32_t)((row + 8) * 128) + cb)) = v23;
            }
        }
        __syncwarp();

        // ---- scalar softmax on row `tid` of P_A, in place (R6-proven math) ----
        const int jlim = causal ? min(AK, qi - k0 + 1) : AK;
        float corr;
        float* sf = &sc[0][0][0];   // reuse fragment registers
        if (jlim > 0) {
            #pragma unroll
            for (int j4 = 0; j4 < 16; ++j4) {
                const float4 v = *(const float4*)(smem + ASH_PA + (j4 >> 3) * 16384
                               + SWZ128((uint32_t)(tid * 128 + (j4 & 7) * 16)));
                sf[j4*4+0] = v.x; sf[j4*4+1] = v.y;
                sf[j4*4+2] = v.z; sf[j4*4+3] = v.w;
            }
            float tmax = -1e30f;
            #pragma unroll
            for (int j = 0; j < 64; ++j)
                if (j < jlim) tmax = fmaxf(tmax, sf[j]);
            tmax *= 0.125f;
            const float mn = fmaxf(m, tmax);
            corr = __expf(m - mn);
            m = mn;
            float rs = 0.f;
            #pragma unroll
            for (int j = 0; j < 64; ++j) {
                const float p = (j < jlim) ? __expf(sf[j] * 0.125f - mn) : 0.f;
                sf[j] = p;
                rs += p;
            }
            l = l * corr + rs;
            #pragma unroll
            for (int j4 = 0; j4 < 16; ++j4) {
                float4 v;
                v.x = sf[j4*4+0]; v.y = sf[j4*4+1];
                v.z = sf[j4*4+2]; v.w = sf[j4*4+3];
                *(float4*)(smem + ASH_PA + (j4 >> 3) * 16384
                  + SWZ128((uint32_t)(tid * 128 + (j4 & 7) * 16))) = v;
            }
        } else {
            corr = 1.f;
            const float4 z = {0.f, 0.f, 0.f, 0.f};
            #pragma unroll
            for (int j4 = 0; j4 < 16; ++j4)
                *(float4*)(smem + ASH_PA + (j4 >> 3) * 16384
                  + SWZ128((uint32_t)(tid * 128 + (j4 & 7) * 16))) = z;
        }
        Csh[tid] = corr;
        __syncwarp();

        // ---- apply row-correction to O fragments (warp-private rows) ----
        #pragma unroll
        for (int mt = 0; mt < 2; ++mt) {
            const float cA = Csh[warp*32 + mt*16 + g];
            const float cB = Csh[warp*32 + mt*16 + g + 8];
            #pragma unroll
            for (int nt = 0; nt < 8; ++nt) {
                oa[mt][nt][0] *= cA; oa[mt][nt][1] *= cA;
                oa[mt][nt][2] *= cB; oa[mt][nt][3] *= cB;
            }
        }

        // ---- O += P @ V  (proven fragment paths: A=P_A rows, B=V^T) ----
        #pragma unroll
        for (int kk = 0; kk < 8; ++kk) {
            uint32_t ap[2][4], bf[8][2];
            #pragma unroll
            for (int mt = 0; mt < 2; ++mt) {
                const uint32_t off = (warp*32 + mt*16 + a_row) * 128 + (kk & 3) * 32 + a_byte;
                ldmat4(ap[mt], sb + ASH_PA + (kk >> 2) * 16384 + SWZ128(off));
                #pragma unroll
                for (int r = 0; r < 4; ++r) ap[mt][r] = f2tf32(ap[mt][r]);
            }
            #pragma unroll
            for (int np = 0; np < 4; ++np) {
                const uint32_t off = (np*16 + b_row) * 128 + (kk & 3) * 32 + b_byte;
                uint32_t r[4];
                ldmat4(r, sb + ASH_VT + (kk >> 2) * 8192 + SWZ128(off));
                bf[np*2][0]   = f2tf32(r[0]); bf[np*2][1]   = f2tf32(r[1]);
                bf[np*2+1][0] = f2tf32(r[2]); bf[np*2+1][1] = f2tf32(r[3]);
            }
            #pragma unroll
            for (int mt = 0; mt < 2; ++mt)
                #pragma unroll
                for (int nt = 0; nt < 8; ++nt)
                    mma_tf32(oa[mt][nt], ap[mt], bf[nt]);
        }
        __syncthreads();   // protect K/V^T/P_A before next tile overwrites
    }

    // ---- normalize + write to g_a [token][h*64+d] (fragment domain) ----
    Lsh[tid] = l;
    __syncwarp();
    const int b = bh >> 4, h = bh & 15;
    #pragma unroll
    for (int mt = 0; mt < 2; ++mt) {
        const int r0 = warp*32 + mt*16 + g;
        const float i0 = 1.f / fmaxf(Lsh[r0], 1e-30f);
        const float i1 = 1.f / fmaxf(Lsh[r0 + 8], 1e-30f);
        float* o0 = g_a + ((size_t)(b * SEQ + q0 + r0)) * DEMB + h * DH;
        float* o1 = g_a + ((size_t)(b * SEQ + q0 + r0 + 8)) * DEMB + h * DH;
        #pragma unroll
        for (int nt = 0; nt < 8; ++nt) {
            float2 v0, v1;
            v0.x = oa[mt][nt][0] * i0; v0.y = oa[mt][nt][1] * i0;
            v1.x = oa[mt][nt][2] * i1; v1.y = oa[mt][nt][3] * i1;
            *(float2*)(o0 + nt*8 + 2*qh) = v0;
            *(float2*)(o1 + nt*8 + 2*qh) = v1;
        }
    }
}

// ---------------------------------------------------------------------------
extern "C" void kernel_launch(void* const* d_in, const int* in_sizes, int n_in,
                              void* d_out, int out_size)
{
    const float* x     = (const float*)d_in[0];
    const float* w_in  = (const float*)d_in[1];
    const float* b_in  = (const float*)d_in[2];
    const float* w_out = (const float*)d_in[3];
    const float* b_out = (const float*)d_in[4];
    const int*   cmask = (const int*)d_in[5];
    float* out = (float*)d_out;

    cudaFuncSetAttribute(gemm_tc<1>, cudaFuncAttributeMaxDynamicSharedMemorySize, SM_TOTAL);
    cudaFuncSetAttribute(gemm_tc<2>, cudaFuncAttributeMaxDynamicSharedMemorySize, SM_TOTAL);
    cudaFuncSetAttribute(attn_tc2,   cudaFuncAttributeMaxDynamicSharedMemorySize, ASH_TOTAL);

    // 1) QKV projection (mma.sync tf32) + scatter into [B,H,S,dh]
    gemm_tc<1><<<dim3(QKV_N/NT, NTOK/MT), 256, SM_TOTAL>>>(
        x, w_in, b_in, nullptr, NTOK, QKV_N, DEMB);

    // 2) Flash attention (both GEMMs on mma.sync) -> g_a [token, DEMB]
    attn_tc2<<<dim3(BATCH*NH, SEQ/AQ), 128, ASH_TOTAL>>>(cmask);

    // 3) Output projection (mma.sync tf32)
    gemm_tc<2><<<dim3(DEMB/NT, NTOK/MT), 256, SM_TOTAL>>>(
        nullptr, w_out, b_out, out, NTOK, DEMB, DEMB);
}

// round 8
// speedup vs baseline: 3.6460x; 1.0134x over previous
#include <cuda_runtime.h>
#include <cstdint>

// Problem constants
#define BATCH   2
#define SEQ     2048
#define NH      16
#define DH      64
#define DEMB    1024
#define NTOK    (BATCH*SEQ)      // 4096
#define QKV_N   (3*DEMB)         // 3072

// Scratch (device globals — no allocation inside kernel_launch)
__device__ float g_q[(size_t)BATCH*NH*SEQ*DH];
__device__ float g_k[(size_t)BATCH*NH*SEQ*DH];
__device__ float g_v[(size_t)BATCH*NH*SEQ*DH];
__device__ float g_a[(size_t)NTOK*DEMB];

// ---------------------------------------------------------------------------
// Helpers (compute_103-safe: cp.async, ldmatrix, mma.sync tf32)
// ---------------------------------------------------------------------------
__device__ __forceinline__ uint32_t smem_u32(const void* p) {
    uint32_t a;
    asm("{ .reg .u64 t; cvta.to.shared.u64 t, %1; cvt.u32.u64 %0, t; }"
        : "=r"(a) : "l"(p));
    return a;
}
__device__ __forceinline__ void cp_async16(uint32_t dst, const void* src) {
    asm volatile("cp.async.cg.shared.global [%0], [%1], 16;\n" :: "r"(dst), "l"(src));
}
#define CP_COMMIT()  asm volatile("cp.async.commit_group;\n" ::: "memory")
#define CP_WAIT0()   asm volatile("cp.async.wait_group 0;\n" ::: "memory")
#define CP_WAIT1()   asm volatile("cp.async.wait_group 1;\n" ::: "memory")

#define SWZ128(off)  ((off) ^ (((off) >> 3) & 0x70))

__device__ __forceinline__ void ldmat4(uint32_t* r, uint32_t addr) {
    asm volatile("ldmatrix.sync.aligned.m8n8.x4.shared.b16 {%0,%1,%2,%3}, [%4];"
        : "=r"(r[0]), "=r"(r[1]), "=r"(r[2]), "=r"(r[3]) : "r"(addr));
}
__device__ __forceinline__ uint32_t f2tf32(uint32_t x) {
    uint32_t o;
    asm("cvt.rna.tf32.f32 %0, %1;" : "=r"(o) : "f"(__uint_as_float(x)));
    return o;
}
__device__ __forceinline__ void mma_tf32(float* d, const uint32_t* a, const uint32_t* b) {
    asm volatile(
        "mma.sync.aligned.m16n8k8.row.col.f32.tf32.tf32.f32 "
        "{%0,%1,%2,%3}, {%4,%5,%6,%7}, {%8,%9}, {%0,%1,%2,%3};"
        : "+f"(d[0]), "+f"(d[1]), "+f"(d[2]), "+f"(d[3])
        : "r"(a[0]), "r"(a[1]), "r"(a[2]), "r"(a[3]), "r"(b[0]), "r"(b[1]));
}

// ---------------------------------------------------------------------------
// mma.sync tf32 GEMM: C[M,N] = A[M,K] @ B[N,K]^T + bias[N]
// Now 3-stage cp.async pipeline (wait_group 1), single barrier per iter.
// ---------------------------------------------------------------------------
#define MT 128
#define NT 128
#define KC 32

#define SM_STAGE (MT*128 + NT*128)     // 32768 per stage (A then B)
#define SM_TOTAL (3*SM_STAGE)          // 98304

template<int ROWS>
__device__ __forceinline__ void load_tile(uint32_t sbase, const float* __restrict__ g,
                                          int K, int k0, int tid) {
    #pragma unroll
    for (int t = 0; t < ROWS * 8 / 256; ++t) {
        const int c = tid + t * 256;
        const int row = c >> 3, kc = c & 7;
        const uint32_t off = row * 128 + kc * 16;
        cp_async16(sbase + SWZ128(off), g + (size_t)row * K + k0 + kc * 4);
    }
}

template<int MODE>
__global__ __launch_bounds__(256)
void gemm_tc(const float* __restrict__ A, const float* __restrict__ B,
             const float* __restrict__ bias, float* __restrict__ C,
             int M, int N, int K)
{
    extern __shared__ __align__(1024) char smem[];
    const uint32_t sb = smem_u32(smem);
    const int tid  = threadIdx.x;
    const int lane = tid & 31;
    const int warp = tid >> 5;
    const int wm   = (warp >> 2) * 64;
    const int wn   = (warp & 3) * 32;
    const int bm   = blockIdx.y * MT;
    const int bn   = blockIdx.x * NT;

    const float* Abase = (MODE == 2) ? (const float*)g_a : A;
    const float* Ag = Abase + (size_t)bm * K;
    const float* Bg = B + (size_t)bn * K;

    float acc[4][4][4];
    #pragma unroll
    for (int i = 0; i < 4; i++)
        #pragma unroll
        for (int j = 0; j < 4; j++)
            #pragma unroll
            for (int r = 0; r < 4; r++) acc[i][j][r] = 0.f;

    const int a_row  = lane & 15;
    const int a_byte = ((lane >> 4) & 1) * 16;
    const int b_row  = (lane & 7) + (((lane >> 4) & 1) << 3);
    const int b_byte = ((lane >> 3) & 1) * 16;

    // prologue: stages 0,1
    load_tile<MT>(sb + 0*SM_STAGE, Ag, K, 0, tid);
    load_tile<NT>(sb + 0*SM_STAGE + MT*128, Bg, K, 0, tid);
    CP_COMMIT();
    load_tile<MT>(sb + 1*SM_STAGE, Ag, K, KC, tid);
    load_tile<NT>(sb + 1*SM_STAGE + MT*128, Bg, K, KC, tid);
    CP_COMMIT();

    const int niter = K / KC;
    int stage = 0;
    for (int it = 0; it < niter; ++it) {
        if (it + 1 < niter) { CP_WAIT1(); } else { CP_WAIT0(); }
        __syncthreads();

        if (it + 2 < niter) {
            const int ps = (stage + 2 == 3) ? 2 : (stage + 2 - 3 >= 0 ? stage - 1 : stage + 2);
            // simpler: (stage+2)%3
            const int s2 = (stage + 2) % 3;
            (void)ps;
            load_tile<MT>(sb + s2*SM_STAGE, Ag, K, (it + 2) * KC, tid);
            load_tile<NT>(sb + s2*SM_STAGE + MT*128, Bg, K, (it + 2) * KC, tid);
            CP_COMMIT();
        }

        const uint32_t abase = sb + stage*SM_STAGE;
        const uint32_t bbase = abase + MT*128;

        #pragma unroll
        for (int kk = 0; kk < KC / 8; ++kk) {
            uint32_t af[4][4], bf[4][2];
            #pragma unroll
            for (int mt = 0; mt < 4; ++mt) {
                const uint32_t off = (wm + mt * 16 + a_row) * 128 + kk * 32 + a_byte;
                ldmat4(af[mt], abase + SWZ128(off));
            }
            #pragma unroll
            for (int np = 0; np < 2; ++np) {
                const uint32_t off = (wn + np * 16 + b_row) * 128 + kk * 32 + b_byte;
                uint32_t r[4];
                ldmat4(r, bbase + SWZ128(off));
                bf[np*2][0]   = r[0]; bf[np*2][1]   = r[1];
                bf[np*2+1][0] = r[2]; bf[np*2+1][1] = r[3];
            }
            #pragma unroll
            for (int mt = 0; mt < 4; ++mt)
                #pragma unroll
                for (int r = 0; r < 4; ++r) af[mt][r] = f2tf32(af[mt][r]);
            #pragma unroll
            for (int nt = 0; nt < 4; ++nt) {
                bf[nt][0] = f2tf32(bf[nt][0]);
                bf[nt][1] = f2tf32(bf[nt][1]);
            }
            #pragma unroll
            for (int mt = 0; mt < 4; ++mt)
                #pragma unroll
                for (int nt = 0; nt < 4; ++nt)
                    mma_tf32(acc[mt][nt], af[mt], bf[nt]);
        }
        stage = (stage + 1) % 3;
    }

    const int g  = lane >> 2;
    const int qd = lane & 3;
    #pragma unroll
    for (int nt = 0; nt < 4; ++nt) {
        const int col = bn + wn + nt * 8 + qd * 2;
        const float2 bv = *(const float2*)&bias[col];
        #pragma unroll
        for (int mt = 0; mt < 4; ++mt) {
            const int row0 = bm + wm + mt * 16 + g;
            float2 v0, v1;
            v0.x = acc[mt][nt][0] + bv.x;
            v0.y = acc[mt][nt][1] + bv.y;
            v1.x = acc[mt][nt][2] + bv.x;
            v1.y = acc[mt][nt][3] + bv.y;
            if (MODE == 1) {
                const int part = col >> 10;
                const int h = (col & 1023) >> 6;
                const int d = col & 63;
                float* dst = (part == 0) ? g_q : (part == 1) ? g_k : g_v;
                const int b0i = row0 >> 11, s0 = row0 & 2047;
                const int b1i = (row0 + 8) >> 11, s1 = (row0 + 8) & 2047;
                *(float2*)&dst[(((size_t)(b0i*NH + h))*SEQ + s0)*DH + d] = v0;
                *(float2*)&dst[(((size_t)(b1i*NH + h))*SEQ + s1)*DH + d] = v1;
            } else {
                *(float2*)&C[(size_t)row0 * N + col] = v0;
                *(float2*)&C[(size_t)(row0 + 8) * N + col] = v1;
            }
        }
    }
}

// ---------------------------------------------------------------------------
// Flash attention, both GEMMs on mma.sync tf32 (R7-proven math), now with:
//  - K tiles double-buffered via cp.async (prefetch K(t+1) during compute)
//  - V loaded into registers before the K wait; STS after S-mma
// ---------------------------------------------------------------------------
#define AQ 128
#define AK 64
#define ASH_Q  0                     // 2 planes x 128 x 128B = 32768
#define ASH_K0 32768                 // 16384
#define ASH_K1 49152                 // 16384
#define ASH_VT 65536                 // 16384 (row=dh, col=key, 2 planes)
#define ASH_PA 81920                 // 32768 (row=q, col=key, 2 planes)
#define ASH_C  114688                // corr[128]
#define ASH_L  115200                // l[128]
#define ASH_TOTAL 115712

__global__ __launch_bounds__(128) void attn_tc2(const int* __restrict__ cmask)
{
    extern __shared__ __align__(1024) char smem[];
    const uint32_t sb = smem_u32(smem);
    float* Csh = (float*)(smem + ASH_C);
    float* Lsh = (float*)(smem + ASH_L);

    const int tid  = threadIdx.x;
    const int lane = tid & 31;
    const int warp = tid >> 5;
    const int bh   = blockIdx.x;
    const int qt   = gridDim.y - 1 - blockIdx.y;   // heavy tiles first
    const int q0   = qt * AQ;
    const int qi   = q0 + tid;

    const bool causal = (cmask[0] != 0);

    const float* gq  = g_q + ((size_t)bh * SEQ + q0) * DH;
    const float* gkb = g_k + (size_t)bh * SEQ * DH;
    const float* gvb = g_v + (size_t)bh * SEQ * DH;

    const int a_row  = lane & 15;
    const int a_byte = ((lane >> 4) & 1) * 16;
    const int b_row  = (lane & 7) + (((lane >> 4) & 1) << 3);
    const int b_byte = ((lane >> 3) & 1) * 16;
    const int g  = lane >> 2;
    const int qh = lane & 3;

    // ---- Q tile (cp.async, group 0) ----
    #pragma unroll
    for (int i = 0; i < 16; ++i) {
        const int c = tid + i * 128;
        const int row = c >> 4, f4 = c & 15;
        const uint32_t dst = sb + ASH_Q + (f4 >> 3) * 16384
                           + SWZ128((uint32_t)(row * 128 + (f4 & 7) * 16));
        cp_async16(dst, gq + (size_t)row * DH + f4 * 4);
    }
    CP_COMMIT();

    // ---- K(0) tile (cp.async, group 1) ----
    #pragma unroll
    for (int i = 0; i < 8; ++i) {
        const int c = tid + i * 128;
        const int row = c >> 4, f4 = c & 15;
        const uint32_t dst = sb + ASH_K0 + (f4 >> 3) * 8192
                           + SWZ128((uint32_t)(row * 128 + (f4 & 7) * 16));
        cp_async16(dst, gkb + (size_t)row * DH + f4 * 4);
    }
    CP_COMMIT();

    float oa[2][8][4];
    #pragma unroll
    for (int mt = 0; mt < 2; ++mt)
        #pragma unroll
        for (int nt = 0; nt < 8; ++nt)
            #pragma unroll
            for (int c = 0; c < 4; ++c) oa[mt][nt][c] = 0.f;
    float m = -1e30f, l = 0.f;

    const int ntiles = causal ? (q0 / AK + 2) : (SEQ / AK);
    const int vkey = tid & 63;
    const int vds  = tid >> 6;

    for (int t = 0; t < ntiles; ++t) {
        const int k0 = t * AK;
        const uint32_t kbase = sb + ((t & 1) ? ASH_K1 : ASH_K0);

        // ---- V(t) -> registers (LDG in flight across the K wait + S-mma) ----
        float4 vreg[8];
        #pragma unroll
        for (int i = 0; i < 8; ++i)
            vreg[i] = *(const float4*)(gvb + (size_t)(k0 + vkey) * DH + (vds + i * 2) * 4);

        CP_WAIT0();
        __syncthreads();

        // ---- prefetch K(t+1) into alternate buffer ----
        if (t + 1 < ntiles) {
            const uint32_t knext = ((t & 1) ? ASH_K0 : ASH_K1);
            #pragma unroll
            for (int i = 0; i < 8; ++i) {
                const int c = tid + i * 128;
                const int row = c >> 4, f4 = c & 15;
                const uint32_t dst = sb + knext + (f4 >> 3) * 8192
                                   + SWZ128((uint32_t)(row * 128 + (f4 & 7) * 16));
                cp_async16(dst, gkb + (size_t)(k0 + AK + row) * DH + f4 * 4);
            }
            CP_COMMIT();
        }

        // ---- S = Q @ K^T (proven fragment paths) ----
        float sc[2][8][4];
        #pragma unroll
        for (int mt = 0; mt < 2; ++mt)
            #pragma unroll
            for (int nt = 0; nt < 8; ++nt)
                #pragma unroll
                for (int c = 0; c < 4; ++c) sc[mt][nt][c] = 0.f;

        #pragma unroll
        for (int kk = 0; kk < 8; ++kk) {
            const uint32_t qpl = sb + ASH_Q + (kk >> 2) * 16384;
            const uint32_t kpl = kbase + (kk >> 2) * 8192;
            uint32_t aq[2][4], bf[8][2];
            #pragma unroll
            for (int mt = 0; mt < 2; ++mt) {
                const uint32_t off = (warp*32 + mt*16 + a_row) * 128 + (kk & 3) * 32 + a_byte;
                ldmat4(aq[mt], qpl + SWZ128(off));
                #pragma unroll
                for (int r = 0; r < 4; ++r) aq[mt][r] = f2tf32(aq[mt][r]);
            }
            #pragma unroll
            for (int np = 0; np < 4; ++np) {
                const uint32_t off = (np*16 + b_row) * 128 + (kk & 3) * 32 + b_byte;
                uint32_t r[4];
                ldmat4(r, kpl + SWZ128(off));
                bf[np*2][0]   = f2tf32(r[0]); bf[np*2][1]   = f2tf32(r[1]);
                bf[np*2+1][0] = f2tf32(r[2]); bf[np*2+1][1] = f2tf32(r[3]);
            }
            #pragma unroll
            for (int mt = 0; mt < 2; ++mt)
                #pragma unroll
                for (int nt = 0; nt < 8; ++nt)
                    mma_tf32(sc[mt][nt], aq[mt], bf[nt]);
        }

        // ---- V(t) registers -> V^T smem (proven swizzled layout) ----
        {
            const int pl = ASH_VT + (vkey >> 5) * 8192;
            const uint32_t kb = (uint32_t)(vkey & 31) * 4;
            #pragma unroll
            for (int i = 0; i < 8; ++i) {
                const int d4 = vds + i * 2;
                *(float*)(smem + pl + SWZ128((uint32_t)((d4*4+0) * 128) + kb)) = vreg[i].x;
                *(float*)(smem + pl + SWZ128((uint32_t)((d4*4+1) * 128) + kb)) = vreg[i].y;
                *(float*)(smem + pl + SWZ128((uint32_t)((d4*4+2) * 128) + kb)) = vreg[i].z;
                *(float*)(smem + pl + SWZ128((uint32_t)((d4*4+3) * 128) + kb)) = vreg[i].w;
            }
        }

        // ---- S fragments -> P_A (row-major swizzled, warp-private rows) ----
        #pragma unroll
        for (int mt = 0; mt < 2; ++mt) {
            const int row = warp*32 + mt*16 + g;
            #pragma unroll
            for (int nt = 0; nt < 8; ++nt) {
                const int col = nt*8 + 2*qh;
                const int pl  = ASH_PA + (col >> 5) * 16384;
                const uint32_t cb = (uint32_t)(col & 31) * 4;
                float2 v01, v23;
                v01.x = sc[mt][nt][0]; v01.y = sc[mt][nt][1];
                v23.x = sc[mt][nt][2]; v23.y = sc[mt][nt][3];
                *(float2*)(smem + pl + SWZ128((uint32_t)(row * 128) + cb))       = v01;
                *(float2*)(smem + pl + SWZ128((uint32_t)((row + 8) * 128) + cb)) = v23;
            }
        }
        __syncwarp();

        // ---- scalar softmax on row `tid` of P_A, in place (proven) ----
        const int jlim = causal ? min(AK, qi - k0 + 1) : AK;
        float corr;
        float* sf = &sc[0][0][0];
        if (jlim > 0) {
            #pragma unroll
            for (int j4 = 0; j4 < 16; ++j4) {
                const float4 v = *(const float4*)(smem + ASH_PA + (j4 >> 3) * 16384
                               + SWZ128((uint32_t)(tid * 128 + (j4 & 7) * 16)));
                sf[j4*4+0] = v.x; sf[j4*4+1] = v.y;
                sf[j4*4+2] = v.z; sf[j4*4+3] = v.w;
            }
            float tmax = -1e30f;
            #pragma unroll
            for (int j = 0; j < 64; ++j)
                if (j < jlim) tmax = fmaxf(tmax, sf[j]);
            tmax *= 0.125f;
            const float mn = fmaxf(m, tmax);
            corr = __expf(m - mn);
            m = mn;
            float rs = 0.f;
            #pragma unroll
            for (int j = 0; j < 64; ++j) {
                const float p = (j < jlim) ? __expf(sf[j] * 0.125f - mn) : 0.f;
                sf[j] = p;
                rs += p;
            }
            l = l * corr + rs;
            #pragma unroll
            for (int j4 = 0; j4 < 16; ++j4) {
                float4 v;
                v.x = sf[j4*4+0]; v.y = sf[j4*4+1];
                v.z = sf[j4*4+2]; v.w = sf[j4*4+3];
                *(float4*)(smem + ASH_PA + (j4 >> 3) * 16384
                  + SWZ128((uint32_t)(tid * 128 + (j4 & 7) * 16))) = v;
            }
        } else {
            corr = 1.f;
            const float4 z = {0.f, 0.f, 0.f, 0.f};
            #pragma unroll
            for (int j4 = 0; j4 < 16; ++j4)
                *(float4*)(smem + ASH_PA + (j4 >> 3) * 16384
                  + SWZ128((uint32_t)(tid * 128 + (j4 & 7) * 16))) = z;
        }
        Csh[tid] = corr;
        __syncwarp();

        // ---- apply row-correction to O fragments ----
        #pragma unroll
        for (int mt = 0; mt < 2; ++mt) {
            const float cA = Csh[warp*32 + mt*16 + g];
            const float cB = Csh[warp*32 + mt*16 + g + 8];
            #pragma unroll
            for (int nt = 0; nt < 8; ++nt) {
                oa[mt][nt][0] *= cA; oa[mt][nt][1] *= cA;
                oa[mt][nt][2] *= cB; oa[mt][nt][3] *= cB;
            }
        }

        __syncthreads();   // V^T visible to all warps

        // ---- O += P @ V (proven fragment paths) ----
        #pragma unroll
        for (int kk = 0; kk < 8; ++kk) {
            uint32_t ap[2][4], bf[8][2];
            #pragma unroll
            for (int mt = 0; mt < 2; ++mt) {
                const uint32_t off = (warp*32 + mt*16 + a_row) * 128 + (kk & 3) * 32 + a_byte;
                ldmat4(ap[mt], sb + ASH_PA + (kk >> 2) * 16384 + SWZ128(off));
                #pragma unroll
                for (int r = 0; r < 4; ++r) ap[mt][r] = f2tf32(ap[mt][r]);
            }
            #pragma unroll
            for (int np = 0; np < 4; ++np) {
                const uint32_t off = (np*16 + b_row) * 128 + (kk & 3) * 32 + b_byte;
                uint32_t r[4];
                ldmat4(r, sb + ASH_VT + (kk >> 2) * 8192 + SWZ128(off));
                bf[np*2][0]   = f2tf32(r[0]); bf[np*2][1]   = f2tf32(r[1]);
                bf[np*2+1][0] = f2tf32(r[2]); bf[np*2+1][1] = f2tf32(r[3]);
            }
            #pragma unroll
            for (int mt = 0; mt < 2; ++mt)
                #pragma unroll
                for (int nt = 0; nt < 8; ++nt)
                    mma_tf32(oa[mt][nt], ap[mt], bf[nt]);
        }
    }

    // ---- normalize + write to g_a [token][h*64+d] ----
    Lsh[tid] = l;
    __syncwarp();
    const int b = bh >> 4, h = bh & 15;
    #pragma unroll
    for (int mt = 0; mt < 2; ++mt) {
        const int r0 = warp*32 + mt*16 + g;
        const float i0 = 1.f / fmaxf(Lsh[r0], 1e-30f);
        const float i1 = 1.f / fmaxf(Lsh[r0 + 8], 1e-30f);
        float* o0 = g_a + ((size_t)(b * SEQ + q0 + r0)) * DEMB + h * DH;
        float* o1 = g_a + ((size_t)(b * SEQ + q0 + r0 + 8)) * DEMB + h * DH;
        #pragma unroll
        for (int nt = 0; nt < 8; ++nt) {
            float2 v0, v1;
            v0.x = oa[mt][nt][0] * i0; v0.y = oa[mt][nt][1] * i0;
            v1.x = oa[mt][nt][2] * i1; v1.y = oa[mt][nt][3] * i1;
            *(float2*)(o0 + nt*8 + 2*qh) = v0;
            *(float2*)(o1 + nt*8 + 2*qh) = v1;
        }
    }
}

// ---------------------------------------------------------------------------
extern "C" void kernel_launch(void* const* d_in, const int* in_sizes, int n_in,
                              void* d_out, int out_size)
{
    const float* x     = (const float*)d_in[0];
    const float* w_in  = (const float*)d_in[1];
    const float* b_in  = (const float*)d_in[2];
    const float* w_out = (const float*)d_in[3];
    const float* b_out = (const float*)d_in[4];
    const int*   cmask = (const int*)d_in[5];
    float* out = (float*)d_out;

    cudaFuncSetAttribute(gemm_tc<1>, cudaFuncAttributeMaxDynamicSharedMemorySize, SM_TOTAL);
    cudaFuncSetAttribute(gemm_tc<2>, cudaFuncAttributeMaxDynamicSharedMemorySize, SM_TOTAL);
    cudaFuncSetAttribute(attn_tc2,   cudaFuncAttributeMaxDynamicSharedMemorySize, ASH_TOTAL);

    // 1) QKV projection (mma.sync tf32, 3-stage) + scatter into [B,H,S,dh]
    gemm_tc<1><<<dim3(QKV_N/NT, NTOK/MT), 256, SM_TOTAL>>>(
        x, w_in, b_in, nullptr, NTOK, QKV_N, DEMB);

    // 2) Flash attention (mma.sync, pipelined K + reg-V) -> g_a
    attn_tc2<<<dim3(BATCH*NH, SEQ/AQ), 128, ASH_TOTAL>>>(cmask);

    // 3) Output projection (mma.sync tf32, 3-stage)
    gemm_tc<2><<<dim3(DEMB/NT, NTOK/MT), 256, SM_TOTAL>>>(
        nullptr, w_out, b_out, out, NTOK, DEMB, DEMB);
}

// round 9
// speedup vs baseline: 3.7576x; 1.0306x over previous
#include <cuda_runtime.h>
#include <cstdint>

// Problem constants
#define BATCH   2
#define SEQ     2048
#define NH      16
#define DH      64
#define DEMB    1024
#define NTOK    (BATCH*SEQ)      // 4096
#define QKV_N   (3*DEMB)         // 3072

// Scratch (device globals — no allocation inside kernel_launch)
__device__ float g_q[(size_t)BATCH*NH*SEQ*DH];
__device__ float g_k[(size_t)BATCH*NH*SEQ*DH];
__device__ float g_v[(size_t)BATCH*NH*SEQ*DH];
__device__ float g_a[(size_t)NTOK*DEMB];
// tf32-pre-rounded copies of inputs
__device__ float g_x [(size_t)NTOK*DEMB];
__device__ float g_wi[(size_t)QKV_N*DEMB];
__device__ float g_wo[(size_t)DEMB*DEMB];

// ---------------------------------------------------------------------------
// Helpers (compute_103-safe: cp.async, ldmatrix, mma.sync tf32)
// ---------------------------------------------------------------------------
__device__ __forceinline__ uint32_t smem_u32(const void* p) {
    uint32_t a;
    asm("{ .reg .u64 t; cvta.to.shared.u64 t, %1; cvt.u32.u64 %0, t; }"
        : "=r"(a) : "l"(p));
    return a;
}
__device__ __forceinline__ void cp_async16(uint32_t dst, const void* src) {
    asm volatile("cp.async.cg.shared.global [%0], [%1], 16;\n" :: "r"(dst), "l"(src));
}
#define CP_COMMIT()  asm volatile("cp.async.commit_group;\n" ::: "memory")
#define CP_WAIT0()   asm volatile("cp.async.wait_group 0;\n" ::: "memory")
#define CP_WAIT1()   asm volatile("cp.async.wait_group 1;\n" ::: "memory")

#define SWZ128(off)  ((off) ^ (((off) >> 3) & 0x70))

__device__ __forceinline__ void ldmat4(uint32_t* r, uint32_t addr) {
    asm volatile("ldmatrix.sync.aligned.m8n8.x4.shared.b16 {%0,%1,%2,%3}, [%4];"
        : "=r"(r[0]), "=r"(r[1]), "=r"(r[2]), "=r"(r[3]) : "r"(addr));
}
__device__ __forceinline__ float f2tf32f(float x) {
    uint32_t o;
    asm("cvt.rna.tf32.f32 %0, %1;" : "=r"(o) : "f"(x));
    return __uint_as_float(o);
}
__device__ __forceinline__ void mma_tf32(float* d, const uint32_t* a, const uint32_t* b) {
    asm volatile(
        "mma.sync.aligned.m16n8k8.row.col.f32.tf32.tf32.f32 "
        "{%0,%1,%2,%3}, {%4,%5,%6,%7}, {%8,%9}, {%0,%1,%2,%3};"
        : "+f"(d[0]), "+f"(d[1]), "+f"(d[2]), "+f"(d[3])
        : "r"(a[0]), "r"(a[1]), "r"(a[2]), "r"(a[3]), "r"(b[0]), "r"(b[1]));
}

// ---------------------------------------------------------------------------
// Prepass: tf32-round inputs into device-global copies (float4 vectorized)
// WHICH: 0 -> g_x, 1 -> g_wi, 2 -> g_wo
// ---------------------------------------------------------------------------
template<int WHICH>
__global__ __launch_bounds__(256) void round_copy(const float* __restrict__ src, int n4)
{
    float* dst = (WHICH == 0) ? g_x : (WHICH == 1) ? g_wi : g_wo;
    const int i = blockIdx.x * 256 + threadIdx.x;
    if (i < n4) {
        float4 v = ((const float4*)src)[i];
        v.x = f2tf32f(v.x); v.y = f2tf32f(v.y);
        v.z = f2tf32f(v.z); v.w = f2tf32f(v.w);
        ((float4*)dst)[i] = v;
    }
}

// ---------------------------------------------------------------------------
// mma.sync tf32 GEMM: C[M,N] = A[M,K] @ B[N,K]^T + bias[N]
// All operands pre-rounded to tf32 -> NO cvt in the inner loop.
// 3-stage cp.async pipeline. MODE 1: A=g_x, B=g_wi, scatter epilogue
// (rounded). MODE 2: A=g_a (pre-rounded), B=g_wo, plain epilogue (full fp32).
// ---------------------------------------------------------------------------
#define MT 128
#define NT 128
#define KC 32

#define SM_STAGE (MT*128 + NT*128)     // 32768 per stage (A then B)
#define SM_TOTAL (3*SM_STAGE)          // 98304

template<int ROWS>
__device__ __forceinline__ void load_tile(uint32_t sbase, const float* __restrict__ g,
                                          int K, int k0, int tid) {
    #pragma unroll
    for (int t = 0; t < ROWS * 8 / 256; ++t) {
        const int c = tid + t * 256;
        const int row = c >> 3, kc = c & 7;
        const uint32_t off = row * 128 + kc * 16;
        cp_async16(sbase + SWZ128(off), g + (size_t)row * K + k0 + kc * 4);
    }
}

template<int MODE>
__global__ __launch_bounds__(256)
void gemm_tc(const float* __restrict__ bias, float* __restrict__ C,
             int M, int N, int K)
{
    extern __shared__ __align__(1024) char smem[];
    const uint32_t sb = smem_u32(smem);
    const int tid  = threadIdx.x;
    const int lane = tid & 31;
    const int warp = tid >> 5;
    const int wm   = (warp >> 2) * 64;
    const int wn   = (warp & 3) * 32;
    const int bm   = blockIdx.y * MT;
    const int bn   = blockIdx.x * NT;

    const float* Abase = (MODE == 2) ? (const float*)g_a : (const float*)g_x;
    const float* Bbase = (MODE == 2) ? (const float*)g_wo : (const float*)g_wi;
    const float* Ag = Abase + (size_t)bm * K;
    const float* Bg = Bbase + (size_t)bn * K;

    float acc[4][4][4];
    #pragma unroll
    for (int i = 0; i < 4; i++)
        #pragma unroll
        for (int j = 0; j < 4; j++)
            #pragma unroll
            for (int r = 0; r < 4; r++) acc[i][j][r] = 0.f;

    const int a_row  = lane & 15;
    const int a_byte = ((lane >> 4) & 1) * 16;
    const int b_row  = (lane & 7) + (((lane >> 4) & 1) << 3);
    const int b_byte = ((lane >> 3) & 1) * 16;

    // prologue: stages 0,1
    load_tile<MT>(sb + 0*SM_STAGE, Ag, K, 0, tid);
    load_tile<NT>(sb + 0*SM_STAGE + MT*128, Bg, K, 0, tid);
    CP_COMMIT();
    load_tile<MT>(sb + 1*SM_STAGE, Ag, K, KC, tid);
    load_tile<NT>(sb + 1*SM_STAGE + MT*128, Bg, K, KC, tid);
    CP_COMMIT();

    const int niter = K / KC;
    int stage = 0;
    for (int it = 0; it < niter; ++it) {
        if (it + 1 < niter) { CP_WAIT1(); } else { CP_WAIT0(); }
        __syncthreads();

        if (it + 2 < niter) {
            const int s2 = (stage + 2) % 3;
            load_tile<MT>(sb + s2*SM_STAGE, Ag, K, (it + 2) * KC, tid);
            load_tile<NT>(sb + s2*SM_STAGE + MT*128, Bg, K, (it + 2) * KC, tid);
            CP_COMMIT();
        }

        const uint32_t abase = sb + stage*SM_STAGE;
        const uint32_t bbase = abase + MT*128;

        #pragma unroll
        for (int kk = 0; kk < KC / 8; ++kk) {
            uint32_t af[4][4], bf[4][2];
            #pragma unroll
            for (int mt = 0; mt < 4; ++mt) {
                const uint32_t off = (wm + mt * 16 + a_row) * 128 + kk * 32 + a_byte;
                ldmat4(af[mt], abase + SWZ128(off));
            }
            #pragma unroll
            for (int np = 0; np < 2; ++np) {
                const uint32_t off = (wn + np * 16 + b_row) * 128 + kk * 32 + b_byte;
                uint32_t r[4];
                ldmat4(r, bbase + SWZ128(off));
                bf[np*2][0]   = r[0]; bf[np*2][1]   = r[1];
                bf[np*2+1][0] = r[2]; bf[np*2+1][1] = r[3];
            }
            #pragma unroll
            for (int mt = 0; mt < 4; ++mt)
                #pragma unroll
                for (int nt = 0; nt < 4; ++nt)
                    mma_tf32(acc[mt][nt], af[mt], bf[nt]);
        }
        stage = (stage + 1) % 3;
    }

    const int g  = lane >> 2;
    const int qd = lane & 3;
    #pragma unroll
    for (int nt = 0; nt < 4; ++nt) {
        const int col = bn + wn + nt * 8 + qd * 2;
        const float2 bv = *(const float2*)&bias[col];
        #pragma unroll
        for (int mt = 0; mt < 4; ++mt) {
            const int row0 = bm + wm + mt * 16 + g;
            float2 v0, v1;
            v0.x = acc[mt][nt][0] + bv.x;
            v0.y = acc[mt][nt][1] + bv.y;
            v1.x = acc[mt][nt][2] + bv.x;
            v1.y = acc[mt][nt][3] + bv.y;
            if (MODE == 1) {
                // pre-round Q/K/V to tf32 so attention needs no fragment cvt
                v0.x = f2tf32f(v0.x); v0.y = f2tf32f(v0.y);
                v1.x = f2tf32f(v1.x); v1.y = f2tf32f(v1.y);
                const int part = col >> 10;
                const int h = (col & 1023) >> 6;
                const int d = col & 63;
                float* dst = (part == 0) ? g_q : (part == 1) ? g_k : g_v;
                const int b0i = row0 >> 11, s0 = row0 & 2047;
                const int b1i = (row0 + 8) >> 11, s1 = (row0 + 8) & 2047;
                *(float2*)&dst[(((size_t)(b0i*NH + h))*SEQ + s0)*DH + d] = v0;
                *(float2*)&dst[(((size_t)(b1i*NH + h))*SEQ + s1)*DH + d] = v1;
            } else {
                *(float2*)&C[(size_t)row0 * N + col] = v0;
                *(float2*)&C[(size_t)(row0 + 8) * N + col] = v1;
            }
        }
    }
}

// ---------------------------------------------------------------------------
// Flash attention, both GEMMs on mma.sync tf32. Q/K/V arrive pre-rounded;
// P rounded at softmax store; NO cvt in any fragment path.
// ---------------------------------------------------------------------------
#define AQ 128
#define AK 64
#define ASH_Q  0                     // 2 planes x 128 x 128B = 32768
#define ASH_K0 32768                 // 16384
#define ASH_K1 49152                 // 16384
#define ASH_VT 65536                 // 16384 (row=dh, col=key, 2 planes)
#define ASH_PA 81920                 // 32768 (row=q, col=key, 2 planes)
#define ASH_C  114688                // corr[128]
#define ASH_L  115200                // l[128]
#define ASH_TOTAL 115712

__global__ __launch_bounds__(128) void attn_tc2(const int* __restrict__ cmask)
{
    extern __shared__ __align__(1024) char smem[];
    const uint32_t sb = smem_u32(smem);
    float* Csh = (float*)(smem + ASH_C);
    float* Lsh = (float*)(smem + ASH_L);

    const int tid  = threadIdx.x;
    const int lane = tid & 31;
    const int warp = tid >> 5;
    const int bh   = blockIdx.x;
    const int qt   = gridDim.y - 1 - blockIdx.y;   // heavy tiles first
    const int q0   = qt * AQ;
    const int qi   = q0 + tid;

    const bool causal = (cmask[0] != 0);

    const float* gq  = g_q + ((size_t)bh * SEQ + q0) * DH;
    const float* gkb = g_k + (size_t)bh * SEQ * DH;
    const float* gvb = g_v + (size_t)bh * SEQ * DH;

    const int a_row  = lane & 15;
    const int a_byte = ((lane >> 4) & 1) * 16;
    const int b_row  = (lane & 7) + (((lane >> 4) & 1) << 3);
    const int b_byte = ((lane >> 3) & 1) * 16;
    const int g  = lane >> 2;
    const int qh = lane & 3;

    // ---- Q tile (cp.async) ----
    #pragma unroll
    for (int i = 0; i < 16; ++i) {
        const int c = tid + i * 128;
        const int row = c >> 4, f4 = c & 15;
        const uint32_t dst = sb + ASH_Q + (f4 >> 3) * 16384
                           + SWZ128((uint32_t)(row * 128 + (f4 & 7) * 16));
        cp_async16(dst, gq + (size_t)row * DH + f4 * 4);
    }
    CP_COMMIT();

    // ---- K(0) tile (cp.async) ----
    #pragma unroll
    for (int i = 0; i < 8; ++i) {
        const int c = tid + i * 128;
        const int row = c >> 4, f4 = c & 15;
        const uint32_t dst = sb + ASH_K0 + (f4 >> 3) * 8192
                           + SWZ128((uint32_t)(row * 128 + (f4 & 7) * 16));
        cp_async16(dst, gkb + (size_t)row * DH + f4 * 4);
    }
    CP_COMMIT();

    float oa[2][8][4];
    #pragma unroll
    for (int mt = 0; mt < 2; ++mt)
        #pragma unroll
        for (int nt = 0; nt < 8; ++nt)
            #pragma unroll
            for (int c = 0; c < 4; ++c) oa[mt][nt][c] = 0.f;
    float m = -1e30f, l = 0.f;

    const int ntiles = causal ? (q0 / AK + 2) : (SEQ / AK);
    const int vkey = tid & 63;
    const int vds  = tid >> 6;

    for (int t = 0; t < ntiles; ++t) {
        const int k0 = t * AK;
        const uint32_t kbase = sb + ((t & 1) ? ASH_K1 : ASH_K0);

        // ---- V(t) -> registers (LDG in flight across K wait + S-mma) ----
        float4 vreg[8];
        #pragma unroll
        for (int i = 0; i < 8; ++i)
            vreg[i] = *(const float4*)(gvb + (size_t)(k0 + vkey) * DH + (vds + i * 2) * 4);

        CP_WAIT0();
        __syncthreads();

        // ---- prefetch K(t+1) ----
        if (t + 1 < ntiles) {
            const uint32_t knext = ((t & 1) ? ASH_K0 : ASH_K1);
            #pragma unroll
            for (int i = 0; i < 8; ++i) {
                const int c = tid + i * 128;
                const int row = c >> 4, f4 = c & 15;
                const uint32_t dst = sb + knext + (f4 >> 3) * 8192
                                   + SWZ128((uint32_t)(row * 128 + (f4 & 7) * 16));
                cp_async16(dst, gkb + (size_t)(k0 + AK + row) * DH + f4 * 4);
            }
            CP_COMMIT();
        }

        // ---- S = Q @ K^T (no cvt: Q,K pre-rounded) ----
        float sc[2][8][4];
        #pragma unroll
        for (int mt = 0; mt < 2; ++mt)
            #pragma unroll
            for (int nt = 0; nt < 8; ++nt)
                #pragma unroll
                for (int c = 0; c < 4; ++c) sc[mt][nt][c] = 0.f;

        #pragma unroll
        for (int kk = 0; kk < 8; ++kk) {
            const uint32_t qpl = sb + ASH_Q + (kk >> 2) * 16384;
            const uint32_t kpl = kbase + (kk >> 2) * 8192;
            uint32_t aq[2][4], bf[8][2];
            #pragma unroll
            for (int mt = 0; mt < 2; ++mt) {
                const uint32_t off = (warp*32 + mt*16 + a_row) * 128 + (kk & 3) * 32 + a_byte;
                ldmat4(aq[mt], qpl + SWZ128(off));
            }
            #pragma unroll
            for (int np = 0; np < 4; ++np) {
                const uint32_t off = (np*16 + b_row) * 128 + (kk & 3) * 32 + b_byte;
                uint32_t r[4];
                ldmat4(r, kpl + SWZ128(off));
                bf[np*2][0]   = r[0]; bf[np*2][1]   = r[1];
                bf[np*2+1][0] = r[2]; bf[np*2+1][1] = r[3];
            }
            #pragma unroll
            for (int mt = 0; mt < 2; ++mt)
                #pragma unroll
                for (int nt = 0; nt < 8; ++nt)
                    mma_tf32(sc[mt][nt], aq[mt], bf[nt]);
        }

        // ---- V(t) registers -> V^T smem (pre-rounded; no cvt) ----
        {
            const int pl = ASH_VT + (vkey >> 5) * 8192;
            const uint32_t kb = (uint32_t)(vkey & 31) * 4;
            #pragma unroll
            for (int i = 0; i < 8; ++i) {
                const int d4 = vds + i * 2;
                *(float*)(smem + pl + SWZ128((uint32_t)((d4*4+0) * 128) + kb)) = vreg[i].x;
                *(float*)(smem + pl + SWZ128((uint32_t)((d4*4+1) * 128) + kb)) = vreg[i].y;
                *(float*)(smem + pl + SWZ128((uint32_t)((d4*4+2) * 128) + kb)) = vreg[i].z;
                *(float*)(smem + pl + SWZ128((uint32_t)((d4*4+3) * 128) + kb)) = vreg[i].w;
            }
        }

        // ---- S fragments -> P_A (row-major swizzled, warp-private rows) ----
        #pragma unroll
        for (int mt = 0; mt < 2; ++mt) {
            const int row = warp*32 + mt*16 + g;
            #pragma unroll
            for (int nt = 0; nt < 8; ++nt) {
                const int col = nt*8 + 2*qh;
                const int pl  = ASH_PA + (col >> 5) * 16384;
                const uint32_t cb = (uint32_t)(col & 31) * 4;
                float2 v01, v23;
                v01.x = sc[mt][nt][0]; v01.y = sc[mt][nt][1];
                v23.x = sc[mt][nt][2]; v23.y = sc[mt][nt][3];
                *(float2*)(smem + pl + SWZ128((uint32_t)(row * 128) + cb))       = v01;
                *(float2*)(smem + pl + SWZ128((uint32_t)((row + 8) * 128) + cb)) = v23;
            }
        }
        __syncwarp();

        // ---- scalar softmax on row `tid` of P_A; store rounded P ----
        const int jlim = causal ? min(AK, qi - k0 + 1) : AK;
        float corr;
        float* sf = &sc[0][0][0];
        if (jlim > 0) {
            #pragma unroll
            for (int j4 = 0; j4 < 16; ++j4) {
                const float4 v = *(const float4*)(smem + ASH_PA + (j4 >> 3) * 16384
                               + SWZ128((uint32_t)(tid * 128 + (j4 & 7) * 16)));
                sf[j4*4+0] = v.x; sf[j4*4+1] = v.y;
                sf[j4*4+2] = v.z; sf[j4*4+3] = v.w;
            }
            float tmax = -1e30f;
            #pragma unroll
            for (int j = 0; j < 64; ++j)
                if (j < jlim) tmax = fmaxf(tmax, sf[j]);
            tmax *= 0.125f;
            const float mn = fmaxf(m, tmax);
            corr = __expf(m - mn);
            m = mn;
            float rs = 0.f;
            #pragma unroll
            for (int j = 0; j < 64; ++j) {
                const float p = (j < jlim) ? __expf(sf[j] * 0.125f - mn) : 0.f;
                sf[j] = f2tf32f(p);     // store pre-rounded for PV mma
                rs += p;                // l sums unrounded p (same as before)
            }
            l = l * corr + rs;
            #pragma unroll
            for (int j4 = 0; j4 < 16; ++j4) {
                float4 v;
                v.x = sf[j4*4+0]; v.y = sf[j4*4+1];
                v.z = sf[j4*4+2]; v.w = sf[j4*4+3];
                *(float4*)(smem + ASH_PA + (j4 >> 3) * 16384
                  + SWZ128((uint32_t)(tid * 128 + (j4 & 7) * 16))) = v;
            }
        } else {
            corr = 1.f;
            const float4 z = {0.f, 0.f, 0.f, 0.f};
            #pragma unroll
            for (int j4 = 0; j4 < 16; ++j4)
                *(float4*)(smem + ASH_PA + (j4 >> 3) * 16384
                  + SWZ128((uint32_t)(tid * 128 + (j4 & 7) * 16))) = z;
        }
        Csh[tid] = corr;
        __syncwarp();

        // ---- apply row-correction to O fragments ----
        #pragma unroll
        for (int mt = 0; mt < 2; ++mt) {
            const float cA = Csh[warp*32 + mt*16 + g];
            const float cB = Csh[warp*32 + mt*16 + g + 8];
            #pragma unroll
            for (int nt = 0; nt < 8; ++nt) {
                oa[mt][nt][0] *= cA; oa[mt][nt][1] *= cA;
                oa[mt][nt][2] *= cB; oa[mt][nt][3] *= cB;
            }
        }

        __syncthreads();   // V^T visible to all warps

        // ---- O += P @ V (no cvt: P,V pre-rounded) ----
        #pragma unroll
        for (int kk = 0; kk < 8; ++kk) {
            uint32_t ap[2][4], bf[8][2];
            #pragma unroll
            for (int mt = 0; mt < 2; ++mt) {
                const uint32_t off = (warp*32 + mt*16 + a_row) * 128 + (kk & 3) * 32 + a_byte;
                ldmat4(ap[mt], sb + ASH_PA + (kk >> 2) * 16384 + SWZ128(off));
            }
            #pragma unroll
            for (int np = 0; np < 4; ++np) {
                const uint32_t off = (np*16 + b_row) * 128 + (kk & 3) * 32 + b_byte;
                uint32_t r[4];
                ldmat4(r, sb + ASH_VT + (kk >> 2) * 8192 + SWZ128(off));
                bf[np*2][0]   = r[0]; bf[np*2][1]   = r[1];
                bf[np*2+1][0] = r[2]; bf[np*2+1][1] = r[3];
            }
            #pragma unroll
            for (int mt = 0; mt < 2; ++mt)
                #pragma unroll
                for (int nt = 0; nt < 8; ++nt)
                    mma_tf32(oa[mt][nt], ap[mt], bf[nt]);
        }
    }

    // ---- normalize + write to g_a pre-rounded (out-proj consumes as A) ----
    Lsh[tid] = l;
    __syncwarp();
    const int b = bh >> 4, h = bh & 15;
    #pragma unroll
    for (int mt = 0; mt < 2; ++mt) {
        const int r0 = warp*32 + mt*16 + g;
        const float i0 = 1.f / fmaxf(Lsh[r0], 1e-30f);
        const float i1 = 1.f / fmaxf(Lsh[r0 + 8], 1e-30f);
        float* o0 = g_a + ((size_t)(b * SEQ + q0 + r0)) * DEMB + h * DH;
        float* o1 = g_a + ((size_t)(b * SEQ + q0 + r0 + 8)) * DEMB + h * DH;
        #pragma unroll
        for (int nt = 0; nt < 8; ++nt) {
            float2 v0, v1;
            v0.x = f2tf32f(oa[mt][nt][0] * i0); v0.y = f2tf32f(oa[mt][nt][1] * i0);
            v1.x = f2tf32f(oa[mt][nt][2] * i1); v1.y = f2tf32f(oa[mt][nt][3] * i1);
            *(float2*)(o0 + nt*8 + 2*qh) = v0;
            *(float2*)(o1 + nt*8 + 2*qh) = v1;
        }
    }
}

// ---------------------------------------------------------------------------
extern "C" void kernel_launch(void* const* d_in, const int* in_sizes, int n_in,
                              void* d_out, int out_size)
{
    const float* x     = (const float*)d_in[0];
    const float* w_in  = (const float*)d_in[1];
    const float* b_in  = (const float*)d_in[2];
    const float* w_out = (const float*)d_in[3];
    const float* b_out = (const float*)d_in[4];
    const int*   cmask = (const int*)d_in[5];
    float* out = (float*)d_out;

    cudaFuncSetAttribute(gemm_tc<1>, cudaFuncAttributeMaxDynamicSharedMemorySize, SM_TOTAL);
    cudaFuncSetAttribute(gemm_tc<2>, cudaFuncAttributeMaxDynamicSharedMemorySize, SM_TOTAL);
    cudaFuncSetAttribute(attn_tc2,   cudaFuncAttributeMaxDynamicSharedMemorySize, ASH_TOTAL);

    // 0) Pre-round inputs to tf32 (once per launch; idempotent, deterministic)
    round_copy<0><<<NTOK*DEMB/4/256, 256>>>(x, NTOK*DEMB/4);
    round_copy<1><<<QKV_N*DEMB/4/256, 256>>>(w_in, QKV_N*DEMB/4);
    round_copy<2><<<DEMB*DEMB/4/256, 256>>>(w_out, DEMB*DEMB/4);

    // 1) QKV projection (cvt-free inner loop) + rounded scatter to q/k/v
    gemm_tc<1><<<dim3(QKV_N/NT, NTOK/MT), 256, SM_TOTAL>>>(
        b_in, nullptr, NTOK, QKV_N, DEMB);

    // 2) Flash attention (cvt-free fragment paths) -> g_a (rounded)
    attn_tc2<<<dim3(BATCH*NH, SEQ/AQ), 128, ASH_TOTAL>>>(cmask);

    // 3) Output projection (cvt-free inner loop) -> out (full fp32)
    gemm_tc<2><<<dim3(DEMB/NT, NTOK/MT), 256, SM_TOTAL>>>(
        b_out, out, NTOK, DEMB, DEMB);
}

// round 10
// speedup vs baseline: 4.9089x; 1.3064x over previous
#include <cuda_runtime.h>
#include <cuda_fp16.h>
#include <cstdint>

// Problem constants
#define BATCH   2
#define SEQ     2048
#define NH      16
#define DH      64
#define DEMB    1024
#define NTOK    (BATCH*SEQ)      // 4096
#define QKV_N   (3*DEMB)         // 3072

// Scratch (device globals — no allocation inside kernel_launch)
__device__ float  g_q[(size_t)BATCH*NH*SEQ*DH];
__device__ float  g_k[(size_t)BATCH*NH*SEQ*DH];
__device__ float  g_v[(size_t)BATCH*NH*SEQ*DH];
__device__ __half g_a [(size_t)NTOK*DEMB];      // attention out (half, A of out-proj)
__device__ __half g_xh[(size_t)NTOK*DEMB];      // half copies of inputs
__device__ __half g_wih[(size_t)QKV_N*DEMB];
__device__ __half g_woh[(size_t)DEMB*DEMB];

// ---------------------------------------------------------------------------
// Helpers (compute_103-safe)
// ---------------------------------------------------------------------------
__device__ __forceinline__ uint32_t smem_u32(const void* p) {
    uint32_t a;
    asm("{ .reg .u64 t; cvta.to.shared.u64 t, %1; cvt.u32.u64 %0, t; }"
        : "=r"(a) : "l"(p));
    return a;
}
__device__ __forceinline__ void cp_async16(uint32_t dst, const void* src) {
    asm volatile("cp.async.cg.shared.global [%0], [%1], 16;\n" :: "r"(dst), "l"(src));
}
#define CP_COMMIT()  asm volatile("cp.async.commit_group;\n" ::: "memory")
#define CP_WAIT0()   asm volatile("cp.async.wait_group 0;\n" ::: "memory")
#define CP_WAIT1()   asm volatile("cp.async.wait_group 1;\n" ::: "memory")

#define SWZ128(off)  ((off) ^ (((off) >> 3) & 0x70))

__device__ __forceinline__ void ldmat4(uint32_t* r, uint32_t addr) {
    asm volatile("ldmatrix.sync.aligned.m8n8.x4.shared.b16 {%0,%1,%2,%3}, [%4];"
        : "=r"(r[0]), "=r"(r[1]), "=r"(r[2]), "=r"(r[3]) : "r"(addr));
}
__device__ __forceinline__ float f2tf32f(float x) {
    uint32_t o;
    asm("cvt.rna.tf32.f32 %0, %1;" : "=r"(o) : "f"(x));
    return __uint_as_float(o);
}
__device__ __forceinline__ void mma_tf32(float* d, const uint32_t* a, const uint32_t* b) {
    asm volatile(
        "mma.sync.aligned.m16n8k8.row.col.f32.tf32.tf32.f32 "
        "{%0,%1,%2,%3}, {%4,%5,%6,%7}, {%8,%9}, {%0,%1,%2,%3};"
        : "+f"(d[0]), "+f"(d[1]), "+f"(d[2]), "+f"(d[3])
        : "r"(a[0]), "r"(a[1]), "r"(a[2]), "r"(a[3]), "r"(b[0]), "r"(b[1]));
}
__device__ __forceinline__ void mma_f16(float* d, const uint32_t* a, const uint32_t* b) {
    asm volatile(
        "mma.sync.aligned.m16n8k16.row.col.f32.f16.f16.f32 "
        "{%0,%1,%2,%3}, {%4,%5,%6,%7}, {%8,%9}, {%0,%1,%2,%3};"
        : "+f"(d[0]), "+f"(d[1]), "+f"(d[2]), "+f"(d[3])
        : "r"(a[0]), "r"(a[1]), "r"(a[2]), "r"(a[3]), "r"(b[0]), "r"(b[1]));
}

// ---------------------------------------------------------------------------
// Prepass: fp32 -> fp16 copies (RN). WHICH: 0->g_xh, 1->g_wih, 2->g_woh
// ---------------------------------------------------------------------------
template<int WHICH>
__global__ __launch_bounds__(256) void round_half(const float* __restrict__ src, int n4)
{
    __half* dst = (WHICH == 0) ? g_xh : (WHICH == 1) ? g_wih : g_woh;
    const int i = blockIdx.x * 256 + threadIdx.x;
    if (i < n4) {
        const float4 v = ((const float4*)src)[i];
        __half2 h0 = __floats2half2_rn(v.x, v.y);
        __half2 h1 = __floats2half2_rn(v.z, v.w);
        ((__half2*)dst)[2*i]   = h0;
        ((__half2*)dst)[2*i+1] = h1;
    }
}

// ---------------------------------------------------------------------------
// fp16 HMMA GEMM: C[M,N] = A[M,K] @ B[N,K]^T + bias[N]   (K in halfs)
// Tile 128x128x64, 3-stage cp.async, m16n8k16 mma, fp32 accumulate.
// MODE 1: A=g_xh, B=g_wih, scatter epilogue (tf32-rounded fp32 q/k/v).
// MODE 2: A=g_a (half), B=g_woh, plain fp32 epilogue.
// ---------------------------------------------------------------------------
#define MT 128
#define NT 128
#define KC 64                           // halfs per K-chunk (128 bytes/row)

#define SM_STAGE (MT*128 + NT*128)      // 32768
#define SM_TOTAL (3*SM_STAGE)           // 98304

template<int ROWS>
__device__ __forceinline__ void load_tile_h(uint32_t sbase, const __half* __restrict__ g,
                                            int K, int k0, int tid) {
    #pragma unroll
    for (int t = 0; t < ROWS * 8 / 256; ++t) {
        const int c = tid + t * 256;
        const int row = c >> 3, kc = c & 7;
        const uint32_t off = row * 128 + kc * 16;
        cp_async16(sbase + SWZ128(off), g + (size_t)row * K + k0 + kc * 8);
    }
}

template<int MODE>
__global__ __launch_bounds__(256)
void gemm_h(const float* __restrict__ bias, float* __restrict__ C,
            int M, int N, int K)
{
    extern __shared__ __align__(1024) char smem[];
    const uint32_t sb = smem_u32(smem);
    const int tid  = threadIdx.x;
    const int lane = tid & 31;
    const int warp = tid >> 5;
    const int wm   = (warp >> 2) * 64;
    const int wn   = (warp & 3) * 32;
    const int bm   = blockIdx.y * MT;
    const int bn   = blockIdx.x * NT;

    const __half* Abase = (MODE == 2) ? (const __half*)g_a : (const __half*)g_xh;
    const __half* Bbase = (MODE == 2) ? (const __half*)g_woh : (const __half*)g_wih;
    const __half* Ag = Abase + (size_t)bm * K;
    const __half* Bg = Bbase + (size_t)bn * K;

    float acc[4][4][4];
    #pragma unroll
    for (int i = 0; i < 4; i++)
        #pragma unroll
        for (int j = 0; j < 4; j++)
            #pragma unroll
            for (int r = 0; r < 4; r++) acc[i][j][r] = 0.f;

    const int a_row  = lane & 15;
    const int a_byte = ((lane >> 4) & 1) * 16;
    const int b_row  = (lane & 7) + (((lane >> 4) & 1) << 3);
    const int b_byte = ((lane >> 3) & 1) * 16;

    load_tile_h<MT>(sb + 0*SM_STAGE, Ag, K, 0, tid);
    load_tile_h<NT>(sb + 0*SM_STAGE + MT*128, Bg, K, 0, tid);
    CP_COMMIT();
    load_tile_h<MT>(sb + 1*SM_STAGE, Ag, K, KC, tid);
    load_tile_h<NT>(sb + 1*SM_STAGE + MT*128, Bg, K, KC, tid);
    CP_COMMIT();

    const int niter = K / KC;              // 16
    int stage = 0;
    for (int it = 0; it < niter; ++it) {
        if (it + 1 < niter) { CP_WAIT1(); } else { CP_WAIT0(); }
        __syncthreads();

        if (it + 2 < niter) {
            const int s2 = (stage + 2) % 3;
            load_tile_h<MT>(sb + s2*SM_STAGE, Ag, K, (it + 2) * KC, tid);
            load_tile_h<NT>(sb + s2*SM_STAGE + MT*128, Bg, K, (it + 2) * KC, tid);
            CP_COMMIT();
        }

        const uint32_t abase = sb + stage*SM_STAGE;
        const uint32_t bbase = abase + MT*128;

        #pragma unroll
        for (int kk = 0; kk < KC / 16; ++kk) {     // 4 k16 steps
            uint32_t af[4][4], bf[4][2];
            #pragma unroll
            for (int mt = 0; mt < 4; ++mt) {
                const uint32_t off = (wm + mt * 16 + a_row) * 128 + kk * 32 + a_byte;
                ldmat4(af[mt], abase + SWZ128(off));
            }
            #pragma unroll
            for (int np = 0; np < 2; ++np) {
                const uint32_t off = (wn + np * 16 + b_row) * 128 + kk * 32 + b_byte;
                uint32_t r[4];
                ldmat4(r, bbase + SWZ128(off));
                bf[np*2][0]   = r[0]; bf[np*2][1]   = r[1];
                bf[np*2+1][0] = r[2]; bf[np*2+1][1] = r[3];
            }
            #pragma unroll
            for (int mt = 0; mt < 4; ++mt)
                #pragma unroll
                for (int nt = 0; nt < 4; ++nt)
                    mma_f16(acc[mt][nt], af[mt], bf[nt]);
        }
        stage = (stage + 1) % 3;
    }

    const int g  = lane >> 2;
    const int qd = lane & 3;
    #pragma unroll
    for (int nt = 0; nt < 4; ++nt) {
        const int col = bn + wn + nt * 8 + qd * 2;
        const float2 bv = *(const float2*)&bias[col];
        #pragma unroll
        for (int mt = 0; mt < 4; ++mt) {
            const int row0 = bm + wm + mt * 16 + g;
            float2 v0, v1;
            v0.x = acc[mt][nt][0] + bv.x;
            v0.y = acc[mt][nt][1] + bv.y;
            v1.x = acc[mt][nt][2] + bv.x;
            v1.y = acc[mt][nt][3] + bv.y;
            if (MODE == 1) {
                // tf32-round q/k/v so the (tf32) attention needs no fragment cvt
                v0.x = f2tf32f(v0.x); v0.y = f2tf32f(v0.y);
                v1.x = f2tf32f(v1.x); v1.y = f2tf32f(v1.y);
                const int part = col >> 10;
                const int h = (col & 1023) >> 6;
                const int d = col & 63;
                float* dst = (part == 0) ? g_q : (part == 1) ? g_k : g_v;
                const int b0i = row0 >> 11, s0 = row0 & 2047;
                const int b1i = (row0 + 8) >> 11, s1 = (row0 + 8) & 2047;
                *(float2*)&dst[(((size_t)(b0i*NH + h))*SEQ + s0)*DH + d] = v0;
                *(float2*)&dst[(((size_t)(b1i*NH + h))*SEQ + s1)*DH + d] = v1;
            } else {
                *(float2*)&C[(size_t)row0 * N + col] = v0;
                *(float2*)&C[(size_t)(row0 + 8) * N + col] = v1;
            }
        }
    }
}

// ---------------------------------------------------------------------------
// Flash attention (UNCHANGED R9 tf32 path, proven) — only g_a write is half.
// ---------------------------------------------------------------------------
#define AQ 128
#define AK 64
#define ASH_Q  0
#define ASH_K0 32768
#define ASH_K1 49152
#define ASH_VT 65536
#define ASH_PA 81920
#define ASH_C  114688
#define ASH_L  115200
#define ASH_TOTAL 115712

__global__ __launch_bounds__(128) void attn_tc2(const int* __restrict__ cmask)
{
    extern __shared__ __align__(1024) char smem[];
    const uint32_t sb = smem_u32(smem);
    float* Csh = (float*)(smem + ASH_C);
    float* Lsh = (float*)(smem + ASH_L);

    const int tid  = threadIdx.x;
    const int lane = tid & 31;
    const int warp = tid >> 5;
    const int bh   = blockIdx.x;
    const int qt   = gridDim.y - 1 - blockIdx.y;
    const int q0   = qt * AQ;
    const int qi   = q0 + tid;

    const bool causal = (cmask[0] != 0);

    const float* gq  = g_q + ((size_t)bh * SEQ + q0) * DH;
    const float* gkb = g_k + (size_t)bh * SEQ * DH;
    const float* gvb = g_v + (size_t)bh * SEQ * DH;

    const int a_row  = lane & 15;
    const int a_byte = ((lane >> 4) & 1) * 16;
    const int b_row  = (lane & 7) + (((lane >> 4) & 1) << 3);
    const int b_byte = ((lane >> 3) & 1) * 16;
    const int g  = lane >> 2;
    const int qh = lane & 3;

    #pragma unroll
    for (int i = 0; i < 16; ++i) {
        const int c = tid + i * 128;
        const int row = c >> 4, f4 = c & 15;
        const uint32_t dst = sb + ASH_Q + (f4 >> 3) * 16384
                           + SWZ128((uint32_t)(row * 128 + (f4 & 7) * 16));
        cp_async16(dst, gq + (size_t)row * DH + f4 * 4);
    }
    CP_COMMIT();

    #pragma unroll
    for (int i = 0; i < 8; ++i) {
        const int c = tid + i * 128;
        const int row = c >> 4, f4 = c & 15;
        const uint32_t dst = sb + ASH_K0 + (f4 >> 3) * 8192
                           + SWZ128((uint32_t)(row * 128 + (f4 & 7) * 16));
        cp_async16(dst, gkb + (size_t)row * DH + f4 * 4);
    }
    CP_COMMIT();

    float oa[2][8][4];
    #pragma unroll
    for (int mt = 0; mt < 2; ++mt)
        #pragma unroll
        for (int nt = 0; nt < 8; ++nt)
            #pragma unroll
            for (int c = 0; c < 4; ++c) oa[mt][nt][c] = 0.f;
    float m = -1e30f, l = 0.f;

    const int ntiles = causal ? (q0 / AK + 2) : (SEQ / AK);
    const int vkey = tid & 63;
    const int vds  = tid >> 6;

    for (int t = 0; t < ntiles; ++t) {
        const int k0 = t * AK;
        const uint32_t kbase = sb + ((t & 1) ? ASH_K1 : ASH_K0);

        float4 vreg[8];
        #pragma unroll
        for (int i = 0; i < 8; ++i)
            vreg[i] = *(const float4*)(gvb + (size_t)(k0 + vkey) * DH + (vds + i * 2) * 4);

        CP_WAIT0();
        __syncthreads();

        if (t + 1 < ntiles) {
            const uint32_t knext = ((t & 1) ? ASH_K0 : ASH_K1);
            #pragma unroll
            for (int i = 0; i < 8; ++i) {
                const int c = tid + i * 128;
                const int row = c >> 4, f4 = c & 15;
                const uint32_t dst = sb + knext + (f4 >> 3) * 8192
                                   + SWZ128((uint32_t)(row * 128 + (f4 & 7) * 16));
                cp_async16(dst, gkb + (size_t)(k0 + AK + row) * DH + f4 * 4);
            }
            CP_COMMIT();
        }

        float sc[2][8][4];
        #pragma unroll
        for (int mt = 0; mt < 2; ++mt)
            #pragma unroll
            for (int nt = 0; nt < 8; ++nt)
                #pragma unroll
                for (int c = 0; c < 4; ++c) sc[mt][nt][c] = 0.f;

        #pragma unroll
        for (int kk = 0; kk < 8; ++kk) {
            const uint32_t qpl = sb + ASH_Q + (kk >> 2) * 16384;
            const uint32_t kpl = kbase + (kk >> 2) * 8192;
            uint32_t aq[2][4], bf[8][2];
            #pragma unroll
            for (int mt = 0; mt < 2; ++mt) {
                const uint32_t off = (warp*32 + mt*16 + a_row) * 128 + (kk & 3) * 32 + a_byte;
                ldmat4(aq[mt], qpl + SWZ128(off));
            }
            #pragma unroll
            for (int np = 0; np < 4; ++np) {
                const uint32_t off = (np*16 + b_row) * 128 + (kk & 3) * 32 + b_byte;
                uint32_t r[4];
                ldmat4(r, kpl + SWZ128(off));
                bf[np*2][0]   = r[0]; bf[np*2][1]   = r[1];
                bf[np*2+1][0] = r[2]; bf[np*2+1][1] = r[3];
            }
            #pragma unroll
            for (int mt = 0; mt < 2; ++mt)
                #pragma unroll
                for (int nt = 0; nt < 8; ++nt)
                    mma_tf32(sc[mt][nt], aq[mt], bf[nt]);
        }

        {
            const int pl = ASH_VT + (vkey >> 5) * 8192;
            const uint32_t kb = (uint32_t)(vkey & 31) * 4;
            #pragma unroll
            for (int i = 0; i < 8; ++i) {
                const int d4 = vds + i * 2;
                *(float*)(smem + pl + SWZ128((uint32_t)((d4*4+0) * 128) + kb)) = vreg[i].x;
                *(float*)(smem + pl + SWZ128((uint32_t)((d4*4+1) * 128) + kb)) = vreg[i].y;
                *(float*)(smem + pl + SWZ128((uint32_t)((d4*4+2) * 128) + kb)) = vreg[i].z;
                *(float*)(smem + pl + SWZ128((uint32_t)((d4*4+3) * 128) + kb)) = vreg[i].w;
            }
        }

        #pragma unroll
        for (int mt = 0; mt < 2; ++mt) {
            const int row = warp*32 + mt*16 + g;
            #pragma unroll
            for (int nt = 0; nt < 8; ++nt) {
                const int col = nt*8 + 2*qh;
                const int pl  = ASH_PA + (col >> 5) * 16384;
                const uint32_t cb = (uint32_t)(col & 31) * 4;
                float2 v01, v23;
                v01.x = sc[mt][nt][0]; v01.y = sc[mt][nt][1];
                v23.x = sc[mt][nt][2]; v23.y = sc[mt][nt][3];
                *(float2*)(smem + pl + SWZ128((uint32_t)(row * 128) + cb))       = v01;
                *(float2*)(smem + pl + SWZ128((uint32_t)((row + 8) * 128) + cb)) = v23;
            }
        }
        __syncwarp();

        const int jlim = causal ? min(AK, qi - k0 + 1) : AK;
        float corr;
        float* sf = &sc[0][0][0];
        if (jlim > 0) {
            #pragma unroll
            for (int j4 = 0; j4 < 16; ++j4) {
                const float4 v = *(const float4*)(smem + ASH_PA + (j4 >> 3) * 16384
                               + SWZ128((uint32_t)(tid * 128 + (j4 & 7) * 16)));
                sf[j4*4+0] = v.x; sf[j4*4+1] = v.y;
                sf[j4*4+2] = v.z; sf[j4*4+3] = v.w;
            }
            float tmax = -1e30f;
            #pragma unroll
            for (int j = 0; j < 64; ++j)
                if (j < jlim) tmax = fmaxf(tmax, sf[j]);
            tmax *= 0.125f;
            const float mn = fmaxf(m, tmax);
            corr = __expf(m - mn);
            m = mn;
            float rs = 0.f;
            #pragma unroll
            for (int j = 0; j < 64; ++j) {
                const float p = (j < jlim) ? __expf(sf[j] * 0.125f - mn) : 0.f;
                sf[j] = f2tf32f(p);
                rs += p;
            }
            l = l * corr + rs;
            #pragma unroll
            for (int j4 = 0; j4 < 16; ++j4) {
                float4 v;
                v.x = sf[j4*4+0]; v.y = sf[j4*4+1];
                v.z = sf[j4*4+2]; v.w = sf[j4*4+3];
                *(float4*)(smem + ASH_PA + (j4 >> 3) * 16384
                  + SWZ128((uint32_t)(tid * 128 + (j4 & 7) * 16))) = v;
            }
        } else {
            corr = 1.f;
            const float4 z = {0.f, 0.f, 0.f, 0.f};
            #pragma unroll
            for (int j4 = 0; j4 < 16; ++j4)
                *(float4*)(smem + ASH_PA + (j4 >> 3) * 16384
                  + SWZ128((uint32_t)(tid * 128 + (j4 & 7) * 16))) = z;
        }
        Csh[tid] = corr;
        __syncwarp();

        #pragma unroll
        for (int mt = 0; mt < 2; ++mt) {
            const float cA = Csh[warp*32 + mt*16 + g];
            const float cB = Csh[warp*32 + mt*16 + g + 8];
            #pragma unroll
            for (int nt = 0; nt < 8; ++nt) {
                oa[mt][nt][0] *= cA; oa[mt][nt][1] *= cA;
                oa[mt][nt][2] *= cB; oa[mt][nt][3] *= cB;
            }
        }

        __syncthreads();

        #pragma unroll
        for (int kk = 0; kk < 8; ++kk) {
            uint32_t ap[2][4], bf[8][2];
            #pragma unroll
            for (int mt = 0; mt < 2; ++mt) {
                const uint32_t off = (warp*32 + mt*16 + a_row) * 128 + (kk & 3) * 32 + a_byte;
                ldmat4(ap[mt], sb + ASH_PA + (kk >> 2) * 16384 + SWZ128(off));
            }
            #pragma unroll
            for (int np = 0; np < 4; ++np) {
                const uint32_t off = (np*16 + b_row) * 128 + (kk & 3) * 32 + b_byte;
                uint32_t r[4];
                ldmat4(r, sb + ASH_VT + (kk >> 2) * 8192 + SWZ128(off));
                bf[np*2][0]   = r[0]; bf[np*2][1]   = r[1];
                bf[np*2+1][0] = r[2]; bf[np*2+1][1] = r[3];
            }
            #pragma unroll
            for (int mt = 0; mt < 2; ++mt)
                #pragma unroll
                for (int nt = 0; nt < 8; ++nt)
                    mma_tf32(oa[mt][nt], ap[mt], bf[nt]);
        }
    }

    // ---- normalize + write g_a as HALF (out-proj A operand) ----
    Lsh[tid] = l;
    __syncwarp();
    const int b = bh >> 4, h = bh & 15;
    #pragma unroll
    for (int mt = 0; mt < 2; ++mt) {
        const int r0 = warp*32 + mt*16 + g;
        const float i0 = 1.f / fmaxf(Lsh[r0], 1e-30f);
        const float i1 = 1.f / fmaxf(Lsh[r0 + 8], 1e-30f);
        __half* o0 = g_a + ((size_t)(b * SEQ + q0 + r0)) * DEMB + h * DH;
        __half* o1 = g_a + ((size_t)(b * SEQ + q0 + r0 + 8)) * DEMB + h * DH;
        #pragma unroll
        for (int nt = 0; nt < 8; ++nt) {
            *(__half2*)(o0 + nt*8 + 2*qh) =
                __floats2half2_rn(oa[mt][nt][0] * i0, oa[mt][nt][1] * i0);
            *(__half2*)(o1 + nt*8 + 2*qh) =
                __floats2half2_rn(oa[mt][nt][2] * i1, oa[mt][nt][3] * i1);
        }
    }
}

// ---------------------------------------------------------------------------
extern "C" void kernel_launch(void* const* d_in, const int* in_sizes, int n_in,
                              void* d_out, int out_size)
{
    const float* x     = (const float*)d_in[0];
    const float* w_in  = (const float*)d_in[1];
    const float* b_in  = (const float*)d_in[2];
    const float* w_out = (const float*)d_in[3];
    const float* b_out = (const float*)d_in[4];
    const int*   cmask = (const int*)d_in[5];
    float* out = (float*)d_out;

    cudaFuncSetAttribute(gemm_h<1>, cudaFuncAttributeMaxDynamicSharedMemorySize, SM_TOTAL);
    cudaFuncSetAttribute(gemm_h<2>, cudaFuncAttributeMaxDynamicSharedMemorySize, SM_TOTAL);
    cudaFuncSetAttribute(attn_tc2,  cudaFuncAttributeMaxDynamicSharedMemorySize, ASH_TOTAL);

    // 0) fp32 -> fp16 input copies
    round_half<0><<<NTOK*DEMB/4/256, 256>>>(x, NTOK*DEMB/4);
    round_half<1><<<QKV_N*DEMB/4/256, 256>>>(w_in, QKV_N*DEMB/4);
    round_half<2><<<DEMB*DEMB/4/256, 256>>>(w_out, DEMB*DEMB/4);

    // 1) QKV projection (fp16 HMMA) + tf32-rounded scatter to q/k/v (fp32)
    gemm_h<1><<<dim3(QKV_N/NT, NTOK/MT), 256, SM_TOTAL>>>(
        b_in, nullptr, NTOK, QKV_N, DEMB);

    // 2) Flash attention (tf32, proven) -> g_a (half)
    attn_tc2<<<dim3(BATCH*NH, SEQ/AQ), 128, ASH_TOTAL>>>(cmask);

    // 3) Output projection (fp16 HMMA) -> out (fp32)
    gemm_h<2><<<dim3(DEMB/NT, NTOK/MT), 256, SM_TOTAL>>>(
        b_out, out, NTOK, DEMB, DEMB);
}

// round 11
// speedup vs baseline: 6.3471x; 1.2930x over previous
#include <cuda_runtime.h>
#include <cuda_fp16.h>
#include <cstdint>

// Problem constants
#define BATCH   2
#define SEQ     2048
#define NH      16
#define DH      64
#define DEMB    1024
#define NTOK    (BATCH*SEQ)      // 4096
#define QKV_N   (3*DEMB)         // 3072

// Scratch (device globals — no allocation inside kernel_launch)
__device__ __half g_qh[(size_t)BATCH*NH*SEQ*DH];
__device__ __half g_kh[(size_t)BATCH*NH*SEQ*DH];
__device__ __half g_vh[(size_t)BATCH*NH*SEQ*DH];
__device__ __half g_a [(size_t)NTOK*DEMB];      // attention out (half, A of out-proj)
__device__ __half g_xh[(size_t)NTOK*DEMB];      // half copies of inputs
__device__ __half g_wih[(size_t)QKV_N*DEMB];
__device__ __half g_woh[(size_t)DEMB*DEMB];

// ---------------------------------------------------------------------------
// Helpers (compute_103-safe)
// ---------------------------------------------------------------------------
__device__ __forceinline__ uint32_t smem_u32(const void* p) {
    uint32_t a;
    asm("{ .reg .u64 t; cvta.to.shared.u64 t, %1; cvt.u32.u64 %0, t; }"
        : "=r"(a) : "l"(p));
    return a;
}
__device__ __forceinline__ void cp_async16(uint32_t dst, const void* src) {
    asm volatile("cp.async.cg.shared.global [%0], [%1], 16;\n" :: "r"(dst), "l"(src));
}
#define CP_COMMIT()  asm volatile("cp.async.commit_group;\n" ::: "memory")
#define CP_WAIT0()   asm volatile("cp.async.wait_group 0;\n" ::: "memory")
#define CP_WAIT1()   asm volatile("cp.async.wait_group 1;\n" ::: "memory")

#define SWZ128(off)  ((off) ^ (((off) >> 3) & 0x70))

__device__ __forceinline__ void ldmat4(uint32_t* r, uint32_t addr) {
    asm volatile("ldmatrix.sync.aligned.m8n8.x4.shared.b16 {%0,%1,%2,%3}, [%4];"
        : "=r"(r[0]), "=r"(r[1]), "=r"(r[2]), "=r"(r[3]) : "r"(addr));
}
__device__ __forceinline__ void mma_f16(float* d, const uint32_t* a, const uint32_t* b) {
    asm volatile(
        "mma.sync.aligned.m16n8k16.row.col.f32.f16.f16.f32 "
        "{%0,%1,%2,%3}, {%4,%5,%6,%7}, {%8,%9}, {%0,%1,%2,%3};"
        : "+f"(d[0]), "+f"(d[1]), "+f"(d[2]), "+f"(d[3])
        : "r"(a[0]), "r"(a[1]), "r"(a[2]), "r"(a[3]), "r"(b[0]), "r"(b[1]));
}
__device__ __forceinline__ uint32_t pack_h2(float a, float b) {
    __half2 h = __floats2half2_rn(a, b);
    return *reinterpret_cast<uint32_t*>(&h);
}

// ---------------------------------------------------------------------------
// Prepass: fp32 -> fp16 copies (RN). WHICH: 0->g_xh, 1->g_wih, 2->g_woh
// ---------------------------------------------------------------------------
template<int WHICH>
__global__ __launch_bounds__(256) void round_half(const float* __restrict__ src, int n4)
{
    __half* dst = (WHICH == 0) ? g_xh : (WHICH == 1) ? g_wih : g_woh;
    const int i = blockIdx.x * 256 + threadIdx.x;
    if (i < n4) {
        const float4 v = ((const float4*)src)[i];
        ((__half2*)dst)[2*i]   = __floats2half2_rn(v.x, v.y);
        ((__half2*)dst)[2*i+1] = __floats2half2_rn(v.z, v.w);
    }
}

// ---------------------------------------------------------------------------
// fp16 HMMA GEMM (proven R10): C[M,N] = A[M,K] @ B[N,K]^T + bias[N]
// MODE 1: A=g_xh, B=g_wih, epilogue scatters HALF q/k/v.
// MODE 2: A=g_a (half), B=g_woh, plain fp32 epilogue.
// ---------------------------------------------------------------------------
#define MT 128
#define NT 128
#define KC 64

#define SM_STAGE (MT*128 + NT*128)
#define SM_TOTAL (3*SM_STAGE)           // 98304

template<int ROWS>
__device__ __forceinline__ void load_tile_h(uint32_t sbase, const __half* __restrict__ g,
                                            int K, int k0, int tid) {
    #pragma unroll
    for (int t = 0; t < ROWS * 8 / 256; ++t) {
        const int c = tid + t * 256;
        const int row = c >> 3, kc = c & 7;
        const uint32_t off = row * 128 + kc * 16;
        cp_async16(sbase + SWZ128(off), g + (size_t)row * K + k0 + kc * 8);
    }
}

template<int MODE>
__global__ __launch_bounds__(256)
void gemm_h(const float* __restrict__ bias, float* __restrict__ C,
            int M, int N, int K)
{
    extern __shared__ __align__(1024) char smem[];
    const uint32_t sb = smem_u32(smem);
    const int tid  = threadIdx.x;
    const int lane = tid & 31;
    const int warp = tid >> 5;
    const int wm   = (warp >> 2) * 64;
    const int wn   = (warp & 3) * 32;
    const int bm   = blockIdx.y * MT;
    const int bn   = blockIdx.x * NT;

    const __half* Abase = (MODE == 2) ? (const __half*)g_a : (const __half*)g_xh;
    const __half* Bbase = (MODE == 2) ? (const __half*)g_woh : (const __half*)g_wih;
    const __half* Ag = Abase + (size_t)bm * K;
    const __half* Bg = Bbase + (size_t)bn * K;

    float acc[4][4][4];
    #pragma unroll
    for (int i = 0; i < 4; i++)
        #pragma unroll
        for (int j = 0; j < 4; j++)
            #pragma unroll
            for (int r = 0; r < 4; r++) acc[i][j][r] = 0.f;

    const int a_row  = lane & 15;
    const int a_byte = ((lane >> 4) & 1) * 16;
    const int b_row  = (lane & 7) + (((lane >> 4) & 1) << 3);
    const int b_byte = ((lane >> 3) & 1) * 16;

    load_tile_h<MT>(sb + 0*SM_STAGE, Ag, K, 0, tid);
    load_tile_h<NT>(sb + 0*SM_STAGE + MT*128, Bg, K, 0, tid);
    CP_COMMIT();
    load_tile_h<MT>(sb + 1*SM_STAGE, Ag, K, KC, tid);
    load_tile_h<NT>(sb + 1*SM_STAGE + MT*128, Bg, K, KC, tid);
    CP_COMMIT();

    const int niter = K / KC;
    int stage = 0;
    for (int it = 0; it < niter; ++it) {
        if (it + 1 < niter) { CP_WAIT1(); } else { CP_WAIT0(); }
        __syncthreads();

        if (it + 2 < niter) {
            const int s2 = (stage + 2) % 3;
            load_tile_h<MT>(sb + s2*SM_STAGE, Ag, K, (it + 2) * KC, tid);
            load_tile_h<NT>(sb + s2*SM_STAGE + MT*128, Bg, K, (it + 2) * KC, tid);
            CP_COMMIT();
        }

        const uint32_t abase = sb + stage*SM_STAGE;
        const uint32_t bbase = abase + MT*128;

        #pragma unroll
        for (int kk = 0; kk < KC / 16; ++kk) {
            uint32_t af[4][4], bf[4][2];
            #pragma unroll
            for (int mt = 0; mt < 4; ++mt) {
                const uint32_t off = (wm + mt * 16 + a_row) * 128 + kk * 32 + a_byte;
                ldmat4(af[mt], abase + SWZ128(off));
            }
            #pragma unroll
            for (int np = 0; np < 2; ++np) {
                const uint32_t off = (wn + np * 16 + b_row) * 128 + kk * 32 + b_byte;
                uint32_t r[4];
                ldmat4(r, bbase + SWZ128(off));
                bf[np*2][0]   = r[0]; bf[np*2][1]   = r[1];
                bf[np*2+1][0] = r[2]; bf[np*2+1][1] = r[3];
            }
            #pragma unroll
            for (int mt = 0; mt < 4; ++mt)
                #pragma unroll
                for (int nt = 0; nt < 4; ++nt)
                    mma_f16(acc[mt][nt], af[mt], bf[nt]);
        }
        stage = (stage + 1) % 3;
    }

    const int g  = lane >> 2;
    const int qd = lane & 3;
    #pragma unroll
    for (int nt = 0; nt < 4; ++nt) {
        const int col = bn + wn + nt * 8 + qd * 2;
        const float2 bv = *(const float2*)&bias[col];
        #pragma unroll
        for (int mt = 0; mt < 4; ++mt) {
            const int row0 = bm + wm + mt * 16 + g;
            float2 v0, v1;
            v0.x = acc[mt][nt][0] + bv.x;
            v0.y = acc[mt][nt][1] + bv.y;
            v1.x = acc[mt][nt][2] + bv.x;
            v1.y = acc[mt][nt][3] + bv.y;
            if (MODE == 1) {
                const int part = col >> 10;
                const int h = (col & 1023) >> 6;
                const int d = col & 63;
                __half* dst = (part == 0) ? g_qh : (part == 1) ? g_kh : g_vh;
                const int b0i = row0 >> 11, s0 = row0 & 2047;
                const int b1i = (row0 + 8) >> 11, s1 = (row0 + 8) & 2047;
                *(__half2*)&dst[(((size_t)(b0i*NH + h))*SEQ + s0)*DH + d] =
                    __floats2half2_rn(v0.x, v0.y);
                *(__half2*)&dst[(((size_t)(b1i*NH + h))*SEQ + s1)*DH + d] =
                    __floats2half2_rn(v1.x, v1.y);
            } else {
                *(float2*)&C[(size_t)row0 * N + col] = v0;
                *(float2*)&C[(size_t)(row0 + 8) * N + col] = v1;
            }
        }
    }
}

// ---------------------------------------------------------------------------
// Flash attention, fp16 MMAs (gemm_h-identical fragment addressing):
//   S = Q@K^T fp16 (fp32 acc) -> S fp32 smem -> scalar fp32 softmax ->
//   P half tile -> O += P@V fp16 (fp32 acc).
// Tiles: Q 128x128B, K 2x 64x128B (double-buffered), V^T 64x128B,
//        S fp32 2 planes, P_H 128x128B. dh=64 halfs = one 128B row.
// ---------------------------------------------------------------------------
#define AQ 128
#define AK 64
#define AH_Q  0         // 16384
#define AH_K0 16384     // 8192
#define AH_K1 24576     // 8192
#define AH_VT 32768     // 8192
#define AH_S  40960     // 32768 (fp32, 2 planes x 16384)
#define AH_PH 73728     // 16384
#define AH_C  90112     // 512
#define AH_L  90624     // 512
#define AH_TOTAL 91136

__global__ __launch_bounds__(128) void attn_h(const int* __restrict__ cmask)
{
    extern __shared__ __align__(1024) char smem[];
    const uint32_t sb = smem_u32(smem);
    float* Csh = (float*)(smem + AH_C);
    float* Lsh = (float*)(smem + AH_L);

    const int tid  = threadIdx.x;
    const int lane = tid & 31;
    const int warp = tid >> 5;
    const int bh   = blockIdx.x;
    const int qt   = gridDim.y - 1 - blockIdx.y;   // heavy tiles first
    const int q0   = qt * AQ;
    const int qi   = q0 + tid;

    const bool causal = (cmask[0] != 0);

    const __half* gq  = g_qh + ((size_t)bh * SEQ + q0) * DH;
    const __half* gkb = g_kh + (size_t)bh * SEQ * DH;
    const __half* gvb = g_vh + (size_t)bh * SEQ * DH;

    const int a_row  = lane & 15;
    const int a_byte = ((lane >> 4) & 1) * 16;
    const int b_row  = (lane & 7) + (((lane >> 4) & 1) << 3);
    const int b_byte = ((lane >> 3) & 1) * 16;
    const int g  = lane >> 2;
    const int qh = lane & 3;

    // ---- Q tile (cp.async): 128 rows x 128B, single plane ----
    #pragma unroll
    for (int i = 0; i < 8; ++i) {
        const int c = tid + i * 128;
        const int row = c >> 3, kc = c & 7;
        cp_async16(sb + AH_Q + SWZ128((uint32_t)(row * 128 + kc * 16)),
                   gq + (size_t)row * DH + kc * 8);
    }
    CP_COMMIT();

    // ---- K(0) tile: 64 rows x 128B ----
    #pragma unroll
    for (int i = 0; i < 4; ++i) {
        const int c = tid + i * 128;
        const int row = c >> 3, kc = c & 7;
        cp_async16(sb + AH_K0 + SWZ128((uint32_t)(row * 128 + kc * 16)),
                   gkb + (size_t)row * DH + kc * 8);
    }
    CP_COMMIT();

    float oa[2][8][4];
    #pragma unroll
    for (int mt = 0; mt < 2; ++mt)
        #pragma unroll
        for (int nt = 0; nt < 8; ++nt)
            #pragma unroll
            for (int c = 0; c < 4; ++c) oa[mt][nt][c] = 0.f;
    float m = -1e30f, l = 0.f;

    const int ntiles = causal ? (q0 / AK + 2) : (SEQ / AK);
    const int vkey = tid & 63;
    const int vds  = tid >> 6;       // 0/1: d-halves [0,32) / [32,64)

    for (int t = 0; t < ntiles; ++t) {
        const int k0 = t * AK;
        const uint32_t kbase = sb + ((t & 1) ? AH_K1 : AH_K0);

        // ---- V(t) -> registers (in flight across K wait + S-mma) ----
        uint4 vreg[4];
        #pragma unroll
        for (int i = 0; i < 4; ++i)
            vreg[i] = *(const uint4*)(gvb + (size_t)(k0 + vkey) * DH + vds * 32 + i * 8);

        CP_WAIT0();
        __syncthreads();

        // ---- prefetch K(t+1) ----
        if (t + 1 < ntiles) {
            const uint32_t knext = ((t & 1) ? AH_K0 : AH_K1);
            #pragma unroll
            for (int i = 0; i < 4; ++i) {
                const int c = tid + i * 128;
                const int row = c >> 3, kc = c & 7;
                cp_async16(sb + knext + SWZ128((uint32_t)(row * 128 + kc * 16)),
                           gkb + (size_t)(k0 + AK + row) * DH + kc * 8);
            }
            CP_COMMIT();
        }

        // ---- S = Q @ K^T (fp16, gemm_h-identical addressing) ----
        float sc[2][8][4];
        #pragma unroll
        for (int mt = 0; mt < 2; ++mt)
            #pragma unroll
            for (int nt = 0; nt < 8; ++nt)
                #pragma unroll
                for (int c = 0; c < 4; ++c) sc[mt][nt][c] = 0.f;

        #pragma unroll
        for (int kk = 0; kk < 4; ++kk) {
            uint32_t aq[2][4], bf[8][2];
            #pragma unroll
            for (int mt = 0; mt < 2; ++mt) {
                const uint32_t off = (warp*32 + mt*16 + a_row) * 128 + kk * 32 + a_byte;
                ldmat4(aq[mt], sb + AH_Q + SWZ128(off));
            }
            #pragma unroll
            for (int np = 0; np < 4; ++np) {
                const uint32_t off = (np*16 + b_row) * 128 + kk * 32 + b_byte;
                uint32_t r[4];
                ldmat4(r, kbase + SWZ128(off));
                bf[np*2][0]   = r[0]; bf[np*2][1]   = r[1];
                bf[np*2+1][0] = r[2]; bf[np*2+1][1] = r[3];
            }
            #pragma unroll
            for (int mt = 0; mt < 2; ++mt)
                #pragma unroll
                for (int nt = 0; nt < 8; ++nt)
                    mma_f16(sc[mt][nt], aq[mt], bf[nt]);
        }

        // ---- V(t) registers -> V^T half tile [d row][key col] ----
        {
            #pragma unroll
            for (int i = 0; i < 4; ++i) {
                __half h[8];
                *(uint4*)h = vreg[i];
                #pragma unroll
                for (int j = 0; j < 8; ++j) {
                    const int d = vds * 32 + i * 8 + j;
                    *(__half*)(smem + AH_VT
                        + SWZ128((uint32_t)(d * 128) + (uint32_t)(vkey * 2))) = h[j];
                }
            }
        }

        // ---- S fragments -> S fp32 tile (proven 2-plane store) ----
        #pragma unroll
        for (int mt = 0; mt < 2; ++mt) {
            const int row = warp*32 + mt*16 + g;
            #pragma unroll
            for (int nt = 0; nt < 8; ++nt) {
                const int col = nt*8 + 2*qh;
                const int pl  = AH_S + (col >> 5) * 16384;
                const uint32_t cb = (uint32_t)(col & 31) * 4;
                float2 v01, v23;
                v01.x = sc[mt][nt][0]; v01.y = sc[mt][nt][1];
                v23.x = sc[mt][nt][2]; v23.y = sc[mt][nt][3];
                *(float2*)(smem + pl + SWZ128((uint32_t)(row * 128) + cb))       = v01;
                *(float2*)(smem + pl + SWZ128((uint32_t)((row + 8) * 128) + cb)) = v23;
            }
        }
        __syncwarp();

        // ---- scalar fp32 softmax on row `tid`; write HALF P tile ----
        const int jlim = causal ? min(AK, qi - k0 + 1) : AK;
        float corr;
        float* sf = &sc[0][0][0];
        if (jlim > 0) {
            #pragma unroll
            for (int j4 = 0; j4 < 16; ++j4) {
                const float4 v = *(const float4*)(smem + AH_S + (j4 >> 3) * 16384
                               + SWZ128((uint32_t)(tid * 128 + (j4 & 7) * 16)));
                sf[j4*4+0] = v.x; sf[j4*4+1] = v.y;
                sf[j4*4+2] = v.z; sf[j4*4+3] = v.w;
            }
            float tmax = -1e30f;
            #pragma unroll
            for (int j = 0; j < 64; ++j)
                if (j < jlim) tmax = fmaxf(tmax, sf[j]);
            tmax *= 0.125f;
            const float mn = fmaxf(m, tmax);
            corr = __expf(m - mn);
            m = mn;
            float rs = 0.f;
            #pragma unroll
            for (int j = 0; j < 64; ++j) {
                const float p = (j < jlim) ? __expf(sf[j] * 0.125f - mn) : 0.f;
                sf[j] = p;
                rs += p;
            }
            l = l * corr + rs;
            #pragma unroll
            for (int j = 0; j < 8; ++j) {     // 8 chunks of 8 halfs
                uint4 u;
                u.x = pack_h2(sf[j*8+0], sf[j*8+1]);
                u.y = pack_h2(sf[j*8+2], sf[j*8+3]);
                u.z = pack_h2(sf[j*8+4], sf[j*8+5]);
                u.w = pack_h2(sf[j*8+6], sf[j*8+7]);
                *(uint4*)(smem + AH_PH + SWZ128((uint32_t)(tid * 128 + j * 16))) = u;
            }
        } else {
            corr = 1.f;
            const uint4 z = {0u, 0u, 0u, 0u};
            #pragma unroll
            for (int j = 0; j < 8; ++j)
                *(uint4*)(smem + AH_PH + SWZ128((uint32_t)(tid * 128 + j * 16))) = z;
        }
        Csh[tid] = corr;
        __syncwarp();

        // ---- apply row-correction to O fragments ----
        #pragma unroll
        for (int mt = 0; mt < 2; ++mt) {
            const float cA = Csh[warp*32 + mt*16 + g];
            const float cB = Csh[warp*32 + mt*16 + g + 8];
            #pragma unroll
            for (int nt = 0; nt < 8; ++nt) {
                oa[mt][nt][0] *= cA; oa[mt][nt][1] *= cA;
                oa[mt][nt][2] *= cB; oa[mt][nt][3] *= cB;
            }
        }

        __syncthreads();   // V^T + P_H visible

        // ---- O += P @ V (fp16, gemm_h-identical addressing) ----
        #pragma unroll
        for (int kk = 0; kk < 4; ++kk) {
            uint32_t ap[2][4], bf[8][2];
            #pragma unroll
            for (int mt = 0; mt < 2; ++mt) {
                const uint32_t off = (warp*32 + mt*16 + a_row) * 128 + kk * 32 + a_byte;
                ldmat4(ap[mt], sb + AH_PH + SWZ128(off));
            }
            #pragma unroll
            for (int np = 0; np < 4; ++np) {
                const uint32_t off = (np*16 + b_row) * 128 + kk * 32 + b_byte;
                uint32_t r[4];
                ldmat4(r, sb + AH_VT + SWZ128(off));
                bf[np*2][0]   = r[0]; bf[np*2][1]   = r[1];
                bf[np*2+1][0] = r[2]; bf[np*2+1][1] = r[3];
            }
            #pragma unroll
            for (int mt = 0; mt < 2; ++mt)
                #pragma unroll
                for (int nt = 0; nt < 8; ++nt)
                    mma_f16(oa[mt][nt], ap[mt], bf[nt]);
        }
    }

    // ---- normalize + write g_a as HALF (out-proj A operand) ----
    Lsh[tid] = l;
    __syncwarp();
    const int b = bh >> 4, h = bh & 15;
    #pragma unroll
    for (int mt = 0; mt < 2; ++mt) {
        const int r0 = warp*32 + mt*16 + g;
        const float i0 = 1.f / fmaxf(Lsh[r0], 1e-30f);
        const float i1 = 1.f / fmaxf(Lsh[r0 + 8], 1e-30f);
        __half* o0 = g_a + ((size_t)(b * SEQ + q0 + r0)) * DEMB + h * DH;
        __half* o1 = g_a + ((size_t)(b * SEQ + q0 + r0 + 8)) * DEMB + h * DH;
        #pragma unroll
        for (int nt = 0; nt < 8; ++nt) {
            *(__half2*)(o0 + nt*8 + 2*qh) =
                __floats2half2_rn(oa[mt][nt][0] * i0, oa[mt][nt][1] * i0);
            *(__half2*)(o1 + nt*8 + 2*qh) =
                __floats2half2_rn(oa[mt][nt][2] * i1, oa[mt][nt][3] * i1);
        }
    }
}

// ---------------------------------------------------------------------------
extern "C" void kernel_launch(void* const* d_in, const int* in_sizes, int n_in,
                              void* d_out, int out_size)
{
    const float* x     = (const float*)d_in[0];
    const float* w_in  = (const float*)d_in[1];
    const float* b_in  = (const float*)d_in[2];
    const float* w_out = (const float*)d_in[3];
    const float* b_out = (const float*)d_in[4];
    const int*   cmask = (const int*)d_in[5];
    float* out = (float*)d_out;

    cudaFuncSetAttribute(gemm_h<1>, cudaFuncAttributeMaxDynamicSharedMemorySize, SM_TOTAL);
    cudaFuncSetAttribute(gemm_h<2>, cudaFuncAttributeMaxDynamicSharedMemorySize, SM_TOTAL);
    cudaFuncSetAttribute(attn_h,    cudaFuncAttributeMaxDynamicSharedMemorySize, AH_TOTAL);

    // 0) fp32 -> fp16 input copies
    round_half<0><<<NTOK*DEMB/4/256, 256>>>(x, NTOK*DEMB/4);
    round_half<1><<<QKV_N*DEMB/4/256, 256>>>(w_in, QKV_N*DEMB/4);
    round_half<2><<<DEMB*DEMB/4/256, 256>>>(w_out, DEMB*DEMB/4);

    // 1) QKV projection (fp16 HMMA) -> half q/k/v
    gemm_h<1><<<dim3(QKV_N/NT, NTOK/MT), 256, SM_TOTAL>>>(
        b_in, nullptr, NTOK, QKV_N, DEMB);

    // 2) Flash attention (fp16 MMAs, fp32 softmax) -> g_a (half)
    attn_h<<<dim3(BATCH*NH, SEQ/AQ), 128, AH_TOTAL>>>(cmask);

    // 3) Output projection (fp16 HMMA) -> out (fp32)
    gemm_h<2><<<dim3(DEMB/NT, NTOK/MT), 256, SM_TOTAL>>>(
        b_out, out, NTOK, DEMB, DEMB);
}

// round 12
// speedup vs baseline: 7.1102x; 1.1202x over previous
#include <cuda_runtime.h>
#include <cuda_fp16.h>
#include <cstdint>

// Problem constants
#define BATCH   2
#define SEQ     2048
#define NH      16
#define DH      64
#define DEMB    1024
#define NTOK    (BATCH*SEQ)      // 4096
#define QKV_N   (3*DEMB)         // 3072

// Scratch (device globals — no allocation inside kernel_launch)
__device__ __half g_qh[(size_t)BATCH*NH*SEQ*DH];
__device__ __half g_kh[(size_t)BATCH*NH*SEQ*DH];
__device__ __half g_vh[(size_t)BATCH*NH*SEQ*DH];
__device__ __half g_a [(size_t)NTOK*DEMB];
__device__ __half g_xh[(size_t)NTOK*DEMB];
__device__ __half g_wih[(size_t)QKV_N*DEMB];
__device__ __half g_woh[(size_t)DEMB*DEMB];

// ---------------------------------------------------------------------------
// Helpers
// ---------------------------------------------------------------------------
__device__ __forceinline__ uint32_t smem_u32(const void* p) {
    uint32_t a;
    asm("{ .reg .u64 t; cvta.to.shared.u64 t, %1; cvt.u32.u64 %0, t; }"
        : "=r"(a) : "l"(p));
    return a;
}
__device__ __forceinline__ void cp_async16(uint32_t dst, const void* src) {
    asm volatile("cp.async.cg.shared.global [%0], [%1], 16;\n" :: "r"(dst), "l"(src));
}
#define CP_COMMIT()  asm volatile("cp.async.commit_group;\n" ::: "memory")
#define CP_WAIT0()   asm volatile("cp.async.wait_group 0;\n" ::: "memory")
#define CP_WAIT1()   asm volatile("cp.async.wait_group 1;\n" ::: "memory")

#define SWZ128(off)  ((off) ^ (((off) >> 3) & 0x70))

__device__ __forceinline__ void ldmat4(uint32_t* r, uint32_t addr) {
    asm volatile("ldmatrix.sync.aligned.m8n8.x4.shared.b16 {%0,%1,%2,%3}, [%4];"
        : "=r"(r[0]), "=r"(r[1]), "=r"(r[2]), "=r"(r[3]) : "r"(addr));
}
__device__ __forceinline__ void mma_f16(float* d, const uint32_t* a, const uint32_t* b) {
    asm volatile(
        "mma.sync.aligned.m16n8k16.row.col.f32.f16.f16.f32 "
        "{%0,%1,%2,%3}, {%4,%5,%6,%7}, {%8,%9}, {%0,%1,%2,%3};"
        : "+f"(d[0]), "+f"(d[1]), "+f"(d[2]), "+f"(d[3])
        : "r"(a[0]), "r"(a[1]), "r"(a[2]), "r"(a[3]), "r"(b[0]), "r"(b[1]));
}
__device__ __forceinline__ uint32_t pack_h2(float a, float b) {
    __half2 h = __floats2half2_rn(a, b);
    return *reinterpret_cast<uint32_t*>(&h);
}

// ---------------------------------------------------------------------------
// Prepass (single kernel): fp32 -> fp16 copies of x, w_in, w_out
// ---------------------------------------------------------------------------
#define NX4  (NTOK*DEMB/4)      // 1048576
#define NWI4 (QKV_N*DEMB/4)     // 786432
#define NWO4 (DEMB*DEMB/4)      // 262144
#define NALL4 (NX4 + NWI4 + NWO4)

__global__ __launch_bounds__(256) void round_all(
    const float* __restrict__ x, const float* __restrict__ wi,
    const float* __restrict__ wo)
{
    const int i = blockIdx.x * 256 + threadIdx.x;
    const float4* src; __half* dst; int j;
    if (i < NX4)             { src = (const float4*)x;  dst = g_xh;  j = i; }
    else if (i < NX4 + NWI4) { src = (const float4*)wi; dst = g_wih; j = i - NX4; }
    else if (i < NALL4)      { src = (const float4*)wo; dst = g_woh; j = i - NX4 - NWI4; }
    else return;
    const float4 v = src[j];
    ((__half2*)dst)[2*j]   = __floats2half2_rn(v.x, v.y);
    ((__half2*)dst)[2*j+1] = __floats2half2_rn(v.z, v.w);
}

// ---------------------------------------------------------------------------
// fp16 HMMA GEMM (proven): now __launch_bounds__(256,2) -> 2 CTA/SM
// ---------------------------------------------------------------------------
#define MT 128
#define NT 128
#define KC 64

#define SM_STAGE (MT*128 + NT*128)
#define SM_TOTAL (3*SM_STAGE)           // 98304

template<int ROWS>
__device__ __forceinline__ void load_tile_h(uint32_t sbase, const __half* __restrict__ g,
                                            int K, int k0, int tid) {
    #pragma unroll
    for (int t = 0; t < ROWS * 8 / 256; ++t) {
        const int c = tid + t * 256;
        const int row = c >> 3, kc = c & 7;
        const uint32_t off = row * 128 + kc * 16;
        cp_async16(sbase + SWZ128(off), g + (size_t)row * K + k0 + kc * 8);
    }
}

template<int MODE>
__global__ __launch_bounds__(256, 2)
void gemm_h(const float* __restrict__ bias, float* __restrict__ C,
            int M, int N, int K)
{
    extern __shared__ __align__(1024) char smem[];
    const uint32_t sb = smem_u32(smem);
    const int tid  = threadIdx.x;
    const int lane = tid & 31;
    const int warp = tid >> 5;
    const int wm   = (warp >> 2) * 64;
    const int wn   = (warp & 3) * 32;
    const int bm   = blockIdx.y * MT;
    const int bn   = blockIdx.x * NT;

    const __half* Abase = (MODE == 2) ? (const __half*)g_a : (const __half*)g_xh;
    const __half* Bbase = (MODE == 2) ? (const __half*)g_woh : (const __half*)g_wih;
    const __half* Ag = Abase + (size_t)bm * K;
    const __half* Bg = Bbase + (size_t)bn * K;

    float acc[4][4][4];
    #pragma unroll
    for (int i = 0; i < 4; i++)
        #pragma unroll
        for (int j = 0; j < 4; j++)
            #pragma unroll
            for (int r = 0; r < 4; r++) acc[i][j][r] = 0.f;

    const int a_row  = lane & 15;
    const int a_byte = ((lane >> 4) & 1) * 16;
    const int b_row  = (lane & 7) + (((lane >> 4) & 1) << 3);
    const int b_byte = ((lane >> 3) & 1) * 16;

    load_tile_h<MT>(sb + 0*SM_STAGE, Ag, K, 0, tid);
    load_tile_h<NT>(sb + 0*SM_STAGE + MT*128, Bg, K, 0, tid);
    CP_COMMIT();
    load_tile_h<MT>(sb + 1*SM_STAGE, Ag, K, KC, tid);
    load_tile_h<NT>(sb + 1*SM_STAGE + MT*128, Bg, K, KC, tid);
    CP_COMMIT();

    const int niter = K / KC;
    int stage = 0;
    for (int it = 0; it < niter; ++it) {
        if (it + 1 < niter) { CP_WAIT1(); } else { CP_WAIT0(); }
        __syncthreads();

        if (it + 2 < niter) {
            const int s2 = (stage + 2) % 3;
            load_tile_h<MT>(sb + s2*SM_STAGE, Ag, K, (it + 2) * KC, tid);
            load_tile_h<NT>(sb + s2*SM_STAGE + MT*128, Bg, K, (it + 2) * KC, tid);
            CP_COMMIT();
        }

        const uint32_t abase = sb + stage*SM_STAGE;
        const uint32_t bbase = abase + MT*128;

        #pragma unroll
        for (int kk = 0; kk < KC / 16; ++kk) {
            uint32_t af[4][4], bf[4][2];
            #pragma unroll
            for (int mt = 0; mt < 4; ++mt) {
                const uint32_t off = (wm + mt * 16 + a_row) * 128 + kk * 32 + a_byte;
                ldmat4(af[mt], abase + SWZ128(off));
            }
            #pragma unroll
            for (int np = 0; np < 2; ++np) {
                const uint32_t off = (wn + np * 16 + b_row) * 128 + kk * 32 + b_byte;
                uint32_t r[4];
                ldmat4(r, bbase + SWZ128(off));
                bf[np*2][0]   = r[0]; bf[np*2][1]   = r[1];
                bf[np*2+1][0] = r[2]; bf[np*2+1][1] = r[3];
            }
            #pragma unroll
            for (int mt = 0; mt < 4; ++mt)
                #pragma unroll
                for (int nt = 0; nt < 4; ++nt)
                    mma_f16(acc[mt][nt], af[mt], bf[nt]);
        }
        stage = (stage + 1) % 3;
    }

    const int g  = lane >> 2;
    const int qd = lane & 3;
    #pragma unroll
    for (int nt = 0; nt < 4; ++nt) {
        const int col = bn + wn + nt * 8 + qd * 2;
        const float2 bv = *(const float2*)&bias[col];
        #pragma unroll
        for (int mt = 0; mt < 4; ++mt) {
            const int row0 = bm + wm + mt * 16 + g;
            float2 v0, v1;
            v0.x = acc[mt][nt][0] + bv.x;
            v0.y = acc[mt][nt][1] + bv.y;
            v1.x = acc[mt][nt][2] + bv.x;
            v1.y = acc[mt][nt][3] + bv.y;
            if (MODE == 1) {
                const int part = col >> 10;
                const int h = (col & 1023) >> 6;
                const int d = col & 63;
                __half* dst = (part == 0) ? g_qh : (part == 1) ? g_kh : g_vh;
                const int b0i = row0 >> 11, s0 = row0 & 2047;
                const int b1i = (row0 + 8) >> 11, s1 = (row0 + 8) & 2047;
                *(__half2*)&dst[(((size_t)(b0i*NH + h))*SEQ + s0)*DH + d] =
                    __floats2half2_rn(v0.x, v0.y);
                *(__half2*)&dst[(((size_t)(b1i*NH + h))*SEQ + s1)*DH + d] =
                    __floats2half2_rn(v1.x, v1.y);
            } else {
                *(float2*)&C[(size_t)row0 * N + col] = v0;
                *(float2*)&C[(size_t)(row0 + 8) * N + col] = v1;
            }
        }
    }
}

// ---------------------------------------------------------------------------
// Flash attention (proven R11 fp16 path, unchanged math)
// ---------------------------------------------------------------------------
#define AQ 128
#define AK 64
#define AH_Q  0         // 16384
#define AH_K0 16384     // 8192
#define AH_K1 24576     // 8192
#define AH_VT 32768     // 8192
#define AH_S  40960     // 32768 (fp32, 2 planes x 16384)
#define AH_PH 73728     // 16384
#define AH_C  90112     // 512
#define AH_L  90624     // 512
#define AH_TOTAL 91136

__global__ __launch_bounds__(128, 2) void attn_h(const int* __restrict__ cmask)
{
    extern __shared__ __align__(1024) char smem[];
    const uint32_t sb = smem_u32(smem);
    float* Csh = (float*)(smem + AH_C);
    float* Lsh = (float*)(smem + AH_L);

    const int tid  = threadIdx.x;
    const int lane = tid & 31;
    const int warp = tid >> 5;
    const int bh   = blockIdx.x;
    const int qt   = gridDim.y - 1 - blockIdx.y;
    const int q0   = qt * AQ;
    const int qi   = q0 + tid;

    const bool causal = (cmask[0] != 0);

    const __half* gq  = g_qh + ((size_t)bh * SEQ + q0) * DH;
    const __half* gkb = g_kh + (size_t)bh * SEQ * DH;
    const __half* gvb = g_vh + (size_t)bh * SEQ * DH;

    const int a_row  = lane & 15;
    const int a_byte = ((lane >> 4) & 1) * 16;
    const int b_row  = (lane & 7) + (((lane >> 4) & 1) << 3);
    const int b_byte = ((lane >> 3) & 1) * 16;
    const int g  = lane >> 2;
    const int qh = lane & 3;

    #pragma unroll
    for (int i = 0; i < 8; ++i) {
        const int c = tid + i * 128;
        const int row = c >> 3, kc = c & 7;
        cp_async16(sb + AH_Q + SWZ128((uint32_t)(row * 128 + kc * 16)),
                   gq + (size_t)row * DH + kc * 8);
    }
    CP_COMMIT();

    #pragma unroll
    for (int i = 0; i < 4; ++i) {
        const int c = tid + i * 128;
        const int row = c >> 3, kc = c & 7;
        cp_async16(sb + AH_K0 + SWZ128((uint32_t)(row * 128 + kc * 16)),
                   gkb + (size_t)row * DH + kc * 8);
    }
    CP_COMMIT();

    float oa[2][8][4];
    #pragma unroll
    for (int mt = 0; mt < 2; ++mt)
        #pragma unroll
        for (int nt = 0; nt < 8; ++nt)
            #pragma unroll
            for (int c = 0; c < 4; ++c) oa[mt][nt][c] = 0.f;
    float m = -1e30f, l = 0.f;

    const int ntiles = causal ? (q0 / AK + 2) : (SEQ / AK);
    const int vkey = tid & 63;
    const int vds  = tid >> 6;

    for (int t = 0; t < ntiles; ++t) {
        const int k0 = t * AK;
        const uint32_t kbase = sb + ((t & 1) ? AH_K1 : AH_K0);

        uint4 vreg[4];
        #pragma unroll
        for (int i = 0; i < 4; ++i)
            vreg[i] = *(const uint4*)(gvb + (size_t)(k0 + vkey) * DH + vds * 32 + i * 8);

        CP_WAIT0();
        __syncthreads();

        if (t + 1 < ntiles) {
            const uint32_t knext = ((t & 1) ? AH_K0 : AH_K1);
            #pragma unroll
            for (int i = 0; i < 4; ++i) {
                const int c = tid + i * 128;
                const int row = c >> 3, kc = c & 7;
                cp_async16(sb + knext + SWZ128((uint32_t)(row * 128 + kc * 16)),
                           gkb + (size_t)(k0 + AK + row) * DH + kc * 8);
            }
            CP_COMMIT();
        }

        float sc[2][8][4];
        #pragma unroll
        for (int mt = 0; mt < 2; ++mt)
            #pragma unroll
            for (int nt = 0; nt < 8; ++nt)
                #pragma unroll
                for (int c = 0; c < 4; ++c) sc[mt][nt][c] = 0.f;

        #pragma unroll
        for (int kk = 0; kk < 4; ++kk) {
            uint32_t aq[2][4], bf[8][2];
            #pragma unroll
            for (int mt = 0; mt < 2; ++mt) {
                const uint32_t off = (warp*32 + mt*16 + a_row) * 128 + kk * 32 + a_byte;
                ldmat4(aq[mt], sb + AH_Q + SWZ128(off));
            }
            #pragma unroll
            for (int np = 0; np < 4; ++np) {
                const uint32_t off = (np*16 + b_row) * 128 + kk * 32 + b_byte;
                uint32_t r[4];
                ldmat4(r, kbase + SWZ128(off));
                bf[np*2][0]   = r[0]; bf[np*2][1]   = r[1];
                bf[np*2+1][0] = r[2]; bf[np*2+1][1] = r[3];
            }
            #pragma unroll
            for (int mt = 0; mt < 2; ++mt)
                #pragma unroll
                for (int nt = 0; nt < 8; ++nt)
                    mma_f16(sc[mt][nt], aq[mt], bf[nt]);
        }

        {
            #pragma unroll
            for (int i = 0; i < 4; ++i) {
                __half h[8];
                *(uint4*)h = vreg[i];
                #pragma unroll
                for (int j = 0; j < 8; ++j) {
                    const int d = vds * 32 + i * 8 + j;
                    *(__half*)(smem + AH_VT
                        + SWZ128((uint32_t)(d * 128) + (uint32_t)(vkey * 2))) = h[j];
                }
            }
        }

        #pragma unroll
        for (int mt = 0; mt < 2; ++mt) {
            const int row = warp*32 + mt*16 + g;
            #pragma unroll
            for (int nt = 0; nt < 8; ++nt) {
                const int col = nt*8 + 2*qh;
                const int pl  = AH_S + (col >> 5) * 16384;
                const uint32_t cb = (uint32_t)(col & 31) * 4;
                float2 v01, v23;
                v01.x = sc[mt][nt][0]; v01.y = sc[mt][nt][1];
                v23.x = sc[mt][nt][2]; v23.y = sc[mt][nt][3];
                *(float2*)(smem + pl + SWZ128((uint32_t)(row * 128) + cb))       = v01;
                *(float2*)(smem + pl + SWZ128((uint32_t)((row + 8) * 128) + cb)) = v23;
            }
        }
        __syncwarp();

        const int jlim = causal ? min(AK, qi - k0 + 1) : AK;
        float corr;
        float* sf = &sc[0][0][0];
        if (jlim > 0) {
            #pragma unroll
            for (int j4 = 0; j4 < 16; ++j4) {
                const float4 v = *(const float4*)(smem + AH_S + (j4 >> 3) * 16384
                               + SWZ128((uint32_t)(tid * 128 + (j4 & 7) * 16)));
                sf[j4*4+0] = v.x; sf[j4*4+1] = v.y;
                sf[j4*4+2] = v.z; sf[j4*4+3] = v.w;
            }
            float tmax = -1e30f;
            #pragma unroll
            for (int j = 0; j < 64; ++j)
                if (j < jlim) tmax = fmaxf(tmax, sf[j]);
            tmax *= 0.125f;
            const float mn = fmaxf(m, tmax);
            corr = __expf(m - mn);
            m = mn;
            float rs = 0.f;
            #pragma unroll
            for (int j = 0; j < 64; ++j) {
                const float p = (j < jlim) ? __expf(sf[j] * 0.125f - mn) : 0.f;
                sf[j] = p;
                rs += p;
            }
            l = l * corr + rs;
            #pragma unroll
            for (int j = 0; j < 8; ++j) {
                uint4 u;
                u.x = pack_h2(sf[j*8+0], sf[j*8+1]);
                u.y = pack_h2(sf[j*8+2], sf[j*8+3]);
                u.z = pack_h2(sf[j*8+4], sf[j*8+5]);
                u.w = pack_h2(sf[j*8+6], sf[j*8+7]);
                *(uint4*)(smem + AH_PH + SWZ128((uint32_t)(tid * 128 + j * 16))) = u;
            }
        } else {
            corr = 1.f;
            const uint4 z = {0u, 0u, 0u, 0u};
            #pragma unroll
            for (int j = 0; j < 8; ++j)
                *(uint4*)(smem + AH_PH + SWZ128((uint32_t)(tid * 128 + j * 16))) = z;
        }
        Csh[tid] = corr;
        __syncwarp();

        #pragma unroll
        for (int mt = 0; mt < 2; ++mt) {
            const float cA = Csh[warp*32 + mt*16 + g];
            const float cB = Csh[warp*32 + mt*16 + g + 8];
            #pragma unroll
            for (int nt = 0; nt < 8; ++nt) {
                oa[mt][nt][0] *= cA; oa[mt][nt][1] *= cA;
                oa[mt][nt][2] *= cB; oa[mt][nt][3] *= cB;
            }
        }

        __syncthreads();

        #pragma unroll
        for (int kk = 0; kk < 4; ++kk) {
            uint32_t ap[2][4], bf[8][2];
            #pragma unroll
            for (int mt = 0; mt < 2; ++mt) {
                const uint32_t off = (warp*32 + mt*16 + a_row) * 128 + kk * 32 + a_byte;
                ldmat4(ap[mt], sb + AH_PH + SWZ128(off));
            }
            #pragma unroll
            for (int np = 0; np < 4; ++np) {
                const uint32_t off = (np*16 + b_row) * 128 + kk * 32 + b_byte;
                uint32_t r[4];
                ldmat4(r, sb + AH_VT + SWZ128(off));
                bf[np*2][0]   = r[0]; bf[np*2][1]   = r[1];
                bf[np*2+1][0] = r[2]; bf[np*2+1][1] = r[3];
            }
            #pragma unroll
            for (int mt = 0; mt < 2; ++mt)
                #pragma unroll
                for (int nt = 0; nt < 8; ++nt)
                    mma_f16(oa[mt][nt], ap[mt], bf[nt]);
        }
    }

    Lsh[tid] = l;
    __syncwarp();
    const int b = bh >> 4, h = bh & 15;
    #pragma unroll
    for (int mt = 0; mt < 2; ++mt) {
        const int r0 = warp*32 + mt*16 + g;
        const float i0 = 1.f / fmaxf(Lsh[r0], 1e-30f);
        const float i1 = 1.f / fmaxf(Lsh[r0 + 8], 1e-30f);
        __half* o0 = g_a + ((size_t)(b * SEQ + q0 + r0)) * DEMB + h * DH;
        __half* o1 = g_a + ((size_t)(b * SEQ + q0 + r0 + 8)) * DEMB + h * DH;
        #pragma unroll
        for (int nt = 0; nt < 8; ++nt) {
            *(__half2*)(o0 + nt*8 + 2*qh) =
                __floats2half2_rn(oa[mt][nt][0] * i0, oa[mt][nt][1] * i0);
            *(__half2*)(o1 + nt*8 + 2*qh) =
                __floats2half2_rn(oa[mt][nt][2] * i1, oa[mt][nt][3] * i1);
        }
    }
}

// ---------------------------------------------------------------------------
extern "C" void kernel_launch(void* const* d_in, const int* in_sizes, int n_in,
                              void* d_out, int out_size)
{
    const float* x     = (const float*)d_in[0];
    const float* w_in  = (const float*)d_in[1];
    const float* b_in  = (const float*)d_in[2];
    const float* w_out = (const float*)d_in[3];
    const float* b_out = (const float*)d_in[4];
    const int*   cmask = (const int*)d_in[5];
    float* out = (float*)d_out;

    cudaFuncSetAttribute(gemm_h<1>, cudaFuncAttributeMaxDynamicSharedMemorySize, SM_TOTAL);
    cudaFuncSetAttribute(gemm_h<2>, cudaFuncAttributeMaxDynamicSharedMemorySize, SM_TOTAL);
    cudaFuncSetAttribute(attn_h,    cudaFuncAttributeMaxDynamicSharedMemorySize, AH_TOTAL);

    // 0) single prepass: fp32 -> fp16 copies
    round_all<<<(NALL4 + 255) / 256, 256>>>(x, w_in, w_out);

    // 1) QKV projection (fp16 HMMA, 2 CTA/SM) -> half q/k/v
    gemm_h<1><<<dim3(QKV_N/NT, NTOK/MT), 256, SM_TOTAL>>>(
        b_in, nullptr, NTOK, QKV_N, DEMB);

    // 2) Flash attention (fp16 MMAs, fp32 softmax) -> g_a (half)
    attn_h<<<dim3(BATCH*NH, SEQ/AQ), 128, AH_TOTAL>>>(cmask);

    // 3) Output projection (fp16 HMMA, 2 CTA/SM) -> out (fp32)
    gemm_h<2><<<dim3(DEMB/NT, NTOK/MT), 256, SM_TOTAL>>>(
        b_out, out, NTOK, DEMB, DEMB);
}

// round 13
// speedup vs baseline: 7.9386x; 1.1165x over previous
#include <cuda_runtime.h>
#include <cuda_fp16.h>
#include <cstdint>

// Problem constants
#define BATCH   2
#define SEQ     2048
#define NH      16
#define DH      64
#define DEMB    1024
#define NTOK    (BATCH*SEQ)      // 4096
#define QKV_N   (3*DEMB)         // 3072

// Scratch (device globals — no allocation inside kernel_launch)
__device__ __half g_qh[(size_t)BATCH*NH*SEQ*DH];
__device__ __half g_kh[(size_t)BATCH*NH*SEQ*DH];
__device__ __half g_vh[(size_t)BATCH*NH*SEQ*DH];
__device__ __half g_a [(size_t)NTOK*DEMB];
__device__ __half g_xh[(size_t)NTOK*DEMB];
__device__ __half g_wih[(size_t)QKV_N*DEMB];
__device__ __half g_woh[(size_t)DEMB*DEMB];

// ---------------------------------------------------------------------------
// Helpers
// ---------------------------------------------------------------------------
__device__ __forceinline__ uint32_t smem_u32(const void* p) {
    uint32_t a;
    asm("{ .reg .u64 t; cvta.to.shared.u64 t, %1; cvt.u32.u64 %0, t; }"
        : "=r"(a) : "l"(p));
    return a;
}
__device__ __forceinline__ void cp_async16(uint32_t dst, const void* src) {
    asm volatile("cp.async.cg.shared.global [%0], [%1], 16;\n" :: "r"(dst), "l"(src));
}
#define CP_COMMIT()  asm volatile("cp.async.commit_group;\n" ::: "memory")
#define CP_WAIT0()   asm volatile("cp.async.wait_group 0;\n" ::: "memory")
#define CP_WAIT1()   asm volatile("cp.async.wait_group 1;\n" ::: "memory")

#define SWZ128(off)  ((off) ^ (((off) >> 3) & 0x70))

__device__ __forceinline__ void ldmat4(uint32_t* r, uint32_t addr) {
    asm volatile("ldmatrix.sync.aligned.m8n8.x4.shared.b16 {%0,%1,%2,%3}, [%4];"
        : "=r"(r[0]), "=r"(r[1]), "=r"(r[2]), "=r"(r[3]) : "r"(addr));
}
__device__ __forceinline__ void mma_f16(float* d, const uint32_t* a, const uint32_t* b) {
    asm volatile(
        "mma.sync.aligned.m16n8k16.row.col.f32.f16.f16.f32 "
        "{%0,%1,%2,%3}, {%4,%5,%6,%7}, {%8,%9}, {%0,%1,%2,%3};"
        : "+f"(d[0]), "+f"(d[1]), "+f"(d[2]), "+f"(d[3])
        : "r"(a[0]), "r"(a[1]), "r"(a[2]), "r"(a[3]), "r"(b[0]), "r"(b[1]));
}
__device__ __forceinline__ uint32_t pack_h2(float a, float b) {
    __half2 h = __floats2half2_rn(a, b);
    return *reinterpret_cast<uint32_t*>(&h);
}

// ---------------------------------------------------------------------------
// Prepass (single kernel): fp32 -> fp16 copies of x, w_in, w_out
// ---------------------------------------------------------------------------
#define NX4  (NTOK*DEMB/4)
#define NWI4 (QKV_N*DEMB/4)
#define NWO4 (DEMB*DEMB/4)
#define NALL4 (NX4 + NWI4 + NWO4)

__global__ __launch_bounds__(256) void round_all(
    const float* __restrict__ x, const float* __restrict__ wi,
    const float* __restrict__ wo)
{
    const int i = blockIdx.x * 256 + threadIdx.x;
    const float4* src; __half* dst; int j;
    if (i < NX4)             { src = (const float4*)x;  dst = g_xh;  j = i; }
    else if (i < NX4 + NWI4) { src = (const float4*)wi; dst = g_wih; j = i - NX4; }
    else if (i < NALL4)      { src = (const float4*)wo; dst = g_woh; j = i - NX4 - NWI4; }
    else return;
    const float4 v = src[j];
    ((__half2*)dst)[2*j]   = __floats2half2_rn(v.x, v.y);
    ((__half2*)dst)[2*j+1] = __floats2half2_rn(v.z, v.w);
}

// ---------------------------------------------------------------------------
// fp16 HMMA GEMM (proven R12, unchanged)
// ---------------------------------------------------------------------------
#define MT 128
#define NT 128
#define KC 64

#define SM_STAGE (MT*128 + NT*128)
#define SM_TOTAL (3*SM_STAGE)           // 98304

template<int ROWS>
__device__ __forceinline__ void load_tile_h(uint32_t sbase, const __half* __restrict__ g,
                                            int K, int k0, int tid) {
    #pragma unroll
    for (int t = 0; t < ROWS * 8 / 256; ++t) {
        const int c = tid + t * 256;
        const int row = c >> 3, kc = c & 7;
        const uint32_t off = row * 128 + kc * 16;
        cp_async16(sbase + SWZ128(off), g + (size_t)row * K + k0 + kc * 8);
    }
}

template<int MODE>
__global__ __launch_bounds__(256, 2)
void gemm_h(const float* __restrict__ bias, float* __restrict__ C,
            int M, int N, int K)
{
    extern __shared__ __align__(1024) char smem[];
    const uint32_t sb = smem_u32(smem);
    const int tid  = threadIdx.x;
    const int lane = tid & 31;
    const int warp = tid >> 5;
    const int wm   = (warp >> 2) * 64;
    const int wn   = (warp & 3) * 32;
    const int bm   = blockIdx.y * MT;
    const int bn   = blockIdx.x * NT;

    const __half* Abase = (MODE == 2) ? (const __half*)g_a : (const __half*)g_xh;
    const __half* Bbase = (MODE == 2) ? (const __half*)g_woh : (const __half*)g_wih;
    const __half* Ag = Abase + (size_t)bm * K;
    const __half* Bg = Bbase + (size_t)bn * K;

    float acc[4][4][4];
    #pragma unroll
    for (int i = 0; i < 4; i++)
        #pragma unroll
        for (int j = 0; j < 4; j++)
            #pragma unroll
            for (int r = 0; r < 4; r++) acc[i][j][r] = 0.f;

    const int a_row  = lane & 15;
    const int a_byte = ((lane >> 4) & 1) * 16;
    const int b_row  = (lane & 7) + (((lane >> 4) & 1) << 3);
    const int b_byte = ((lane >> 3) & 1) * 16;

    load_tile_h<MT>(sb + 0*SM_STAGE, Ag, K, 0, tid);
    load_tile_h<NT>(sb + 0*SM_STAGE + MT*128, Bg, K, 0, tid);
    CP_COMMIT();
    load_tile_h<MT>(sb + 1*SM_STAGE, Ag, K, KC, tid);
    load_tile_h<NT>(sb + 1*SM_STAGE + MT*128, Bg, K, KC, tid);
    CP_COMMIT();

    const int niter = K / KC;
    int stage = 0;
    for (int it = 0; it < niter; ++it) {
        if (it + 1 < niter) { CP_WAIT1(); } else { CP_WAIT0(); }
        __syncthreads();

        if (it + 2 < niter) {
            const int s2 = (stage + 2) % 3;
            load_tile_h<MT>(sb + s2*SM_STAGE, Ag, K, (it + 2) * KC, tid);
            load_tile_h<NT>(sb + s2*SM_STAGE + MT*128, Bg, K, (it + 2) * KC, tid);
            CP_COMMIT();
        }

        const uint32_t abase = sb + stage*SM_STAGE;
        const uint32_t bbase = abase + MT*128;

        #pragma unroll
        for (int kk = 0; kk < KC / 16; ++kk) {
            uint32_t af[4][4], bf[4][2];
            #pragma unroll
            for (int mt = 0; mt < 4; ++mt) {
                const uint32_t off = (wm + mt * 16 + a_row) * 128 + kk * 32 + a_byte;
                ldmat4(af[mt], abase + SWZ128(off));
            }
            #pragma unroll
            for (int np = 0; np < 2; ++np) {
                const uint32_t off = (wn + np * 16 + b_row) * 128 + kk * 32 + b_byte;
                uint32_t r[4];
                ldmat4(r, bbase + SWZ128(off));
                bf[np*2][0]   = r[0]; bf[np*2][1]   = r[1];
                bf[np*2+1][0] = r[2]; bf[np*2+1][1] = r[3];
            }
            #pragma unroll
            for (int mt = 0; mt < 4; ++mt)
                #pragma unroll
                for (int nt = 0; nt < 4; ++nt)
                    mma_f16(acc[mt][nt], af[mt], bf[nt]);
        }
        stage = (stage + 1) % 3;
    }

    const int g  = lane >> 2;
    const int qd = lane & 3;
    #pragma unroll
    for (int nt = 0; nt < 4; ++nt) {
        const int col = bn + wn + nt * 8 + qd * 2;
        const float2 bv = *(const float2*)&bias[col];
        #pragma unroll
        for (int mt = 0; mt < 4; ++mt) {
            const int row0 = bm + wm + mt * 16 + g;
            float2 v0, v1;
            v0.x = acc[mt][nt][0] + bv.x;
            v0.y = acc[mt][nt][1] + bv.y;
            v1.x = acc[mt][nt][2] + bv.x;
            v1.y = acc[mt][nt][3] + bv.y;
            if (MODE == 1) {
                const int part = col >> 10;
                const int h = (col & 1023) >> 6;
                const int d = col & 63;
                __half* dst = (part == 0) ? g_qh : (part == 1) ? g_kh : g_vh;
                const int b0i = row0 >> 11, s0 = row0 & 2047;
                const int b1i = (row0 + 8) >> 11, s1 = (row0 + 8) & 2047;
                *(__half2*)&dst[(((size_t)(b0i*NH + h))*SEQ + s0)*DH + d] =
                    __floats2half2_rn(v0.x, v0.y);
                *(__half2*)&dst[(((size_t)(b1i*NH + h))*SEQ + s1)*DH + d] =
                    __floats2half2_rn(v1.x, v1.y);
            } else {
                *(float2*)&C[(size_t)row0 * N + col] = v0;
                *(float2*)&C[(size_t)(row0 + 8) * N + col] = v1;
            }
        }
    }
}

// ---------------------------------------------------------------------------
// Flash attention: fp16 MMAs + FRAGMENT-DOMAIN softmax (no S round-trip).
// P written directly as half2 into P_H; corr/l are lane-local.
// ---------------------------------------------------------------------------
#define AQ 128
#define AK 64
#define AH_Q  0         // 16384
#define AH_K0 16384     // 8192
#define AH_K1 24576     // 8192
#define AH_VT 32768     // 8192
#define AH_PH 40960     // 16384
#define AH_TOTAL 57344

__global__ __launch_bounds__(128, 2) void attn_h(const int* __restrict__ cmask)
{
    extern __shared__ __align__(1024) char smem[];
    const uint32_t sb = smem_u32(smem);

    const int tid  = threadIdx.x;
    const int lane = tid & 31;
    const int warp = tid >> 5;
    const int bh   = blockIdx.x;
    const int qt   = gridDim.y - 1 - blockIdx.y;
    const int q0   = qt * AQ;

    const bool causal = (cmask[0] != 0);

    const __half* gq  = g_qh + ((size_t)bh * SEQ + q0) * DH;
    const __half* gkb = g_kh + (size_t)bh * SEQ * DH;
    const __half* gvb = g_vh + (size_t)bh * SEQ * DH;

    const int a_row  = lane & 15;
    const int a_byte = ((lane >> 4) & 1) * 16;
    const int b_row  = (lane & 7) + (((lane >> 4) & 1) << 3);
    const int b_byte = ((lane >> 3) & 1) * 16;
    const int g  = lane >> 2;
    const int qh = lane & 3;

    #pragma unroll
    for (int i = 0; i < 8; ++i) {
        const int c = tid + i * 128;
        const int row = c >> 3, kc = c & 7;
        cp_async16(sb + AH_Q + SWZ128((uint32_t)(row * 128 + kc * 16)),
                   gq + (size_t)row * DH + kc * 8);
    }
    CP_COMMIT();

    #pragma unroll
    for (int i = 0; i < 4; ++i) {
        const int c = tid + i * 128;
        const int row = c >> 3, kc = c & 7;
        cp_async16(sb + AH_K0 + SWZ128((uint32_t)(row * 128 + kc * 16)),
                   gkb + (size_t)row * DH + kc * 8);
    }
    CP_COMMIT();

    float oa[2][8][4];
    #pragma unroll
    for (int mt = 0; mt < 2; ++mt)
        #pragma unroll
        for (int nt = 0; nt < 8; ++nt)
            #pragma unroll
            for (int c = 0; c < 4; ++c) oa[mt][nt][c] = 0.f;
    float mrow[2][2], lrow[2][2];
    #pragma unroll
    for (int mt = 0; mt < 2; ++mt) {
        mrow[mt][0] = mrow[mt][1] = -1e30f;
        lrow[mt][0] = lrow[mt][1] = 0.f;
    }

    const int ntiles = causal ? (q0 / AK + 2) : (SEQ / AK);
    const int vkey = tid & 63;
    const int vds  = tid >> 6;
    const int rw   = q0 + warp * 32;     // warp's first q-row

    for (int t = 0; t < ntiles; ++t) {
        const int k0 = t * AK;
        const uint32_t kbase = sb + ((t & 1) ? AH_K1 : AH_K0);

        uint4 vreg[4];
        #pragma unroll
        for (int i = 0; i < 4; ++i)
            vreg[i] = *(const uint4*)(gvb + (size_t)(k0 + vkey) * DH + vds * 32 + i * 8);

        CP_WAIT0();
        __syncthreads();

        if (t + 1 < ntiles) {
            const uint32_t knext = ((t & 1) ? AH_K0 : AH_K1);
            #pragma unroll
            for (int i = 0; i < 4; ++i) {
                const int c = tid + i * 128;
                const int row = c >> 3, kc = c & 7;
                cp_async16(sb + knext + SWZ128((uint32_t)(row * 128 + kc * 16)),
                           gkb + (size_t)(k0 + AK + row) * DH + kc * 8);
            }
            CP_COMMIT();
        }

        // ---- S = Q @ K^T (fp16, proven addressing) ----
        float sc[2][8][4];
        #pragma unroll
        for (int mt = 0; mt < 2; ++mt)
            #pragma unroll
            for (int nt = 0; nt < 8; ++nt)
                #pragma unroll
                for (int c = 0; c < 4; ++c) sc[mt][nt][c] = 0.f;

        #pragma unroll
        for (int kk = 0; kk < 4; ++kk) {
            uint32_t aq[2][4], bf[8][2];
            #pragma unroll
            for (int mt = 0; mt < 2; ++mt) {
                const uint32_t off = (warp*32 + mt*16 + a_row) * 128 + kk * 32 + a_byte;
                ldmat4(aq[mt], sb + AH_Q + SWZ128(off));
            }
            #pragma unroll
            for (int np = 0; np < 4; ++np) {
                const uint32_t off = (np*16 + b_row) * 128 + kk * 32 + b_byte;
                uint32_t r[4];
                ldmat4(r, kbase + SWZ128(off));
                bf[np*2][0]   = r[0]; bf[np*2][1]   = r[1];
                bf[np*2+1][0] = r[2]; bf[np*2+1][1] = r[3];
            }
            #pragma unroll
            for (int mt = 0; mt < 2; ++mt)
                #pragma unroll
                for (int nt = 0; nt < 8; ++nt)
                    mma_f16(sc[mt][nt], aq[mt], bf[nt]);
        }

        // ---- V(t) registers -> V^T half tile ----
        {
            #pragma unroll
            for (int i = 0; i < 4; ++i) {
                __half h[8];
                *(uint4*)h = vreg[i];
                #pragma unroll
                for (int j = 0; j < 8; ++j) {
                    const int d = vds * 32 + i * 8 + j;
                    *(__half*)(smem + AH_VT
                        + SWZ128((uint32_t)(d * 128) + (uint32_t)(vkey * 2))) = h[j];
                }
            }
        }

        // ---- scale + causal mask (fragment coords, proven C layout) ----
        #pragma unroll
        for (int mt = 0; mt < 2; ++mt)
            #pragma unroll
            for (int nt = 0; nt < 8; ++nt)
                #pragma unroll
                for (int c = 0; c < 4; ++c) sc[mt][nt][c] *= 0.125f;

        if (causal && (k0 + AK - 1 > rw)) {
            #pragma unroll
            for (int mt = 0; mt < 2; ++mt)
                #pragma unroll
                for (int nt = 0; nt < 8; ++nt)
                    #pragma unroll
                    for (int c = 0; c < 4; ++c) {
                        const int row = rw + mt*16 + g + (c >> 1) * 8;
                        const int col = k0 + nt*8 + 2*qh + (c & 1);
                        if (col > row) sc[mt][nt][c] = -1e30f;
                    }
        }

        // ---- online softmax, fragment domain ----
        #pragma unroll
        for (int mt = 0; mt < 2; ++mt) {
            #pragma unroll
            for (int half = 0; half < 2; ++half) {
                float tmax = -1e30f;
                #pragma unroll
                for (int nt = 0; nt < 8; ++nt)
                    tmax = fmaxf(tmax, fmaxf(sc[mt][nt][half*2], sc[mt][nt][half*2+1]));
                tmax = fmaxf(tmax, __shfl_xor_sync(0xffffffffu, tmax, 1));
                tmax = fmaxf(tmax, __shfl_xor_sync(0xffffffffu, tmax, 2));
                const float mn = fmaxf(mrow[mt][half], tmax);
                const float corr = __expf(mrow[mt][half] - mn);
                mrow[mt][half] = mn;
                float rs = 0.f;
                #pragma unroll
                for (int nt = 0; nt < 8; ++nt) {
                    const float p0 = __expf(sc[mt][nt][half*2]   - mn);
                    const float p1 = __expf(sc[mt][nt][half*2+1] - mn);
                    sc[mt][nt][half*2]   = p0;
                    sc[mt][nt][half*2+1] = p1;
                    rs += p0 + p1;
                    oa[mt][nt][half*2]   *= corr;
                    oa[mt][nt][half*2+1] *= corr;
                }
                rs += __shfl_xor_sync(0xffffffffu, rs, 1);
                rs += __shfl_xor_sync(0xffffffffu, rs, 2);
                lrow[mt][half] = lrow[mt][half] * corr + rs;
            }
        }

        // ---- P fragments -> P_H half tile (direct half2 stores) ----
        #pragma unroll
        for (int mt = 0; mt < 2; ++mt) {
            const int row0 = warp*32 + mt*16 + g;
            #pragma unroll
            for (int nt = 0; nt < 8; ++nt) {
                const uint32_t cb = (uint32_t)(nt*16 + 4*qh);
                *(uint32_t*)(smem + AH_PH + SWZ128((uint32_t)(row0 * 128) + cb)) =
                    pack_h2(sc[mt][nt][0], sc[mt][nt][1]);
                *(uint32_t*)(smem + AH_PH + SWZ128((uint32_t)((row0 + 8) * 128) + cb)) =
                    pack_h2(sc[mt][nt][2], sc[mt][nt][3]);
            }
        }

        __syncthreads();   // V^T + P_H visible

        // ---- O += P @ V (fp16, proven addressing) ----
        #pragma unroll
        for (int kk = 0; kk < 4; ++kk) {
            uint32_t ap[2][4], bf[8][2];
            #pragma unroll
            for (int mt = 0; mt < 2; ++mt) {
                const uint32_t off = (warp*32 + mt*16 + a_row) * 128 + kk * 32 + a_byte;
                ldmat4(ap[mt], sb + AH_PH + SWZ128(off));
            }
            #pragma unroll
            for (int np = 0; np < 4; ++np) {
                const uint32_t off = (np*16 + b_row) * 128 + kk * 32 + b_byte;
                uint32_t r[4];
                ldmat4(r, sb + AH_VT + SWZ128(off));
                bf[np*2][0]   = r[0]; bf[np*2][1]   = r[1];
                bf[np*2+1][0] = r[2]; bf[np*2+1][1] = r[3];
            }
            #pragma unroll
            for (int mt = 0; mt < 2; ++mt)
                #pragma unroll
                for (int nt = 0; nt < 8; ++nt)
                    mma_f16(oa[mt][nt], ap[mt], bf[nt]);
        }
    }

    // ---- normalize (lane-local l) + write g_a as HALF ----
    const int b = bh >> 4, h = bh & 15;
    #pragma unroll
    for (int mt = 0; mt < 2; ++mt) {
        const int r0 = warp*32 + mt*16 + g;
        const float i0 = 1.f / fmaxf(lrow[mt][0], 1e-30f);
        const float i1 = 1.f / fmaxf(lrow[mt][1], 1e-30f);
        __half* o0 = g_a + ((size_t)(b * SEQ + q0 + r0)) * DEMB + h * DH;
        __half* o1 = g_a + ((size_t)(b * SEQ + q0 + r0 + 8)) * DEMB + h * DH;
        #pragma unroll
        for (int nt = 0; nt < 8; ++nt) {
            *(__half2*)(o0 + nt*8 + 2*qh) =
                __floats2half2_rn(oa[mt][nt][0] * i0, oa[mt][nt][1] * i0);
            *(__half2*)(o1 + nt*8 + 2*qh) =
                __floats2half2_rn(oa[mt][nt][2] * i1, oa[mt][nt][3] * i1);
        }
    }
}

// ---------------------------------------------------------------------------
extern "C" void kernel_launch(void* const* d_in, const int* in_sizes, int n_in,
                              void* d_out, int out_size)
{
    const float* x     = (const float*)d_in[0];
    const float* w_in  = (const float*)d_in[1];
    const float* b_in  = (const float*)d_in[2];
    const float* w_out = (const float*)d_in[3];
    const float* b_out = (const float*)d_in[4];
    const int*   cmask = (const int*)d_in[5];
    float* out = (float*)d_out;

    cudaFuncSetAttribute(gemm_h<1>, cudaFuncAttributeMaxDynamicSharedMemorySize, SM_TOTAL);
    cudaFuncSetAttribute(gemm_h<2>, cudaFuncAttributeMaxDynamicSharedMemorySize, SM_TOTAL);
    cudaFuncSetAttribute(attn_h,    cudaFuncAttributeMaxDynamicSharedMemorySize, AH_TOTAL);

    round_all<<<(NALL4 + 255) / 256, 256>>>(x, w_in, w_out);

    gemm_h<1><<<dim3(QKV_N/NT, NTOK/MT), 256, SM_TOTAL>>>(
        b_in, nullptr, NTOK, QKV_N, DEMB);

    attn_h<<<dim3(BATCH*NH, SEQ/AQ), 128, AH_TOTAL>>>(cmask);

    gemm_h<2><<<dim3(DEMB/NT, NTOK/MT), 256, SM_TOTAL>>>(
        b_out, out, NTOK, DEMB, DEMB);
}